// round 5
// baseline (speedup 1.0000x reference)
#include <cuda_runtime.h>
#include <cuda_bf16.h>
#include <math.h>

// Problem constants
#define BATCH 2
#define SEQ 2048
#define HIDDEN 2048
#define HEADS 16
#define HEAD_DIM 128
#define TOKENS (BATCH * SEQ)          // 4096
#define QKV_N (3 * HIDDEN)            // 6144

// Scratch buffers (allocation-free: __device__ globals)
__device__ float g_qkv[(size_t)TOKENS * QKV_N];     // [token][3*HIDDEN]
__device__ float g_attn[(size_t)TOKENS * HIDDEN];   // [token][H*Dh]

// ---------------------------------------------------------------------------
// SGEMM with fused bias: C[M,N] = A[M,K] @ B[K,N] + bias[N]
// BM=BN=128, BK=8, TM=TN=8, 256 threads. M%128==0, N%128==0, K%8==0 assumed.
// ---------------------------------------------------------------------------
__global__ __launch_bounds__(256) void sgemm_bias_kernel(
    int M, int N, int K,
    const float* __restrict__ A, const float* __restrict__ B,
    const float* __restrict__ bias, float* __restrict__ C)
{
    __shared__ float As[8][128];
    __shared__ float Bs[8][128];

    const int t = threadIdx.x;
    const int cRow = blockIdx.y;
    const int cCol = blockIdx.x;

    const int threadRow = t >> 4;     // 0..15
    const int threadCol = t & 15;     // 0..15

    const float* Ablk = A + (size_t)cRow * 128 * K;
    const float* Bblk = B + (size_t)cCol * 128;

    const int innerRowA = t >> 1;          // 0..127
    const int innerColA = (t & 1) * 4;     // 0 or 4
    const int innerRowB = t >> 5;          // 0..7
    const int innerColB = (t & 31) * 4;    // 0..124

    float acc[8][8];
    #pragma unroll
    for (int i = 0; i < 8; i++)
        #pragma unroll
        for (int j = 0; j < 8; j++) acc[i][j] = 0.0f;

    float regM[8], regN[8];

    for (int k0 = 0; k0 < K; k0 += 8) {
        float4 a = *(const float4*)&Ablk[(size_t)innerRowA * K + k0 + innerColA];
        As[innerColA + 0][innerRowA] = a.x;
        As[innerColA + 1][innerRowA] = a.y;
        As[innerColA + 2][innerRowA] = a.z;
        As[innerColA + 3][innerRowA] = a.w;
        *(float4*)&Bs[innerRowB][innerColB] =
            *(const float4*)&Bblk[(size_t)(k0 + innerRowB) * N + innerColB];
        __syncthreads();

        #pragma unroll
        for (int k = 0; k < 8; k++) {
            #pragma unroll
            for (int i = 0; i < 8; i++) regM[i] = As[k][threadRow * 8 + i];
            #pragma unroll
            for (int j = 0; j < 8; j++) regN[j] = Bs[k][threadCol * 8 + j];
            #pragma unroll
            for (int i = 0; i < 8; i++)
                #pragma unroll
                for (int j = 0; j < 8; j++)
                    acc[i][j] = fmaf(regM[i], regN[j], acc[i][j]);
        }
        __syncthreads();
    }

    #pragma unroll
    for (int i = 0; i < 8; i++) {
        const int row = cRow * 128 + threadRow * 8 + i;
        #pragma unroll
        for (int j = 0; j < 8; j += 4) {
            const int col = cCol * 128 + threadCol * 8 + j;
            float4 o;
            o.x = acc[i][j + 0] + bias[col + 0];
            o.y = acc[i][j + 1] + bias[col + 1];
            o.z = acc[i][j + 2] + bias[col + 2];
            o.w = acc[i][j + 3] + bias[col + 3];
            *(float4*)&C[(size_t)row * N + col] = o;
        }
    }
}

// ---------------------------------------------------------------------------
// RoPE in-place on q and k halves of g_qkv.
// grid = TOKENS blocks of 1024 threads; thread = (head h, pair index j<64).
// Position buffer may be int32 or int64 (JAX x64-disabled downcasts); detect:
// for int64 little-endian positive values, the int32 view at odd indices is 0;
// for int32 arange, view[1] == 1 != 0.
// ---------------------------------------------------------------------------
__global__ __launch_bounds__(1024) void rope_kernel(
    float* __restrict__ qkv, const int* __restrict__ pos32)
{
    const int token = blockIdx.x;
    const int t = threadIdx.x;
    const int h = t >> 6;
    const int j = t & 63;

    const bool is64 = (pos32[1] == 0);
    const int posi = is64 ? pos32[2 * token] : pos32[token];
    const float pos = (float)posi;

    // inv_freq = 10000^(-j/64) = 2^(-j * log2(10000)/64)
    const float inv = exp2f(-(float)j * 0.20762050595283508f);
    const float ang = pos * inv;
    float s, c;
    sincosf(ang, &s, &c);

    size_t base = (size_t)token * QKV_N + h * HEAD_DIM;
    // q
    {
        float x1 = qkv[base + j];
        float x2 = qkv[base + j + 64];
        qkv[base + j]      = x1 * c - x2 * s;
        qkv[base + j + 64] = x2 * c + x1 * s;
    }
    // k
    base += HIDDEN;
    {
        float x1 = qkv[base + j];
        float x2 = qkv[base + j + 64];
        qkv[base + j]      = x1 * c - x2 * s;
        qkv[base + j + 64] = x2 * c + x1 * s;
    }
}

// ---------------------------------------------------------------------------
// Flash attention, fp32, causal. One block per (q tile of 64 rows, b*H+h).
// 256 threads (16x16). Smem: Qs[128][64], Ks[128][64], Vs[64][128], Ss[64][65],
// stats m/l/alpha [64] each.
// ---------------------------------------------------------------------------
#define FL_SMEM_FLOATS (128*64 + 128*64 + 64*128 + 64*65 + 3*64)
#define FL_SMEM_BYTES  (FL_SMEM_FLOATS * 4)

__global__ __launch_bounds__(256) void flash_kernel(
    const float* __restrict__ qkv, float* __restrict__ out)
{
    extern __shared__ float sm[];
    float* Qs = sm;                 // [d][r] 128x64
    float* Ks = Qs + 128 * 64;      // [d][c] 128x64
    float* Vs = Ks + 128 * 64;      // [c][d] 64x128
    float* Ss = Vs + 64 * 128;      // [r][c] 64x65 (padded)
    float* mrow = Ss + 64 * 65;
    float* lrow = mrow + 64;
    float* arow = lrow + 64;

    const int qt = blockIdx.x;            // q tile index (0..31)
    const int bh = blockIdx.y;            // b*HEADS + h
    const int b = bh >> 4;
    const int h = bh & 15;
    const int q0 = qt * 64;

    const int t = threadIdx.x;
    const int tx = t & 15;
    const int ty = t >> 4;

    const float scale = 0.08838834764831845f; // 1/sqrt(128)

    // Load Q tile (scaled) into Qs[d][r]
    for (int i = t; i < 64 * 32; i += 256) {
        const int r = i >> 5;
        const int d4 = (i & 31) * 4;
        const float4 v = *(const float4*)
            &qkv[(size_t)(b * SEQ + q0 + r) * QKV_N + h * HEAD_DIM + d4];
        Qs[(d4 + 0) * 64 + r] = v.x * scale;
        Qs[(d4 + 1) * 64 + r] = v.y * scale;
        Qs[(d4 + 2) * 64 + r] = v.z * scale;
        Qs[(d4 + 3) * 64 + r] = v.w * scale;
    }
    if (t < 64) { mrow[t] = -INFINITY; lrow[t] = 0.0f; }

    float acc[4][8];
    #pragma unroll
    for (int i = 0; i < 4; i++)
        #pragma unroll
        for (int j = 0; j < 8; j++) acc[i][j] = 0.0f;

    for (int kt = 0; kt <= qt; ++kt) {
        const int k0 = kt * 64;
        __syncthreads();  // protect smem from previous iteration / Q load done

        // Load K tile -> Ks[d][c], V tile -> Vs[c][d]
        for (int i = t; i < 64 * 32; i += 256) {
            const int r = i >> 5;
            const int d4 = (i & 31) * 4;
            const size_t gb = (size_t)(b * SEQ + k0 + r) * QKV_N + h * HEAD_DIM + d4;
            const float4 kv = *(const float4*)&qkv[gb + HIDDEN];
            Ks[(d4 + 0) * 64 + r] = kv.x;
            Ks[(d4 + 1) * 64 + r] = kv.y;
            Ks[(d4 + 2) * 64 + r] = kv.z;
            Ks[(d4 + 3) * 64 + r] = kv.w;
            *(float4*)&Vs[r * 128 + d4] = *(const float4*)&qkv[gb + 2 * HIDDEN];
        }
        __syncthreads();

        // S = Q * K^T  (each thread: rows ty+16i, cols tx+16j)
        float s[4][4];
        #pragma unroll
        for (int i = 0; i < 4; i++)
            #pragma unroll
            for (int j = 0; j < 4; j++) s[i][j] = 0.0f;

        for (int d = 0; d < 128; ++d) {
            float qv[4], kv[4];
            #pragma unroll
            for (int i = 0; i < 4; i++) qv[i] = Qs[d * 64 + ty + 16 * i];
            #pragma unroll
            for (int j = 0; j < 4; j++) kv[j] = Ks[d * 64 + tx + 16 * j];
            #pragma unroll
            for (int i = 0; i < 4; i++)
                #pragma unroll
                for (int j = 0; j < 4; j++)
                    s[i][j] = fmaf(qv[i], kv[j], s[i][j]);
        }

        const bool diag = (kt == qt);
        #pragma unroll
        for (int i = 0; i < 4; i++) {
            const int r = ty + 16 * i;
            #pragma unroll
            for (int j = 0; j < 4; j++) {
                const int c = tx + 16 * j;
                float val = s[i][j];
                if (diag && c > r) val = -INFINITY;
                Ss[r * 65 + c] = val;
            }
        }
        __syncthreads();

        // Online softmax: one row per thread (threads 0..63)
        if (t < 64) {
            const int r = t;
            const float m_old = mrow[r];
            float mx = m_old;
            #pragma unroll 8
            for (int c = 0; c < 64; c++) mx = fmaxf(mx, Ss[r * 65 + c]);
            const float al = __expf(m_old - mx);
            float sum = 0.0f;
            #pragma unroll 8
            for (int c = 0; c < 64; c++) {
                const float p = __expf(Ss[r * 65 + c] - mx);
                Ss[r * 65 + c] = p;
                sum += p;
            }
            lrow[r] = lrow[r] * al + sum;
            mrow[r] = mx;
            arow[r] = al;
        }
        __syncthreads();

        // Rescale O and accumulate P*V
        #pragma unroll
        for (int i = 0; i < 4; i++) {
            const float al = arow[ty + 16 * i];
            #pragma unroll
            for (int j = 0; j < 8; j++) acc[i][j] *= al;
        }
        for (int kk = 0; kk < 64; ++kk) {
            float p[4], v[8];
            #pragma unroll
            for (int i = 0; i < 4; i++) p[i] = Ss[(ty + 16 * i) * 65 + kk];
            #pragma unroll
            for (int j = 0; j < 8; j++) v[j] = Vs[kk * 128 + tx + 16 * j];
            #pragma unroll
            for (int i = 0; i < 4; i++)
                #pragma unroll
                for (int j = 0; j < 8; j++)
                    acc[i][j] = fmaf(p[i], v[j], acc[i][j]);
        }
    }

    // Epilogue: normalize and store [token][h*128 + c]
    #pragma unroll
    for (int i = 0; i < 4; i++) {
        const int r = ty + 16 * i;
        const float linv = 1.0f / lrow[r];
        const size_t row_base = (size_t)(b * SEQ + q0 + r) * HIDDEN + h * HEAD_DIM;
        #pragma unroll
        for (int j = 0; j < 8; j++) {
            out[row_base + tx + 16 * j] = acc[i][j] * linv;
        }
    }
}

// ---------------------------------------------------------------------------
// Launch
// ---------------------------------------------------------------------------
extern "C" void kernel_launch(void* const* d_in, const int* in_sizes, int n_in,
                              void* d_out, int out_size)
{
    const float* hidden       = (const float*)d_in[0];
    const int*   pos32        = (const int*)d_in[1];   // int32 or int64 view
    const float* Wqkv         = (const float*)d_in[2];
    const float* bqkv         = (const float*)d_in[3];
    const float* Wo           = (const float*)d_in[4];
    const float* bo           = (const float*)d_in[5];
    float* out                = (float*)d_out;

    float* qkv;  cudaGetSymbolAddress((void**)&qkv,  g_qkv);
    float* attn; cudaGetSymbolAddress((void**)&attn, g_attn);

    // 1) QKV projection: [4096,2048] @ [2048,6144] + bias
    {
        dim3 grid(QKV_N / 128, TOKENS / 128);
        sgemm_bias_kernel<<<grid, 256>>>(TOKENS, QKV_N, HIDDEN,
                                         hidden, Wqkv, bqkv, qkv);
    }

    // 2) RoPE on q,k in place
    rope_kernel<<<TOKENS, 1024>>>(qkv, pos32);

    // 3) Flash attention
    {
        cudaFuncSetAttribute(flash_kernel,
                             cudaFuncAttributeMaxDynamicSharedMemorySize,
                             FL_SMEM_BYTES);
        dim3 grid(SEQ / 64, BATCH * HEADS);
        flash_kernel<<<grid, 256, FL_SMEM_BYTES>>>(qkv, attn);
    }

    // 4) Output projection: [4096,2048] @ [2048,2048] + bias
    {
        dim3 grid(HIDDEN / 128, TOKENS / 128);
        sgemm_bias_kernel<<<grid, 256>>>(TOKENS, HIDDEN, HIDDEN,
                                         attn, Wo, bo, out);
    }
}

// round 7
// speedup vs baseline: 1.4899x; 1.4899x over previous
#include <cuda_runtime.h>
#include <cuda_bf16.h>
#include <mma.h>
#include <math.h>
#include <stdint.h>

using namespace nvcuda;

// Problem constants
#define BATCH 2
#define SEQ 2048
#define HIDDEN 2048
#define HEADS 16
#define HEAD_DIM 128
#define TOKENS (BATCH * SEQ)          // 4096
#define QKV_N (3 * HIDDEN)            // 6144

// ---------------------------------------------------------------------------
// Scratch (allocation-free: __device__ globals)
// ---------------------------------------------------------------------------
__device__ float g_qkv[(size_t)TOKENS * QKV_N];     // [token][3*HIDDEN]
__device__ float g_attn[(size_t)TOKENS * HIDDEN];   // [token][H*Dh]
// hi/lo bf16 splits of the GEMM "A" operand (hidden, later attn) [M,K] K-major
__device__ __nv_bfloat16 g_Ahi[(size_t)TOKENS * HIDDEN];
__device__ __nv_bfloat16 g_Alo[(size_t)TOKENS * HIDDEN];
// hi/lo bf16 splits of transposed weights [N,K] K-major
__device__ __nv_bfloat16 g_Wqkv_hi[(size_t)QKV_N * HIDDEN];
__device__ __nv_bfloat16 g_Wqkv_lo[(size_t)QKV_N * HIDDEN];
__device__ __nv_bfloat16 g_Wo_hi[(size_t)HIDDEN * HIDDEN];
__device__ __nv_bfloat16 g_Wo_lo[(size_t)HIDDEN * HIDDEN];

// ---------------------------------------------------------------------------
// cp.async helpers (sm_80+, legal on plain compute_103 PTX)
// ---------------------------------------------------------------------------
__device__ __forceinline__ uint32_t smem_to_u32(const void* p) {
    uint32_t a;
    asm("{ .reg .u64 t; cvta.to.shared.u64 t, %1; cvt.u32.u64 %0, t; }"
        : "=r"(a) : "l"(p));
    return a;
}
__device__ __forceinline__ void cp_async16(uint32_t dst, const void* src) {
    asm volatile("cp.async.cg.shared.global [%0], [%1], 16;"
                 :: "r"(dst), "l"(src));
}
__device__ __forceinline__ void cp_commit() {
    asm volatile("cp.async.commit_group;" ::: "memory");
}
template <int N>
__device__ __forceinline__ void cp_wait() {
    asm volatile("cp.async.wait_group %0;" :: "n"(N) : "memory");
}

// ---------------------------------------------------------------------------
// Elementwise hi/lo bf16 split: x -> hi=bf16(x), lo=bf16(x-hi). float4-wide.
// ---------------------------------------------------------------------------
__global__ __launch_bounds__(256) void split_kernel(
    const float* __restrict__ x, __nv_bfloat16* __restrict__ hi,
    __nv_bfloat16* __restrict__ lo, int n4)
{
    const int i = blockIdx.x * 256 + threadIdx.x;
    if (i >= n4) return;
    const float4 v = ((const float4*)x)[i];
    float f[4] = {v.x, v.y, v.z, v.w};
    uint32_t hp[2], lp[2];
    #pragma unroll
    for (int p = 0; p < 2; p++) {
        __nv_bfloat16 h0 = __float2bfloat16(f[2*p]);
        __nv_bfloat16 h1 = __float2bfloat16(f[2*p+1]);
        __nv_bfloat16 l0 = __float2bfloat16(f[2*p]   - __bfloat162float(h0));
        __nv_bfloat16 l1 = __float2bfloat16(f[2*p+1] - __bfloat162float(h1));
        __nv_bfloat162 hh; hh.x = h0; hh.y = h1;
        __nv_bfloat162 ll; ll.x = l0; ll.y = l1;
        hp[p] = *(uint32_t*)&hh;
        lp[p] = *(uint32_t*)&ll;
    }
    ((uint2*)hi)[i] = make_uint2(hp[0], hp[1]);
    ((uint2*)lo)[i] = make_uint2(lp[0], lp[1]);
}

// ---------------------------------------------------------------------------
// Transpose + hi/lo split: W [K,N] fp32 -> Thi/Tlo [N,K] bf16. 32x32 tiles.
// ---------------------------------------------------------------------------
__global__ __launch_bounds__(256) void tsplit_kernel(
    const float* __restrict__ W, __nv_bfloat16* __restrict__ Thi,
    __nv_bfloat16* __restrict__ Tlo, int K, int N)
{
    __shared__ float sm[32][33];
    const int n0 = blockIdx.x * 32;
    const int k0 = blockIdx.y * 32;
    const int tx = threadIdx.x & 31;
    const int ty = threadIdx.x >> 5;   // 0..7
    #pragma unroll
    for (int i = 0; i < 32; i += 8)
        sm[ty + i][tx] = W[(size_t)(k0 + ty + i) * N + n0 + tx];
    __syncthreads();
    #pragma unroll
    for (int i = 0; i < 32; i += 8) {
        const float v = sm[tx][ty + i];
        const __nv_bfloat16 h = __float2bfloat16(v);
        const __nv_bfloat16 l = __float2bfloat16(v - __bfloat162float(h));
        const size_t o = (size_t)(n0 + ty + i) * K + k0 + tx;
        Thi[o] = h;
        Tlo[o] = l;
    }
}

// ---------------------------------------------------------------------------
// wmma bf16 GEMM with hi/lo split: C[M,N] = A @ B^T + bias
// A (Ahi/Alo): [M,K] K-major bf16.  B (Bhi/Blo): [N,K] K-major bf16.
// CTA tile 128x128, BK=32, 2-stage cp.async pipeline, 256 threads (8 warps,
// warp grid 4Mx2N; each warp 32x64 = 2x4 m16n16k16 fragments).
// Bias fused by initializing accumulators from a broadcast bias tile.
// ---------------------------------------------------------------------------
#define ROWPAD 40                               // bf16 per smem row (pad 32->40)
#define TILE_SM_BYTES (128 * ROWPAD * 2)        // 10240
#define STAGE_BYTES   (4 * TILE_SM_BYTES)       // Ahi,Alo,Bhi,Blo = 40960
#define BIAS_LDM 136
#define GEMM_SMEM_BYTES (2 * STAGE_BYTES + 16 * BIAS_LDM * 4)  // 90624

__global__ __launch_bounds__(256) void gemm_mma_kernel(
    int M, int Ntot, int K,
    const __nv_bfloat16* __restrict__ Ahi, const __nv_bfloat16* __restrict__ Alo,
    const __nv_bfloat16* __restrict__ Bhi, const __nv_bfloat16* __restrict__ Blo,
    const float* __restrict__ bias, float* __restrict__ C)
{
    extern __shared__ char smem[];
    char* stage0 = smem;
    char* stage1 = smem + STAGE_BYTES;
    float* bias_tile = (float*)(smem + 2 * STAGE_BYTES);
    const uint32_t smem_u32 = smem_to_u32(smem);

    const int t = threadIdx.x;
    const int wid = t >> 5;
    const int warpM = wid & 3;      // 0..3 -> 32-row band
    const int warpN = wid >> 2;     // 0..1 -> 64-col band
    const int m0 = blockIdx.y * 128;
    const int n0 = blockIdx.x * 128;

    // Broadcast-bias tile: 16 identical rows of bias[n0 .. n0+128)
    for (int u = t; u < 16 * 128; u += 256) {
        const int r = u >> 7;
        const int c = u & 127;
        bias_tile[r * BIAS_LDM + c] = __ldg(bias + n0 + c);
    }
    __syncthreads();

    wmma::fragment<wmma::accumulator, 16, 16, 16, float> acc[2][4];
    #pragma unroll
    for (int mt = 0; mt < 2; mt++)
        #pragma unroll
        for (int nt = 0; nt < 4; nt++)
            wmma::load_matrix_sync(acc[mt][nt],
                bias_tile + warpN * 64 + nt * 16, BIAS_LDM, wmma::mem_row_major);

    const int Ku4 = K >> 3;   // row stride in uint4 (8 bf16 each)
    const uint4* srcs[4] = {
        (const uint4*)Ahi + (size_t)m0 * Ku4,
        (const uint4*)Alo + (size_t)m0 * Ku4,
        (const uint4*)Bhi + (size_t)n0 * Ku4,
        (const uint4*)Blo + (size_t)n0 * Ku4
    };

    const int NC = K >> 5;    // number of 32-wide K chunks

    // ---- stage loader: 4 tiles x 128 rows x 4 x 16B = 2048 cp.async / 256thr
    auto load_stage = [&](int chunk, int s) {
        const int kq = chunk << 2;  // uint4 offset of chunk within a row
        const uint32_t sbase = smem_u32 + s * STAGE_BYTES;
        #pragma unroll
        for (int j = 0; j < 8; j++) {
            const int u = t + j * 256;
            const int tile = u >> 9;
            const int row = (u >> 2) & 127;
            const int seg = u & 3;
            const uint4* src = srcs[tile] + (size_t)row * Ku4 + kq + seg;
            const uint32_t dst = sbase + tile * TILE_SM_BYTES + row * 80 + seg * 16;
            cp_async16(dst, src);
        }
        cp_commit();
    };

    load_stage(0, 0);

    for (int i = 0; i < NC; i++) {
        const int s = i & 1;
        if (i + 1 < NC) {
            load_stage(i + 1, s ^ 1);
            cp_wait<1>();
        } else {
            cp_wait<0>();
        }
        __syncthreads();

        const char* st = s ? stage1 : stage0;
        const __nv_bfloat16* Ah = (const __nv_bfloat16*)st;
        const __nv_bfloat16* Al = (const __nv_bfloat16*)(st + TILE_SM_BYTES);
        const __nv_bfloat16* Bh = (const __nv_bfloat16*)(st + 2 * TILE_SM_BYTES);
        const __nv_bfloat16* Bl = (const __nv_bfloat16*)(st + 3 * TILE_SM_BYTES);

        #pragma unroll
        for (int ks = 0; ks < 2; ks++) {
            wmma::fragment<wmma::matrix_a, 16, 16, 16, __nv_bfloat16, wmma::row_major> aH[2], aL[2];
            wmma::fragment<wmma::matrix_b, 16, 16, 16, __nv_bfloat16, wmma::col_major> bH[4], bL[4];
            #pragma unroll
            for (int mt = 0; mt < 2; mt++) {
                const int r = warpM * 32 + mt * 16;
                wmma::load_matrix_sync(aH[mt], Ah + r * ROWPAD + ks * 16, ROWPAD);
                wmma::load_matrix_sync(aL[mt], Al + r * ROWPAD + ks * 16, ROWPAD);
            }
            #pragma unroll
            for (int nt = 0; nt < 4; nt++) {
                const int r = warpN * 64 + nt * 16;
                wmma::load_matrix_sync(bH[nt], Bh + r * ROWPAD + ks * 16, ROWPAD);
                wmma::load_matrix_sync(bL[nt], Bl + r * ROWPAD + ks * 16, ROWPAD);
            }
            #pragma unroll
            for (int mt = 0; mt < 2; mt++)
                #pragma unroll
                for (int nt = 0; nt < 4; nt++) {
                    wmma::mma_sync(acc[mt][nt], aH[mt], bH[nt], acc[mt][nt]);
                    wmma::mma_sync(acc[mt][nt], aH[mt], bL[nt], acc[mt][nt]);
                    wmma::mma_sync(acc[mt][nt], aL[mt], bH[nt], acc[mt][nt]);
                }
        }
        __syncthreads();
    }

    // Epilogue: direct global store (bias already folded into accumulators)
    #pragma unroll
    for (int mt = 0; mt < 2; mt++)
        #pragma unroll
        for (int nt = 0; nt < 4; nt++) {
            float* dst = C + (size_t)(m0 + warpM * 32 + mt * 16) * Ntot
                           + n0 + warpN * 64 + nt * 16;
            wmma::store_matrix_sync(dst, acc[mt][nt], Ntot, wmma::mem_row_major);
        }
}

// ---------------------------------------------------------------------------
// RoPE in-place on q and k halves of g_qkv. Position buffer may be int32 or
// int64 (detect: int64 LE positives have zero at odd int32 indices).
// ---------------------------------------------------------------------------
__global__ __launch_bounds__(1024) void rope_kernel(
    float* __restrict__ qkv, const int* __restrict__ pos32)
{
    const int token = blockIdx.x;
    const int t = threadIdx.x;
    const int h = t >> 6;
    const int j = t & 63;

    const bool is64 = (pos32[1] == 0);
    const int posi = is64 ? pos32[2 * token] : pos32[token];
    const float pos = (float)posi;

    const float inv = exp2f(-(float)j * 0.20762050595283508f);
    const float ang = pos * inv;
    float s, c;
    sincosf(ang, &s, &c);

    size_t base = (size_t)token * QKV_N + h * HEAD_DIM;
    {
        float x1 = qkv[base + j];
        float x2 = qkv[base + j + 64];
        qkv[base + j]      = x1 * c - x2 * s;
        qkv[base + j + 64] = x2 * c + x1 * s;
    }
    base += HIDDEN;
    {
        float x1 = qkv[base + j];
        float x2 = qkv[base + j + 64];
        qkv[base + j]      = x1 * c - x2 * s;
        qkv[base + j + 64] = x2 * c + x1 * s;
    }
}

// ---------------------------------------------------------------------------
// Flash attention, fp32, causal (unchanged from passing round).
// ---------------------------------------------------------------------------
#define FL_SMEM_FLOATS (128*64 + 128*64 + 64*128 + 64*65 + 3*64)
#define FL_SMEM_BYTES  (FL_SMEM_FLOATS * 4)

__global__ __launch_bounds__(256) void flash_kernel(
    const float* __restrict__ qkv, float* __restrict__ out)
{
    extern __shared__ float sm[];
    float* Qs = sm;
    float* Ks = Qs + 128 * 64;
    float* Vs = Ks + 128 * 64;
    float* Ss = Vs + 64 * 128;
    float* mrow = Ss + 64 * 65;
    float* lrow = mrow + 64;
    float* arow = lrow + 64;

    const int qt = blockIdx.x;
    const int bh = blockIdx.y;
    const int b = bh >> 4;
    const int h = bh & 15;
    const int q0 = qt * 64;

    const int t = threadIdx.x;
    const int tx = t & 15;
    const int ty = t >> 4;

    const float scale = 0.08838834764831845f;

    for (int i = t; i < 64 * 32; i += 256) {
        const int r = i >> 5;
        const int d4 = (i & 31) * 4;
        const float4 v = *(const float4*)
            &qkv[(size_t)(b * SEQ + q0 + r) * QKV_N + h * HEAD_DIM + d4];
        Qs[(d4 + 0) * 64 + r] = v.x * scale;
        Qs[(d4 + 1) * 64 + r] = v.y * scale;
        Qs[(d4 + 2) * 64 + r] = v.z * scale;
        Qs[(d4 + 3) * 64 + r] = v.w * scale;
    }
    if (t < 64) { mrow[t] = -INFINITY; lrow[t] = 0.0f; }

    float acc[4][8];
    #pragma unroll
    for (int i = 0; i < 4; i++)
        #pragma unroll
        for (int j = 0; j < 8; j++) acc[i][j] = 0.0f;

    for (int kt = 0; kt <= qt; ++kt) {
        const int k0 = kt * 64;
        __syncthreads();

        for (int i = t; i < 64 * 32; i += 256) {
            const int r = i >> 5;
            const int d4 = (i & 31) * 4;
            const size_t gb = (size_t)(b * SEQ + k0 + r) * QKV_N + h * HEAD_DIM + d4;
            const float4 kv = *(const float4*)&qkv[gb + HIDDEN];
            Ks[(d4 + 0) * 64 + r] = kv.x;
            Ks[(d4 + 1) * 64 + r] = kv.y;
            Ks[(d4 + 2) * 64 + r] = kv.z;
            Ks[(d4 + 3) * 64 + r] = kv.w;
            *(float4*)&Vs[r * 128 + d4] = *(const float4*)&qkv[gb + 2 * HIDDEN];
        }
        __syncthreads();

        float s[4][4];
        #pragma unroll
        for (int i = 0; i < 4; i++)
            #pragma unroll
            for (int j = 0; j < 4; j++) s[i][j] = 0.0f;

        for (int d = 0; d < 128; ++d) {
            float qv[4], kv[4];
            #pragma unroll
            for (int i = 0; i < 4; i++) qv[i] = Qs[d * 64 + ty + 16 * i];
            #pragma unroll
            for (int j = 0; j < 4; j++) kv[j] = Ks[d * 64 + tx + 16 * j];
            #pragma unroll
            for (int i = 0; i < 4; i++)
                #pragma unroll
                for (int j = 0; j < 4; j++)
                    s[i][j] = fmaf(qv[i], kv[j], s[i][j]);
        }

        const bool diag = (kt == qt);
        #pragma unroll
        for (int i = 0; i < 4; i++) {
            const int r = ty + 16 * i;
            #pragma unroll
            for (int j = 0; j < 4; j++) {
                const int c = tx + 16 * j;
                float val = s[i][j];
                if (diag && c > r) val = -INFINITY;
                Ss[r * 65 + c] = val;
            }
        }
        __syncthreads();

        if (t < 64) {
            const int r = t;
            const float m_old = mrow[r];
            float mx = m_old;
            #pragma unroll 8
            for (int c = 0; c < 64; c++) mx = fmaxf(mx, Ss[r * 65 + c]);
            const float al = __expf(m_old - mx);
            float sum = 0.0f;
            #pragma unroll 8
            for (int c = 0; c < 64; c++) {
                const float p = __expf(Ss[r * 65 + c] - mx);
                Ss[r * 65 + c] = p;
                sum += p;
            }
            lrow[r] = lrow[r] * al + sum;
            mrow[r] = mx;
            arow[r] = al;
        }
        __syncthreads();

        #pragma unroll
        for (int i = 0; i < 4; i++) {
            const float al = arow[ty + 16 * i];
            #pragma unroll
            for (int j = 0; j < 8; j++) acc[i][j] *= al;
        }
        for (int kk = 0; kk < 64; ++kk) {
            float p[4], v[8];
            #pragma unroll
            for (int i = 0; i < 4; i++) p[i] = Ss[(ty + 16 * i) * 65 + kk];
            #pragma unroll
            for (int j = 0; j < 8; j++) v[j] = Vs[kk * 128 + tx + 16 * j];
            #pragma unroll
            for (int i = 0; i < 4; i++)
                #pragma unroll
                for (int j = 0; j < 8; j++)
                    acc[i][j] = fmaf(p[i], v[j], acc[i][j]);
        }
    }

    #pragma unroll
    for (int i = 0; i < 4; i++) {
        const int r = ty + 16 * i;
        const float linv = 1.0f / lrow[r];
        const size_t row_base = (size_t)(b * SEQ + q0 + r) * HIDDEN + h * HEAD_DIM;
        #pragma unroll
        for (int j = 0; j < 8; j++) {
            out[row_base + tx + 16 * j] = acc[i][j] * linv;
        }
    }
}

// ---------------------------------------------------------------------------
// Launch
// ---------------------------------------------------------------------------
extern "C" void kernel_launch(void* const* d_in, const int* in_sizes, int n_in,
                              void* d_out, int out_size)
{
    const float* hidden = (const float*)d_in[0];
    const int*   pos32  = (const int*)d_in[1];
    const float* Wqkv   = (const float*)d_in[2];
    const float* bqkv   = (const float*)d_in[3];
    const float* Wo     = (const float*)d_in[4];
    const float* bo     = (const float*)d_in[5];
    float* out          = (float*)d_out;

    float* qkv;  cudaGetSymbolAddress((void**)&qkv,  g_qkv);
    float* attn; cudaGetSymbolAddress((void**)&attn, g_attn);
    __nv_bfloat16 *Ahi, *Alo, *Wqh, *Wql, *Woh, *Wol;
    cudaGetSymbolAddress((void**)&Ahi, g_Ahi);
    cudaGetSymbolAddress((void**)&Alo, g_Alo);
    cudaGetSymbolAddress((void**)&Wqh, g_Wqkv_hi);
    cudaGetSymbolAddress((void**)&Wql, g_Wqkv_lo);
    cudaGetSymbolAddress((void**)&Woh, g_Wo_hi);
    cudaGetSymbolAddress((void**)&Wol, g_Wo_lo);

    cudaFuncSetAttribute(gemm_mma_kernel,
                         cudaFuncAttributeMaxDynamicSharedMemorySize,
                         GEMM_SMEM_BYTES);
    cudaFuncSetAttribute(flash_kernel,
                         cudaFuncAttributeMaxDynamicSharedMemorySize,
                         FL_SMEM_BYTES);

    // 0a) split hidden -> Ahi/Alo
    {
        const int n4 = TOKENS * HIDDEN / 4;
        split_kernel<<<(n4 + 255) / 256, 256>>>(hidden, Ahi, Alo, n4);
    }
    // 0b) transpose+split weights
    tsplit_kernel<<<dim3(QKV_N / 32, HIDDEN / 32), 256>>>(Wqkv, Wqh, Wql, HIDDEN, QKV_N);
    tsplit_kernel<<<dim3(HIDDEN / 32, HIDDEN / 32), 256>>>(Wo, Woh, Wol, HIDDEN, HIDDEN);

    // 1) QKV projection (wmma bf16 split): [4096,6144]
    gemm_mma_kernel<<<dim3(QKV_N / 128, TOKENS / 128), 256, GEMM_SMEM_BYTES>>>(
        TOKENS, QKV_N, HIDDEN, Ahi, Alo, Wqh, Wql, bqkv, qkv);

    // 2) RoPE
    rope_kernel<<<TOKENS, 1024>>>(qkv, pos32);

    // 3) Flash attention (fp32)
    flash_kernel<<<dim3(SEQ / 64, BATCH * HEADS), 256, FL_SMEM_BYTES>>>(qkv, attn);

    // 4) split attn -> Ahi/Alo (reuse buffers)
    {
        const int n4 = TOKENS * HIDDEN / 4;
        split_kernel<<<(n4 + 255) / 256, 256>>>(attn, Ahi, Alo, n4);
    }

    // 5) Output projection (wmma bf16 split): [4096,2048]
    gemm_mma_kernel<<<dim3(HIDDEN / 128, TOKENS / 128), 256, GEMM_SMEM_BYTES>>>(
        TOKENS, HIDDEN, HIDDEN, Ahi, Alo, Woh, Wol, bo, out);
}

// round 8
// speedup vs baseline: 2.7586x; 1.8516x over previous
#include <cuda_runtime.h>
#include <cuda_bf16.h>
#include <mma.h>
#include <math.h>
#include <stdint.h>

using namespace nvcuda;

// Problem constants
#define BATCH 2
#define SEQ 2048
#define HIDDEN 2048
#define HEADS 16
#define HEAD_DIM 128
#define TOKENS (BATCH * SEQ)          // 4096
#define QKV_N (3 * HIDDEN)            // 6144

// ---------------------------------------------------------------------------
// Scratch (allocation-free: __device__ globals)
// ---------------------------------------------------------------------------
__device__ float g_qkv[(size_t)TOKENS * QKV_N];     // [token][3*HIDDEN]
// hi/lo bf16 splits of GEMM "A" operand (hidden; later attention output)
__device__ __nv_bfloat16 g_Ahi[(size_t)TOKENS * HIDDEN];
__device__ __nv_bfloat16 g_Alo[(size_t)TOKENS * HIDDEN];
// hi/lo bf16 splits of transposed weights [N,K] K-major
__device__ __nv_bfloat16 g_Wqkv_hi[(size_t)QKV_N * HIDDEN];
__device__ __nv_bfloat16 g_Wqkv_lo[(size_t)QKV_N * HIDDEN];
__device__ __nv_bfloat16 g_Wo_hi[(size_t)HIDDEN * HIDDEN];
__device__ __nv_bfloat16 g_Wo_lo[(size_t)HIDDEN * HIDDEN];
// hi/lo bf16 splits of roped Q (scaled), roped K, V: [b*H+h][s][128]
#define BH (BATCH * HEADS)
__device__ __nv_bfloat16 g_Qh[(size_t)BH * SEQ * HEAD_DIM];
__device__ __nv_bfloat16 g_Ql[(size_t)BH * SEQ * HEAD_DIM];
__device__ __nv_bfloat16 g_Kh[(size_t)BH * SEQ * HEAD_DIM];
__device__ __nv_bfloat16 g_Kl[(size_t)BH * SEQ * HEAD_DIM];
__device__ __nv_bfloat16 g_Vh[(size_t)BH * SEQ * HEAD_DIM];
__device__ __nv_bfloat16 g_Vl[(size_t)BH * SEQ * HEAD_DIM];

// ---------------------------------------------------------------------------
// PTX helpers (sm_80-level, legal on plain compute_103 PTX)
// ---------------------------------------------------------------------------
__device__ __forceinline__ uint32_t smem_to_u32(const void* p) {
    uint32_t a;
    asm("{ .reg .u64 t; cvta.to.shared.u64 t, %1; cvt.u32.u64 %0, t; }"
        : "=r"(a) : "l"(p));
    return a;
}
__device__ __forceinline__ void cp_async16(uint32_t dst, const void* src) {
    asm volatile("cp.async.cg.shared.global [%0], [%1], 16;"
                 :: "r"(dst), "l"(src));
}
__device__ __forceinline__ void cp_commit() {
    asm volatile("cp.async.commit_group;" ::: "memory");
}
template <int N>
__device__ __forceinline__ void cp_wait() {
    asm volatile("cp.async.wait_group %0;" :: "n"(N) : "memory");
}
__device__ __forceinline__ void ldm_x4(uint32_t* r, uint32_t addr) {
    asm volatile("ldmatrix.sync.aligned.m8n8.x4.shared.b16 {%0,%1,%2,%3}, [%4];"
        : "=r"(r[0]), "=r"(r[1]), "=r"(r[2]), "=r"(r[3]) : "r"(addr));
}
__device__ __forceinline__ void ldm_x2(uint32_t* r, uint32_t addr) {
    asm volatile("ldmatrix.sync.aligned.m8n8.x2.shared.b16 {%0,%1}, [%2];"
        : "=r"(r[0]), "=r"(r[1]) : "r"(addr));
}
__device__ __forceinline__ void ldm_x2_trans(uint32_t* r, uint32_t addr) {
    asm volatile("ldmatrix.sync.aligned.m8n8.x2.trans.shared.b16 {%0,%1}, [%2];"
        : "=r"(r[0]), "=r"(r[1]) : "r"(addr));
}
__device__ __forceinline__ void mma_bf16(float* c, const uint32_t* a, const uint32_t* b) {
    asm volatile(
        "mma.sync.aligned.m16n8k16.row.col.f32.bf16.bf16.f32 "
        "{%0,%1,%2,%3}, {%4,%5,%6,%7}, {%8,%9}, {%0,%1,%2,%3};"
        : "+f"(c[0]), "+f"(c[1]), "+f"(c[2]), "+f"(c[3])
        : "r"(a[0]), "r"(a[1]), "r"(a[2]), "r"(a[3]), "r"(b[0]), "r"(b[1]));
}
__device__ __forceinline__ uint32_t pack_bf16(float a, float b) {
    __nv_bfloat162 t;
    t.x = __float2bfloat16(a);
    t.y = __float2bfloat16(b);
    return *(uint32_t*)&t;
}

// ---------------------------------------------------------------------------
// Elementwise hi/lo bf16 split: x -> hi=bf16(x), lo=bf16(x-hi). float4-wide.
// ---------------------------------------------------------------------------
__global__ __launch_bounds__(256) void split_kernel(
    const float* __restrict__ x, __nv_bfloat16* __restrict__ hi,
    __nv_bfloat16* __restrict__ lo, int n4)
{
    const int i = blockIdx.x * 256 + threadIdx.x;
    if (i >= n4) return;
    const float4 v = ((const float4*)x)[i];
    float f[4] = {v.x, v.y, v.z, v.w};
    uint32_t hp[2], lp[2];
    #pragma unroll
    for (int p = 0; p < 2; p++) {
        __nv_bfloat16 h0 = __float2bfloat16(f[2*p]);
        __nv_bfloat16 h1 = __float2bfloat16(f[2*p+1]);
        __nv_bfloat16 l0 = __float2bfloat16(f[2*p]   - __bfloat162float(h0));
        __nv_bfloat16 l1 = __float2bfloat16(f[2*p+1] - __bfloat162float(h1));
        __nv_bfloat162 hh; hh.x = h0; hh.y = h1;
        __nv_bfloat162 ll; ll.x = l0; ll.y = l1;
        hp[p] = *(uint32_t*)&hh;
        lp[p] = *(uint32_t*)&ll;
    }
    ((uint2*)hi)[i] = make_uint2(hp[0], hp[1]);
    ((uint2*)lo)[i] = make_uint2(lp[0], lp[1]);
}

// ---------------------------------------------------------------------------
// Transpose + hi/lo split: W [K,N] fp32 -> Thi/Tlo [N,K] bf16. 32x32 tiles.
// ---------------------------------------------------------------------------
__global__ __launch_bounds__(256) void tsplit_kernel(
    const float* __restrict__ W, __nv_bfloat16* __restrict__ Thi,
    __nv_bfloat16* __restrict__ Tlo, int K, int N)
{
    __shared__ float sm[32][33];
    const int n0 = blockIdx.x * 32;
    const int k0 = blockIdx.y * 32;
    const int tx = threadIdx.x & 31;
    const int ty = threadIdx.x >> 5;
    #pragma unroll
    for (int i = 0; i < 32; i += 8)
        sm[ty + i][tx] = W[(size_t)(k0 + ty + i) * N + n0 + tx];
    __syncthreads();
    #pragma unroll
    for (int i = 0; i < 32; i += 8) {
        const float v = sm[tx][ty + i];
        const __nv_bfloat16 h = __float2bfloat16(v);
        const __nv_bfloat16 l = __float2bfloat16(v - __bfloat162float(h));
        const size_t o = (size_t)(n0 + ty + i) * K + k0 + tx;
        Thi[o] = h;
        Tlo[o] = l;
    }
}

// ---------------------------------------------------------------------------
// wmma bf16 GEMM with hi/lo split (unchanged, passing): C = A @ B^T + bias
// ---------------------------------------------------------------------------
#define ROWPAD 40
#define TILE_SM_BYTES (128 * ROWPAD * 2)
#define STAGE_BYTES   (4 * TILE_SM_BYTES)
#define BIAS_LDM 136
#define GEMM_SMEM_BYTES (2 * STAGE_BYTES + 16 * BIAS_LDM * 4)

__global__ __launch_bounds__(256) void gemm_mma_kernel(
    int M, int Ntot, int K,
    const __nv_bfloat16* __restrict__ Ahi, const __nv_bfloat16* __restrict__ Alo,
    const __nv_bfloat16* __restrict__ Bhi, const __nv_bfloat16* __restrict__ Blo,
    const float* __restrict__ bias, float* __restrict__ C)
{
    extern __shared__ char smem[];
    char* stage0 = smem;
    char* stage1 = smem + STAGE_BYTES;
    float* bias_tile = (float*)(smem + 2 * STAGE_BYTES);
    const uint32_t smem_u32 = smem_to_u32(smem);

    const int t = threadIdx.x;
    const int wid = t >> 5;
    const int warpM = wid & 3;
    const int warpN = wid >> 2;
    const int m0 = blockIdx.y * 128;
    const int n0 = blockIdx.x * 128;

    for (int u = t; u < 16 * 128; u += 256) {
        const int r = u >> 7;
        const int c = u & 127;
        bias_tile[r * BIAS_LDM + c] = __ldg(bias + n0 + c);
    }
    __syncthreads();

    wmma::fragment<wmma::accumulator, 16, 16, 16, float> acc[2][4];
    #pragma unroll
    for (int mt = 0; mt < 2; mt++)
        #pragma unroll
        for (int nt = 0; nt < 4; nt++)
            wmma::load_matrix_sync(acc[mt][nt],
                bias_tile + warpN * 64 + nt * 16, BIAS_LDM, wmma::mem_row_major);

    const int Ku4 = K >> 3;
    const uint4* srcs[4] = {
        (const uint4*)Ahi + (size_t)m0 * Ku4,
        (const uint4*)Alo + (size_t)m0 * Ku4,
        (const uint4*)Bhi + (size_t)n0 * Ku4,
        (const uint4*)Blo + (size_t)n0 * Ku4
    };

    const int NC = K >> 5;

    auto load_stage = [&](int chunk, int s) {
        const int kq = chunk << 2;
        const uint32_t sbase = smem_u32 + s * STAGE_BYTES;
        #pragma unroll
        for (int j = 0; j < 8; j++) {
            const int u = t + j * 256;
            const int tile = u >> 9;
            const int row = (u >> 2) & 127;
            const int seg = u & 3;
            const uint4* src = srcs[tile] + (size_t)row * Ku4 + kq + seg;
            const uint32_t dst = sbase + tile * TILE_SM_BYTES + row * 80 + seg * 16;
            cp_async16(dst, src);
        }
        cp_commit();
    };

    load_stage(0, 0);

    for (int i = 0; i < NC; i++) {
        const int s = i & 1;
        if (i + 1 < NC) {
            load_stage(i + 1, s ^ 1);
            cp_wait<1>();
        } else {
            cp_wait<0>();
        }
        __syncthreads();

        const char* st = s ? stage1 : stage0;
        const __nv_bfloat16* Ah = (const __nv_bfloat16*)st;
        const __nv_bfloat16* Al = (const __nv_bfloat16*)(st + TILE_SM_BYTES);
        const __nv_bfloat16* Bh = (const __nv_bfloat16*)(st + 2 * TILE_SM_BYTES);
        const __nv_bfloat16* Bl = (const __nv_bfloat16*)(st + 3 * TILE_SM_BYTES);

        #pragma unroll
        for (int ks = 0; ks < 2; ks++) {
            wmma::fragment<wmma::matrix_a, 16, 16, 16, __nv_bfloat16, wmma::row_major> aH[2], aL[2];
            wmma::fragment<wmma::matrix_b, 16, 16, 16, __nv_bfloat16, wmma::col_major> bH[4], bL[4];
            #pragma unroll
            for (int mt = 0; mt < 2; mt++) {
                const int r = warpM * 32 + mt * 16;
                wmma::load_matrix_sync(aH[mt], Ah + r * ROWPAD + ks * 16, ROWPAD);
                wmma::load_matrix_sync(aL[mt], Al + r * ROWPAD + ks * 16, ROWPAD);
            }
            #pragma unroll
            for (int nt = 0; nt < 4; nt++) {
                const int r = warpN * 64 + nt * 16;
                wmma::load_matrix_sync(bH[nt], Bh + r * ROWPAD + ks * 16, ROWPAD);
                wmma::load_matrix_sync(bL[nt], Bl + r * ROWPAD + ks * 16, ROWPAD);
            }
            #pragma unroll
            for (int mt = 0; mt < 2; mt++)
                #pragma unroll
                for (int nt = 0; nt < 4; nt++) {
                    wmma::mma_sync(acc[mt][nt], aH[mt], bH[nt], acc[mt][nt]);
                    wmma::mma_sync(acc[mt][nt], aH[mt], bL[nt], acc[mt][nt]);
                    wmma::mma_sync(acc[mt][nt], aL[mt], bH[nt], acc[mt][nt]);
                }
        }
        __syncthreads();
    }

    #pragma unroll
    for (int mt = 0; mt < 2; mt++)
        #pragma unroll
        for (int nt = 0; nt < 4; nt++) {
            float* dst = C + (size_t)(m0 + warpM * 32 + mt * 16) * Ntot
                           + n0 + warpN * 64 + nt * 16;
            wmma::store_matrix_sync(dst, acc[mt][nt], Ntot, wmma::mem_row_major);
        }
}

// ---------------------------------------------------------------------------
// RoPE + scale + hi/lo split into per-head-contiguous Q/K/V buffers.
// grid = TOKENS, 1024 threads. Position buffer int32-or-int64 autodetect.
// ---------------------------------------------------------------------------
__global__ __launch_bounds__(1024) void rope_split_kernel(
    const float* __restrict__ qkv, const int* __restrict__ pos32)
{
    const int token = blockIdx.x;
    const int b = token >> 11;
    const int s = token & 2047;
    const int t = threadIdx.x;
    const int h = t >> 6;
    const int j = t & 63;
    const float scale = 0.08838834764831845f;  // 1/sqrt(128)

    const bool is64 = (pos32[1] == 0);
    const int posi = is64 ? pos32[2 * token] : pos32[token];
    const float pos = (float)posi;

    const float inv = exp2f(-(float)j * 0.20762050595283508f);
    const float ang = pos * inv;
    float sn, cs;
    sincosf(ang, &sn, &cs);

    const size_t tb = (size_t)token * QKV_N;
    const size_t ob = ((size_t)(b * HEADS + h) * SEQ + s) * HEAD_DIM;

    // q (scaled)
    {
        const float x1 = qkv[tb + h * HEAD_DIM + j];
        const float x2 = qkv[tb + h * HEAD_DIM + j + 64];
        const float r1 = (x1 * cs - x2 * sn) * scale;
        const float r2 = (x2 * cs + x1 * sn) * scale;
        const __nv_bfloat16 h1 = __float2bfloat16(r1);
        const __nv_bfloat16 h2 = __float2bfloat16(r2);
        g_Qh[ob + j]      = h1;
        g_Qh[ob + j + 64] = h2;
        g_Ql[ob + j]      = __float2bfloat16(r1 - __bfloat162float(h1));
        g_Ql[ob + j + 64] = __float2bfloat16(r2 - __bfloat162float(h2));
    }
    // k
    {
        const float x1 = qkv[tb + HIDDEN + h * HEAD_DIM + j];
        const float x2 = qkv[tb + HIDDEN + h * HEAD_DIM + j + 64];
        const float r1 = x1 * cs - x2 * sn;
        const float r2 = x2 * cs + x1 * sn;
        const __nv_bfloat16 h1 = __float2bfloat16(r1);
        const __nv_bfloat16 h2 = __float2bfloat16(r2);
        g_Kh[ob + j]      = h1;
        g_Kh[ob + j + 64] = h2;
        g_Kl[ob + j]      = __float2bfloat16(r1 - __bfloat162float(h1));
        g_Kl[ob + j + 64] = __float2bfloat16(r2 - __bfloat162float(h2));
    }
    // v: thread t handles elements t and t+1024 of the 2048-wide v row
    #pragma unroll
    for (int rep = 0; rep < 2; rep++) {
        const int e = t + rep * 1024;
        const int hv = e >> 7;
        const int dv = e & 127;
        const float x = qkv[tb + 2 * HIDDEN + e];
        const __nv_bfloat16 hb = __float2bfloat16(x);
        const size_t vo = ((size_t)(b * HEADS + hv) * SEQ + s) * HEAD_DIM + dv;
        g_Vh[vo] = hb;
        g_Vl[vo] = __float2bfloat16(x - __bfloat162float(hb));
    }
}

// ---------------------------------------------------------------------------
// Tensor-core flash attention (mma.sync m16n8k16 bf16, hi/lo split).
// Block: 128 q-rows x (iterate 64-key tiles), 8 warps. K/V double-buffered.
// S and O live in registers; epilogue writes bf16 hi/lo into g_Ahi/g_Alo.
// ---------------------------------------------------------------------------
#define FLD 136                        // smem row pitch in bf16 (272 bytes)
#define FQ_BYTES  (128 * FLD * 2)      // one Q array (hi or lo): 34816
#define FKV_ARR   (64 * FLD * 2)       // one K/V array: 17408
#define FSTAGE_BYTES (4 * FKV_ARR)     // Kh,Kl,Vh,Vl: 69632
#define FL_SMEM_BYTES (2 * FQ_BYTES + 2 * FSTAGE_BYTES)  // 208896

__global__ __launch_bounds__(256) void flash_mma_kernel()
{
    extern __shared__ char smem[];
    const uint32_t sb = smem_to_u32(smem);
    const uint32_t sQh = sb;
    const uint32_t sQl = sb + FQ_BYTES;
    const uint32_t sKV = sb + 2 * FQ_BYTES;   // + stage*FSTAGE_BYTES

    const int t = threadIdx.x;
    const int w = t >> 5;
    const int lane = t & 31;
    const int qt = (int)gridDim.x - 1 - (int)blockIdx.x;   // big tiles first
    const int bh = blockIdx.y;
    const int b = bh >> 4;
    const int h = bh & 15;
    const int q0 = qt * 128;
    const int nkt = 2 * qt + 2;

    const __nv_bfloat16* Qhg = g_Qh + (size_t)bh * SEQ * HEAD_DIM;
    const __nv_bfloat16* Qlg = g_Ql + (size_t)bh * SEQ * HEAD_DIM;
    const __nv_bfloat16* Khg = g_Kh + (size_t)bh * SEQ * HEAD_DIM;
    const __nv_bfloat16* Klg = g_Kl + (size_t)bh * SEQ * HEAD_DIM;
    const __nv_bfloat16* Vhg = g_Vh + (size_t)bh * SEQ * HEAD_DIM;
    const __nv_bfloat16* Vlg = g_Vl + (size_t)bh * SEQ * HEAD_DIM;

    // Load Q (hi+lo): 4096 16B chunks over 256 threads
    {
        #pragma unroll
        for (int i = 0; i < 16; i++) {
            const int u = t + i * 256;
            const int arr = u >> 11;              // 0=hi, 1=lo
            const int row = (u >> 4) & 127;
            const int ch = u & 15;
            const __nv_bfloat16* src = (arr ? Qlg : Qhg)
                + (size_t)(q0 + row) * HEAD_DIM + ch * 8;
            cp_async16(sb + arr * FQ_BYTES + row * 272 + ch * 16, src);
        }
    }
    // Load KV tile 0 into stage 0 and commit together with Q (group 0)
    auto load_kv = [&](int kt, int stage) {
        const int k0 = kt * 64;
        const uint32_t dstb = sKV + stage * FSTAGE_BYTES;
        const __nv_bfloat16* srcs[4] = {Khg, Klg, Vhg, Vlg};
        #pragma unroll
        for (int i = 0; i < 16; i++) {
            const int u = t + i * 256;
            const int arr = u >> 10;              // Kh,Kl,Vh,Vl
            const int row = (u >> 4) & 63;
            const int ch = u & 15;
            const __nv_bfloat16* src = srcs[arr]
                + (size_t)(k0 + row) * HEAD_DIM + ch * 8;
            cp_async16(dstb + arr * FKV_ARR + row * 272 + ch * 16, src);
        }
        cp_commit();
    };
    load_kv(0, 0);

    // Per-thread state (rows row1 = w*16 + lane>>2, row2 = row1+8)
    const int rloc1 = w * 16 + (lane >> 2);
    const int row1 = q0 + rloc1;
    const int row2 = row1 + 8;
    float m1 = -INFINITY, m2 = -INFINITY, l1 = 0.0f, l2 = 0.0f;
    float sO[16][4];
    #pragma unroll
    for (int f = 0; f < 16; f++)
        #pragma unroll
        for (int e = 0; e < 4; e++) sO[f][e] = 0.0f;

    for (int kt = 0; kt < nkt; kt++) {
        const int st = kt & 1;
        if (kt + 1 < nkt) {
            load_kv(kt + 1, st ^ 1);
            cp_wait<1>();
        } else {
            cp_wait<0>();
        }
        __syncthreads();

        const uint32_t kb = sKV + st * FSTAGE_BYTES;          // Kh
        const uint32_t kbl = kb + FKV_ARR;                    // Kl
        const uint32_t vb = kb + 2 * FKV_ARR;                 // Vh
        const uint32_t vbl = kb + 3 * FKV_ARR;                // Vl
        const int k0 = kt * 64;

        // ---- S = Q K^T (3 split passes), accumulators in regs
        float sS[8][4];
        #pragma unroll
        for (int f = 0; f < 8; f++)
            #pragma unroll
            for (int e = 0; e < 4; e++) sS[f][e] = 0.0f;

        #pragma unroll
        for (int kg = 0; kg < 8; kg++) {
            uint32_t aH[4], aL[4];
            const uint32_t qoff = (w * 16 + (lane & 15)) * 272
                                + (kg * 16 + (lane >> 4) * 8) * 2;
            ldm_x4(aH, sQh + qoff);
            ldm_x4(aL, sQl + qoff);
            #pragma unroll
            for (int f = 0; f < 8; f++) {
                uint32_t bH[2], bL[2];
                const uint32_t koff = (f * 8 + (lane & 7)) * 272
                                    + (kg * 16 + ((lane >> 3) & 1) * 8) * 2;
                ldm_x2(bH, kb + koff);
                ldm_x2(bL, kbl + koff);
                mma_bf16(sS[f], aH, bH);
                mma_bf16(sS[f], aH, bL);
                mma_bf16(sS[f], aL, bH);
            }
        }

        // ---- causal mask (only when this tile can cross the diagonal)
        if (k0 + 63 > row1) {
            #pragma unroll
            for (int f = 0; f < 8; f++)
                #pragma unroll
                for (int e = 0; e < 4; e++) {
                    const int col = k0 + f * 8 + (lane & 3) * 2 + (e & 1);
                    const int rw = (e < 2) ? row1 : row2;
                    if (col > rw) sS[f][e] = -INFINITY;
                }
        }

        // ---- online softmax (quad-shuffle row reductions; no smem)
        float mx1 = -INFINITY, mx2 = -INFINITY;
        #pragma unroll
        for (int f = 0; f < 8; f++) {
            mx1 = fmaxf(mx1, fmaxf(sS[f][0], sS[f][1]));
            mx2 = fmaxf(mx2, fmaxf(sS[f][2], sS[f][3]));
        }
        mx1 = fmaxf(mx1, __shfl_xor_sync(0xffffffffu, mx1, 1));
        mx1 = fmaxf(mx1, __shfl_xor_sync(0xffffffffu, mx1, 2));
        mx2 = fmaxf(mx2, __shfl_xor_sync(0xffffffffu, mx2, 1));
        mx2 = fmaxf(mx2, __shfl_xor_sync(0xffffffffu, mx2, 2));

        const float mn1 = fmaxf(m1, mx1);
        const float mn2 = fmaxf(m2, mx2);
        const float al1 = __expf(m1 - mn1);
        const float al2 = __expf(m2 - mn2);
        m1 = mn1; m2 = mn2;

        float sum1 = 0.0f, sum2 = 0.0f;
        #pragma unroll
        for (int f = 0; f < 8; f++) {
            sS[f][0] = __expf(sS[f][0] - m1);
            sS[f][1] = __expf(sS[f][1] - m1);
            sS[f][2] = __expf(sS[f][2] - m2);
            sS[f][3] = __expf(sS[f][3] - m2);
            sum1 += sS[f][0] + sS[f][1];
            sum2 += sS[f][2] + sS[f][3];
        }
        sum1 += __shfl_xor_sync(0xffffffffu, sum1, 1);
        sum1 += __shfl_xor_sync(0xffffffffu, sum1, 2);
        sum2 += __shfl_xor_sync(0xffffffffu, sum2, 1);
        sum2 += __shfl_xor_sync(0xffffffffu, sum2, 2);
        l1 = l1 * al1 + sum1;
        l2 = l2 * al2 + sum2;

        #pragma unroll
        for (int f = 0; f < 16; f++) {
            sO[f][0] *= al1; sO[f][1] *= al1;
            sO[f][2] *= al2; sO[f][3] *= al2;
        }

        // ---- O += P V (3 split passes); P repacked from S regs directly
        #pragma unroll
        for (int g = 0; g < 4; g++) {
            uint32_t aPh[4], aPl[4];
            {
                const float* p0 = sS[2 * g];
                const float* p1 = sS[2 * g + 1];
                aPh[0] = pack_bf16(p0[0], p0[1]);
                aPh[1] = pack_bf16(p0[2], p0[3]);
                aPh[2] = pack_bf16(p1[0], p1[1]);
                aPh[3] = pack_bf16(p1[2], p1[3]);
                __nv_bfloat162 h0 = *(__nv_bfloat162*)&aPh[0];
                __nv_bfloat162 h1 = *(__nv_bfloat162*)&aPh[1];
                __nv_bfloat162 h2 = *(__nv_bfloat162*)&aPh[2];
                __nv_bfloat162 h3 = *(__nv_bfloat162*)&aPh[3];
                aPl[0] = pack_bf16(p0[0] - __bfloat162float(h0.x),
                                   p0[1] - __bfloat162float(h0.y));
                aPl[1] = pack_bf16(p0[2] - __bfloat162float(h1.x),
                                   p0[3] - __bfloat162float(h1.y));
                aPl[2] = pack_bf16(p1[0] - __bfloat162float(h2.x),
                                   p1[1] - __bfloat162float(h2.y));
                aPl[3] = pack_bf16(p1[2] - __bfloat162float(h3.x),
                                   p1[3] - __bfloat162float(h3.y));
            }
            #pragma unroll
            for (int f2 = 0; f2 < 16; f2++) {
                uint32_t bVh[2], bVl[2];
                const uint32_t voff = (g * 16 + (lane & 15)) * 272 + f2 * 16;
                ldm_x2_trans(bVh, vb + voff);
                ldm_x2_trans(bVl, vbl + voff);
                mma_bf16(sO[f2], aPh, bVh);
                mma_bf16(sO[f2], aPh, bVl);
                mma_bf16(sO[f2], aPl, bVh);
            }
        }
        __syncthreads();
    }

    // ---- epilogue: normalize, split hi/lo, write to g_Ahi/g_Alo
    const float linv1 = 1.0f / l1;
    const float linv2 = 1.0f / l2;
    const size_t tok1 = (size_t)(b * SEQ + row1) * HIDDEN + h * HEAD_DIM;
    const size_t tok2 = (size_t)(b * SEQ + row2) * HIDDEN + h * HEAD_DIM;
    #pragma unroll
    for (int f2 = 0; f2 < 16; f2++) {
        const int d = f2 * 8 + (lane & 3) * 2;
        {
            const float v0 = sO[f2][0] * linv1;
            const float v1 = sO[f2][1] * linv1;
            const uint32_t hh = pack_bf16(v0, v1);
            __nv_bfloat162 h2v = *(__nv_bfloat162*)&hh;
            const uint32_t ll = pack_bf16(v0 - __bfloat162float(h2v.x),
                                          v1 - __bfloat162float(h2v.y));
            *(uint32_t*)(g_Ahi + tok1 + d) = hh;
            *(uint32_t*)(g_Alo + tok1 + d) = ll;
        }
        {
            const float v0 = sO[f2][2] * linv2;
            const float v1 = sO[f2][3] * linv2;
            const uint32_t hh = pack_bf16(v0, v1);
            __nv_bfloat162 h2v = *(__nv_bfloat162*)&hh;
            const uint32_t ll = pack_bf16(v0 - __bfloat162float(h2v.x),
                                          v1 - __bfloat162float(h2v.y));
            *(uint32_t*)(g_Ahi + tok2 + d) = hh;
            *(uint32_t*)(g_Alo + tok2 + d) = ll;
        }
    }
}

// ---------------------------------------------------------------------------
// Launch
// ---------------------------------------------------------------------------
extern "C" void kernel_launch(void* const* d_in, const int* in_sizes, int n_in,
                              void* d_out, int out_size)
{
    const float* hidden = (const float*)d_in[0];
    const int*   pos32  = (const int*)d_in[1];
    const float* Wqkv   = (const float*)d_in[2];
    const float* bqkv   = (const float*)d_in[3];
    const float* Wo     = (const float*)d_in[4];
    const float* bo     = (const float*)d_in[5];
    float* out          = (float*)d_out;

    float* qkv;  cudaGetSymbolAddress((void**)&qkv,  g_qkv);
    __nv_bfloat16 *Ahi, *Alo, *Wqh, *Wql, *Woh, *Wol;
    cudaGetSymbolAddress((void**)&Ahi, g_Ahi);
    cudaGetSymbolAddress((void**)&Alo, g_Alo);
    cudaGetSymbolAddress((void**)&Wqh, g_Wqkv_hi);
    cudaGetSymbolAddress((void**)&Wql, g_Wqkv_lo);
    cudaGetSymbolAddress((void**)&Woh, g_Wo_hi);
    cudaGetSymbolAddress((void**)&Wol, g_Wo_lo);

    cudaFuncSetAttribute(gemm_mma_kernel,
                         cudaFuncAttributeMaxDynamicSharedMemorySize,
                         GEMM_SMEM_BYTES);
    cudaFuncSetAttribute(flash_mma_kernel,
                         cudaFuncAttributeMaxDynamicSharedMemorySize,
                         FL_SMEM_BYTES);

    // 0a) split hidden -> Ahi/Alo
    {
        const int n4 = TOKENS * HIDDEN / 4;
        split_kernel<<<(n4 + 255) / 256, 256>>>(hidden, Ahi, Alo, n4);
    }
    // 0b) transpose+split weights
    tsplit_kernel<<<dim3(QKV_N / 32, HIDDEN / 32), 256>>>(Wqkv, Wqh, Wql, HIDDEN, QKV_N);
    tsplit_kernel<<<dim3(HIDDEN / 32, HIDDEN / 32), 256>>>(Wo, Woh, Wol, HIDDEN, HIDDEN);

    // 1) QKV projection
    gemm_mma_kernel<<<dim3(QKV_N / 128, TOKENS / 128), 256, GEMM_SMEM_BYTES>>>(
        TOKENS, QKV_N, HIDDEN, Ahi, Alo, Wqh, Wql, bqkv, qkv);

    // 2) RoPE + scale + split into Q/K/V bf16 hi/lo buffers
    rope_split_kernel<<<TOKENS, 1024>>>(qkv, pos32);

    // 3) Tensor-core flash attention -> writes g_Ahi/g_Alo directly
    flash_mma_kernel<<<dim3(SEQ / 128, BH), 256, FL_SMEM_BYTES>>>();

    // 4) Output projection
    gemm_mma_kernel<<<dim3(HIDDEN / 128, TOKENS / 128), 256, GEMM_SMEM_BYTES>>>(
        TOKENS, HIDDEN, HIDDEN, Ahi, Alo, Woh, Wol, bo, out);
}

// round 9
// speedup vs baseline: 2.9175x; 1.0576x over previous
#include <cuda_runtime.h>
#include <cuda_bf16.h>
#include <mma.h>
#include <math.h>
#include <stdint.h>

using namespace nvcuda;

// Problem constants
#define BATCH 2
#define SEQ 2048
#define HIDDEN 2048
#define HEADS 16
#define HEAD_DIM 128
#define TOKENS (BATCH * SEQ)          // 4096
#define QKV_N (3 * HIDDEN)            // 6144

// ---------------------------------------------------------------------------
// Scratch (allocation-free: __device__ globals)
// ---------------------------------------------------------------------------
__device__ float g_qkv[(size_t)TOKENS * QKV_N];     // [token][3*HIDDEN]
// hi/lo bf16 splits of GEMM "A" operand (hidden; later attention output)
__device__ __nv_bfloat16 g_Ahi[(size_t)TOKENS * HIDDEN];
__device__ __nv_bfloat16 g_Alo[(size_t)TOKENS * HIDDEN];
// hi/lo bf16 splits of transposed weights [N,K] K-major
__device__ __nv_bfloat16 g_Wqkv_hi[(size_t)QKV_N * HIDDEN];
__device__ __nv_bfloat16 g_Wqkv_lo[(size_t)QKV_N * HIDDEN];
__device__ __nv_bfloat16 g_Wo_hi[(size_t)HIDDEN * HIDDEN];
__device__ __nv_bfloat16 g_Wo_lo[(size_t)HIDDEN * HIDDEN];
// hi/lo bf16 splits of roped Q (scaled), roped K, V: [b*H+h][s][128]
#define BH (BATCH * HEADS)
__device__ __nv_bfloat16 g_Qh[(size_t)BH * SEQ * HEAD_DIM];
__device__ __nv_bfloat16 g_Ql[(size_t)BH * SEQ * HEAD_DIM];
__device__ __nv_bfloat16 g_Kh[(size_t)BH * SEQ * HEAD_DIM];
__device__ __nv_bfloat16 g_Kl[(size_t)BH * SEQ * HEAD_DIM];
__device__ __nv_bfloat16 g_Vh[(size_t)BH * SEQ * HEAD_DIM];
__device__ __nv_bfloat16 g_Vl[(size_t)BH * SEQ * HEAD_DIM];

// ---------------------------------------------------------------------------
// PTX helpers (sm_80-level, legal on plain compute_103 PTX)
// ---------------------------------------------------------------------------
__device__ __forceinline__ uint32_t smem_to_u32(const void* p) {
    uint32_t a;
    asm("{ .reg .u64 t; cvta.to.shared.u64 t, %1; cvt.u32.u64 %0, t; }"
        : "=r"(a) : "l"(p));
    return a;
}
__device__ __forceinline__ void cp_async16(uint32_t dst, const void* src) {
    asm volatile("cp.async.cg.shared.global [%0], [%1], 16;"
                 :: "r"(dst), "l"(src));
}
__device__ __forceinline__ void cp_commit() {
    asm volatile("cp.async.commit_group;" ::: "memory");
}
template <int N>
__device__ __forceinline__ void cp_wait() {
    asm volatile("cp.async.wait_group %0;" :: "n"(N) : "memory");
}
__device__ __forceinline__ void ldm_x4(uint32_t* r, uint32_t addr) {
    asm volatile("ldmatrix.sync.aligned.m8n8.x4.shared.b16 {%0,%1,%2,%3}, [%4];"
        : "=r"(r[0]), "=r"(r[1]), "=r"(r[2]), "=r"(r[3]) : "r"(addr));
}
__device__ __forceinline__ void ldm_x2(uint32_t* r, uint32_t addr) {
    asm volatile("ldmatrix.sync.aligned.m8n8.x2.shared.b16 {%0,%1}, [%2];"
        : "=r"(r[0]), "=r"(r[1]) : "r"(addr));
}
__device__ __forceinline__ void ldm_x2_trans(uint32_t* r, uint32_t addr) {
    asm volatile("ldmatrix.sync.aligned.m8n8.x2.trans.shared.b16 {%0,%1}, [%2];"
        : "=r"(r[0]), "=r"(r[1]) : "r"(addr));
}
__device__ __forceinline__ void mma_bf16(float* c, const uint32_t* a, const uint32_t* b) {
    asm volatile(
        "mma.sync.aligned.m16n8k16.row.col.f32.bf16.bf16.f32 "
        "{%0,%1,%2,%3}, {%4,%5,%6,%7}, {%8,%9}, {%0,%1,%2,%3};"
        : "+f"(c[0]), "+f"(c[1]), "+f"(c[2]), "+f"(c[3])
        : "r"(a[0]), "r"(a[1]), "r"(a[2]), "r"(a[3]), "r"(b[0]), "r"(b[1]));
}
__device__ __forceinline__ uint32_t pack_bf16(float a, float b) {
    __nv_bfloat162 t;
    t.x = __float2bfloat16(a);
    t.y = __float2bfloat16(b);
    return *(uint32_t*)&t;
}

// ---------------------------------------------------------------------------
// Elementwise hi/lo bf16 split: x -> hi=bf16(x), lo=bf16(x-hi). float4-wide.
// ---------------------------------------------------------------------------
__global__ __launch_bounds__(256) void split_kernel(
    const float* __restrict__ x, __nv_bfloat16* __restrict__ hi,
    __nv_bfloat16* __restrict__ lo, int n4)
{
    const int i = blockIdx.x * 256 + threadIdx.x;
    if (i >= n4) return;
    const float4 v = ((const float4*)x)[i];
    float f[4] = {v.x, v.y, v.z, v.w};
    uint32_t hp[2], lp[2];
    #pragma unroll
    for (int p = 0; p < 2; p++) {
        __nv_bfloat16 h0 = __float2bfloat16(f[2*p]);
        __nv_bfloat16 h1 = __float2bfloat16(f[2*p+1]);
        __nv_bfloat16 l0 = __float2bfloat16(f[2*p]   - __bfloat162float(h0));
        __nv_bfloat16 l1 = __float2bfloat16(f[2*p+1] - __bfloat162float(h1));
        __nv_bfloat162 hh; hh.x = h0; hh.y = h1;
        __nv_bfloat162 ll; ll.x = l0; ll.y = l1;
        hp[p] = *(uint32_t*)&hh;
        lp[p] = *(uint32_t*)&ll;
    }
    ((uint2*)hi)[i] = make_uint2(hp[0], hp[1]);
    ((uint2*)lo)[i] = make_uint2(lp[0], lp[1]);
}

// ---------------------------------------------------------------------------
// Transpose + hi/lo split: W [K,N] fp32 -> Thi/Tlo [N,K] bf16. 32x32 tiles.
// ---------------------------------------------------------------------------
__global__ __launch_bounds__(256) void tsplit_kernel(
    const float* __restrict__ W, __nv_bfloat16* __restrict__ Thi,
    __nv_bfloat16* __restrict__ Tlo, int K, int N)
{
    __shared__ float sm[32][33];
    const int n0 = blockIdx.x * 32;
    const int k0 = blockIdx.y * 32;
    const int tx = threadIdx.x & 31;
    const int ty = threadIdx.x >> 5;
    #pragma unroll
    for (int i = 0; i < 32; i += 8)
        sm[ty + i][tx] = W[(size_t)(k0 + ty + i) * N + n0 + tx];
    __syncthreads();
    #pragma unroll
    for (int i = 0; i < 32; i += 8) {
        const float v = sm[tx][ty + i];
        const __nv_bfloat16 h = __float2bfloat16(v);
        const __nv_bfloat16 l = __float2bfloat16(v - __bfloat162float(h));
        const size_t o = (size_t)(n0 + ty + i) * K + k0 + tx;
        Thi[o] = h;
        Tlo[o] = l;
    }
}

// ---------------------------------------------------------------------------
// wmma bf16 GEMM with hi/lo split: C = A @ B^T + bias
// CTA tile 128x128, BK=32, 2-stage cp.async pipeline, 256 threads (8 warps,
// warp grid 4Mx2N; each warp 32x64). __launch_bounds__(256,2) -> 2 CTAs/SM;
// inner loop restructured (nt outer, single live B-frag pair) to fit 128 regs.
// ---------------------------------------------------------------------------
#define ROWPAD 40
#define TILE_SM_BYTES (128 * ROWPAD * 2)
#define STAGE_BYTES   (4 * TILE_SM_BYTES)
#define BIAS_LDM 136
#define GEMM_SMEM_BYTES (2 * STAGE_BYTES + 16 * BIAS_LDM * 4)

__global__ __launch_bounds__(256, 2) void gemm_mma_kernel(
    int M, int Ntot, int K,
    const __nv_bfloat16* __restrict__ Ahi, const __nv_bfloat16* __restrict__ Alo,
    const __nv_bfloat16* __restrict__ Bhi, const __nv_bfloat16* __restrict__ Blo,
    const float* __restrict__ bias, float* __restrict__ C)
{
    extern __shared__ char smem[];
    char* stage0 = smem;
    char* stage1 = smem + STAGE_BYTES;
    float* bias_tile = (float*)(smem + 2 * STAGE_BYTES);
    const uint32_t smem_u32 = smem_to_u32(smem);

    const int t = threadIdx.x;
    const int wid = t >> 5;
    const int warpM = wid & 3;
    const int warpN = wid >> 2;
    const int m0 = blockIdx.y * 128;
    const int n0 = blockIdx.x * 128;

    for (int u = t; u < 16 * 128; u += 256) {
        const int r = u >> 7;
        const int c = u & 127;
        bias_tile[r * BIAS_LDM + c] = __ldg(bias + n0 + c);
    }
    __syncthreads();

    wmma::fragment<wmma::accumulator, 16, 16, 16, float> acc[2][4];
    #pragma unroll
    for (int mt = 0; mt < 2; mt++)
        #pragma unroll
        for (int nt = 0; nt < 4; nt++)
            wmma::load_matrix_sync(acc[mt][nt],
                bias_tile + warpN * 64 + nt * 16, BIAS_LDM, wmma::mem_row_major);

    const int Ku4 = K >> 3;
    const uint4* srcs[4] = {
        (const uint4*)Ahi + (size_t)m0 * Ku4,
        (const uint4*)Alo + (size_t)m0 * Ku4,
        (const uint4*)Bhi + (size_t)n0 * Ku4,
        (const uint4*)Blo + (size_t)n0 * Ku4
    };

    const int NC = K >> 5;

    auto load_stage = [&](int chunk, int s) {
        const int kq = chunk << 2;
        const uint32_t sbase = smem_u32 + s * STAGE_BYTES;
        #pragma unroll
        for (int j = 0; j < 8; j++) {
            const int u = t + j * 256;
            const int tile = u >> 9;
            const int row = (u >> 2) & 127;
            const int seg = u & 3;
            const uint4* src = srcs[tile] + (size_t)row * Ku4 + kq + seg;
            const uint32_t dst = sbase + tile * TILE_SM_BYTES + row * 80 + seg * 16;
            cp_async16(dst, src);
        }
        cp_commit();
    };

    load_stage(0, 0);

    for (int i = 0; i < NC; i++) {
        const int s = i & 1;
        if (i + 1 < NC) {
            load_stage(i + 1, s ^ 1);
            cp_wait<1>();
        } else {
            cp_wait<0>();
        }
        __syncthreads();

        const char* st = s ? stage1 : stage0;
        const __nv_bfloat16* Ah = (const __nv_bfloat16*)st;
        const __nv_bfloat16* Al = (const __nv_bfloat16*)(st + TILE_SM_BYTES);
        const __nv_bfloat16* Bh = (const __nv_bfloat16*)(st + 2 * TILE_SM_BYTES);
        const __nv_bfloat16* Bl = (const __nv_bfloat16*)(st + 3 * TILE_SM_BYTES);

        #pragma unroll
        for (int ks = 0; ks < 2; ks++) {
            wmma::fragment<wmma::matrix_a, 16, 16, 16, __nv_bfloat16, wmma::row_major> aH[2], aL[2];
            #pragma unroll
            for (int mt = 0; mt < 2; mt++) {
                const int r = warpM * 32 + mt * 16;
                wmma::load_matrix_sync(aH[mt], Ah + r * ROWPAD + ks * 16, ROWPAD);
                wmma::load_matrix_sync(aL[mt], Al + r * ROWPAD + ks * 16, ROWPAD);
            }
            #pragma unroll
            for (int nt = 0; nt < 4; nt++) {
                wmma::fragment<wmma::matrix_b, 16, 16, 16, __nv_bfloat16, wmma::col_major> bH, bL;
                const int r = warpN * 64 + nt * 16;
                wmma::load_matrix_sync(bH, Bh + r * ROWPAD + ks * 16, ROWPAD);
                wmma::load_matrix_sync(bL, Bl + r * ROWPAD + ks * 16, ROWPAD);
                #pragma unroll
                for (int mt = 0; mt < 2; mt++) {
                    wmma::mma_sync(acc[mt][nt], aH[mt], bH, acc[mt][nt]);
                    wmma::mma_sync(acc[mt][nt], aH[mt], bL, acc[mt][nt]);
                    wmma::mma_sync(acc[mt][nt], aL[mt], bH, acc[mt][nt]);
                }
            }
        }
        __syncthreads();
    }

    #pragma unroll
    for (int mt = 0; mt < 2; mt++)
        #pragma unroll
        for (int nt = 0; nt < 4; nt++) {
            float* dst = C + (size_t)(m0 + warpM * 32 + mt * 16) * Ntot
                           + n0 + warpN * 64 + nt * 16;
            wmma::store_matrix_sync(dst, acc[mt][nt], Ntot, wmma::mem_row_major);
        }
}

// ---------------------------------------------------------------------------
// RoPE + scale + hi/lo split into per-head-contiguous Q/K/V buffers.
// ---------------------------------------------------------------------------
__global__ __launch_bounds__(1024) void rope_split_kernel(
    const float* __restrict__ qkv, const int* __restrict__ pos32)
{
    const int token = blockIdx.x;
    const int b = token >> 11;
    const int s = token & 2047;
    const int t = threadIdx.x;
    const int h = t >> 6;
    const int j = t & 63;
    const float scale = 0.08838834764831845f;  // 1/sqrt(128)

    const bool is64 = (pos32[1] == 0);
    const int posi = is64 ? pos32[2 * token] : pos32[token];
    const float pos = (float)posi;

    const float inv = exp2f(-(float)j * 0.20762050595283508f);
    const float ang = pos * inv;
    float sn, cs;
    sincosf(ang, &sn, &cs);

    const size_t tb = (size_t)token * QKV_N;
    const size_t ob = ((size_t)(b * HEADS + h) * SEQ + s) * HEAD_DIM;

    // q (scaled)
    {
        const float x1 = qkv[tb + h * HEAD_DIM + j];
        const float x2 = qkv[tb + h * HEAD_DIM + j + 64];
        const float r1 = (x1 * cs - x2 * sn) * scale;
        const float r2 = (x2 * cs + x1 * sn) * scale;
        const __nv_bfloat16 h1 = __float2bfloat16(r1);
        const __nv_bfloat16 h2 = __float2bfloat16(r2);
        g_Qh[ob + j]      = h1;
        g_Qh[ob + j + 64] = h2;
        g_Ql[ob + j]      = __float2bfloat16(r1 - __bfloat162float(h1));
        g_Ql[ob + j + 64] = __float2bfloat16(r2 - __bfloat162float(h2));
    }
    // k
    {
        const float x1 = qkv[tb + HIDDEN + h * HEAD_DIM + j];
        const float x2 = qkv[tb + HIDDEN + h * HEAD_DIM + j + 64];
        const float r1 = x1 * cs - x2 * sn;
        const float r2 = x2 * cs + x1 * sn;
        const __nv_bfloat16 h1 = __float2bfloat16(r1);
        const __nv_bfloat16 h2 = __float2bfloat16(r2);
        g_Kh[ob + j]      = h1;
        g_Kh[ob + j + 64] = h2;
        g_Kl[ob + j]      = __float2bfloat16(r1 - __bfloat162float(h1));
        g_Kl[ob + j + 64] = __float2bfloat16(r2 - __bfloat162float(h2));
    }
    // v
    #pragma unroll
    for (int rep = 0; rep < 2; rep++) {
        const int e = t + rep * 1024;
        const int hv = e >> 7;
        const int dv = e & 127;
        const float x = qkv[tb + 2 * HIDDEN + e];
        const __nv_bfloat16 hb = __float2bfloat16(x);
        const size_t vo = ((size_t)(b * HEADS + hv) * SEQ + s) * HEAD_DIM + dv;
        g_Vh[vo] = hb;
        g_Vl[vo] = __float2bfloat16(x - __bfloat162float(hb));
    }
}

// ---------------------------------------------------------------------------
// Tensor-core flash attention (mma.sync m16n8k16 bf16, hi/lo split).
// ---------------------------------------------------------------------------
#define FLD 136
#define FQ_BYTES  (128 * FLD * 2)
#define FKV_ARR   (64 * FLD * 2)
#define FSTAGE_BYTES (4 * FKV_ARR)
#define FL_SMEM_BYTES (2 * FQ_BYTES + 2 * FSTAGE_BYTES)  // 208896

__global__ __launch_bounds__(256) void flash_mma_kernel()
{
    extern __shared__ char smem[];
    const uint32_t sb = smem_to_u32(smem);
    const uint32_t sQh = sb;
    const uint32_t sQl = sb + FQ_BYTES;
    const uint32_t sKV = sb + 2 * FQ_BYTES;

    const int t = threadIdx.x;
    const int w = t >> 5;
    const int lane = t & 31;
    const int qt = (int)gridDim.x - 1 - (int)blockIdx.x;
    const int bh = blockIdx.y;
    const int b = bh >> 4;
    const int h = bh & 15;
    const int q0 = qt * 128;
    const int nkt = 2 * qt + 2;

    const __nv_bfloat16* Qhg = g_Qh + (size_t)bh * SEQ * HEAD_DIM;
    const __nv_bfloat16* Qlg = g_Ql + (size_t)bh * SEQ * HEAD_DIM;
    const __nv_bfloat16* Khg = g_Kh + (size_t)bh * SEQ * HEAD_DIM;
    const __nv_bfloat16* Klg = g_Kl + (size_t)bh * SEQ * HEAD_DIM;
    const __nv_bfloat16* Vhg = g_Vh + (size_t)bh * SEQ * HEAD_DIM;
    const __nv_bfloat16* Vlg = g_Vl + (size_t)bh * SEQ * HEAD_DIM;

    {
        #pragma unroll
        for (int i = 0; i < 16; i++) {
            const int u = t + i * 256;
            const int arr = u >> 11;
            const int row = (u >> 4) & 127;
            const int ch = u & 15;
            const __nv_bfloat16* src = (arr ? Qlg : Qhg)
                + (size_t)(q0 + row) * HEAD_DIM + ch * 8;
            cp_async16(sb + arr * FQ_BYTES + row * 272 + ch * 16, src);
        }
    }
    auto load_kv = [&](int kt, int stage) {
        const int k0 = kt * 64;
        const uint32_t dstb = sKV + stage * FSTAGE_BYTES;
        const __nv_bfloat16* srcs[4] = {Khg, Klg, Vhg, Vlg};
        #pragma unroll
        for (int i = 0; i < 16; i++) {
            const int u = t + i * 256;
            const int arr = u >> 10;
            const int row = (u >> 4) & 63;
            const int ch = u & 15;
            const __nv_bfloat16* src = srcs[arr]
                + (size_t)(k0 + row) * HEAD_DIM + ch * 8;
            cp_async16(dstb + arr * FKV_ARR + row * 272 + ch * 16, src);
        }
        cp_commit();
    };
    load_kv(0, 0);

    const int rloc1 = w * 16 + (lane >> 2);
    const int row1 = q0 + rloc1;
    const int row2 = row1 + 8;
    float m1 = -INFINITY, m2 = -INFINITY, l1 = 0.0f, l2 = 0.0f;
    float sO[16][4];
    #pragma unroll
    for (int f = 0; f < 16; f++)
        #pragma unroll
        for (int e = 0; e < 4; e++) sO[f][e] = 0.0f;

    for (int kt = 0; kt < nkt; kt++) {
        const int st = kt & 1;
        if (kt + 1 < nkt) {
            load_kv(kt + 1, st ^ 1);
            cp_wait<1>();
        } else {
            cp_wait<0>();
        }
        __syncthreads();

        const uint32_t kb = sKV + st * FSTAGE_BYTES;
        const uint32_t kbl = kb + FKV_ARR;
        const uint32_t vb = kb + 2 * FKV_ARR;
        const uint32_t vbl = kb + 3 * FKV_ARR;
        const int k0 = kt * 64;

        float sS[8][4];
        #pragma unroll
        for (int f = 0; f < 8; f++)
            #pragma unroll
            for (int e = 0; e < 4; e++) sS[f][e] = 0.0f;

        #pragma unroll
        for (int kg = 0; kg < 8; kg++) {
            uint32_t aH[4], aL[4];
            const uint32_t qoff = (w * 16 + (lane & 15)) * 272
                                + (kg * 16 + (lane >> 4) * 8) * 2;
            ldm_x4(aH, sQh + qoff);
            ldm_x4(aL, sQl + qoff);
            #pragma unroll
            for (int f = 0; f < 8; f++) {
                uint32_t bH[2], bL[2];
                const uint32_t koff = (f * 8 + (lane & 7)) * 272
                                    + (kg * 16 + ((lane >> 3) & 1) * 8) * 2;
                ldm_x2(bH, kb + koff);
                ldm_x2(bL, kbl + koff);
                mma_bf16(sS[f], aH, bH);
                mma_bf16(sS[f], aH, bL);
                mma_bf16(sS[f], aL, bH);
            }
        }

        if (k0 + 63 > row1) {
            #pragma unroll
            for (int f = 0; f < 8; f++)
                #pragma unroll
                for (int e = 0; e < 4; e++) {
                    const int col = k0 + f * 8 + (lane & 3) * 2 + (e & 1);
                    const int rw = (e < 2) ? row1 : row2;
                    if (col > rw) sS[f][e] = -INFINITY;
                }
        }

        float mx1 = -INFINITY, mx2 = -INFINITY;
        #pragma unroll
        for (int f = 0; f < 8; f++) {
            mx1 = fmaxf(mx1, fmaxf(sS[f][0], sS[f][1]));
            mx2 = fmaxf(mx2, fmaxf(sS[f][2], sS[f][3]));
        }
        mx1 = fmaxf(mx1, __shfl_xor_sync(0xffffffffu, mx1, 1));
        mx1 = fmaxf(mx1, __shfl_xor_sync(0xffffffffu, mx1, 2));
        mx2 = fmaxf(mx2, __shfl_xor_sync(0xffffffffu, mx2, 1));
        mx2 = fmaxf(mx2, __shfl_xor_sync(0xffffffffu, mx2, 2));

        const float mn1 = fmaxf(m1, mx1);
        const float mn2 = fmaxf(m2, mx2);
        const float al1 = __expf(m1 - mn1);
        const float al2 = __expf(m2 - mn2);
        m1 = mn1; m2 = mn2;

        float sum1 = 0.0f, sum2 = 0.0f;
        #pragma unroll
        for (int f = 0; f < 8; f++) {
            sS[f][0] = __expf(sS[f][0] - m1);
            sS[f][1] = __expf(sS[f][1] - m1);
            sS[f][2] = __expf(sS[f][2] - m2);
            sS[f][3] = __expf(sS[f][3] - m2);
            sum1 += sS[f][0] + sS[f][1];
            sum2 += sS[f][2] + sS[f][3];
        }
        sum1 += __shfl_xor_sync(0xffffffffu, sum1, 1);
        sum1 += __shfl_xor_sync(0xffffffffu, sum1, 2);
        sum2 += __shfl_xor_sync(0xffffffffu, sum2, 1);
        sum2 += __shfl_xor_sync(0xffffffffu, sum2, 2);
        l1 = l1 * al1 + sum1;
        l2 = l2 * al2 + sum2;

        #pragma unroll
        for (int f = 0; f < 16; f++) {
            sO[f][0] *= al1; sO[f][1] *= al1;
            sO[f][2] *= al2; sO[f][3] *= al2;
        }

        #pragma unroll
        for (int g = 0; g < 4; g++) {
            uint32_t aPh[4], aPl[4];
            {
                const float* p0 = sS[2 * g];
                const float* p1 = sS[2 * g + 1];
                aPh[0] = pack_bf16(p0[0], p0[1]);
                aPh[1] = pack_bf16(p0[2], p0[3]);
                aPh[2] = pack_bf16(p1[0], p1[1]);
                aPh[3] = pack_bf16(p1[2], p1[3]);
                __nv_bfloat162 h0 = *(__nv_bfloat162*)&aPh[0];
                __nv_bfloat162 h1 = *(__nv_bfloat162*)&aPh[1];
                __nv_bfloat162 h2 = *(__nv_bfloat162*)&aPh[2];
                __nv_bfloat162 h3 = *(__nv_bfloat162*)&aPh[3];
                aPl[0] = pack_bf16(p0[0] - __bfloat162float(h0.x),
                                   p0[1] - __bfloat162float(h0.y));
                aPl[1] = pack_bf16(p0[2] - __bfloat162float(h1.x),
                                   p0[3] - __bfloat162float(h1.y));
                aPl[2] = pack_bf16(p1[0] - __bfloat162float(h2.x),
                                   p1[1] - __bfloat162float(h2.y));
                aPl[3] = pack_bf16(p1[2] - __bfloat162float(h3.x),
                                   p1[3] - __bfloat162float(h3.y));
            }
            #pragma unroll
            for (int f2 = 0; f2 < 16; f2++) {
                uint32_t bVh[2], bVl[2];
                const uint32_t voff = (g * 16 + (lane & 15)) * 272 + f2 * 16;
                ldm_x2_trans(bVh, vb + voff);
                ldm_x2_trans(bVl, vbl + voff);
                mma_bf16(sO[f2], aPh, bVh);
                mma_bf16(sO[f2], aPh, bVl);
                mma_bf16(sO[f2], aPl, bVh);
            }
        }
        __syncthreads();
    }

    const float linv1 = 1.0f / l1;
    const float linv2 = 1.0f / l2;
    const size_t tok1 = (size_t)(b * SEQ + row1) * HIDDEN + h * HEAD_DIM;
    const size_t tok2 = (size_t)(b * SEQ + row2) * HIDDEN + h * HEAD_DIM;
    #pragma unroll
    for (int f2 = 0; f2 < 16; f2++) {
        const int d = f2 * 8 + (lane & 3) * 2;
        {
            const float v0 = sO[f2][0] * linv1;
            const float v1 = sO[f2][1] * linv1;
            const uint32_t hh = pack_bf16(v0, v1);
            __nv_bfloat162 h2v = *(__nv_bfloat162*)&hh;
            const uint32_t ll = pack_bf16(v0 - __bfloat162float(h2v.x),
                                          v1 - __bfloat162float(h2v.y));
            *(uint32_t*)(g_Ahi + tok1 + d) = hh;
            *(uint32_t*)(g_Alo + tok1 + d) = ll;
        }
        {
            const float v0 = sO[f2][2] * linv2;
            const float v1 = sO[f2][3] * linv2;
            const uint32_t hh = pack_bf16(v0, v1);
            __nv_bfloat162 h2v = *(__nv_bfloat162*)&hh;
            const uint32_t ll = pack_bf16(v0 - __bfloat162float(h2v.x),
                                          v1 - __bfloat162float(h2v.y));
            *(uint32_t*)(g_Ahi + tok2 + d) = hh;
            *(uint32_t*)(g_Alo + tok2 + d) = ll;
        }
    }
}

// ---------------------------------------------------------------------------
// Launch
// ---------------------------------------------------------------------------
extern "C" void kernel_launch(void* const* d_in, const int* in_sizes, int n_in,
                              void* d_out, int out_size)
{
    const float* hidden = (const float*)d_in[0];
    const int*   pos32  = (const int*)d_in[1];
    const float* Wqkv   = (const float*)d_in[2];
    const float* bqkv   = (const float*)d_in[3];
    const float* Wo     = (const float*)d_in[4];
    const float* bo     = (const float*)d_in[5];
    float* out          = (float*)d_out;

    float* qkv;  cudaGetSymbolAddress((void**)&qkv,  g_qkv);
    __nv_bfloat16 *Ahi, *Alo, *Wqh, *Wql, *Woh, *Wol;
    cudaGetSymbolAddress((void**)&Ahi, g_Ahi);
    cudaGetSymbolAddress((void**)&Alo, g_Alo);
    cudaGetSymbolAddress((void**)&Wqh, g_Wqkv_hi);
    cudaGetSymbolAddress((void**)&Wql, g_Wqkv_lo);
    cudaGetSymbolAddress((void**)&Woh, g_Wo_hi);
    cudaGetSymbolAddress((void**)&Wol, g_Wo_lo);

    cudaFuncSetAttribute(gemm_mma_kernel,
                         cudaFuncAttributeMaxDynamicSharedMemorySize,
                         GEMM_SMEM_BYTES);
    cudaFuncSetAttribute(flash_mma_kernel,
                         cudaFuncAttributeMaxDynamicSharedMemorySize,
                         FL_SMEM_BYTES);

    // 0a) split hidden -> Ahi/Alo
    {
        const int n4 = TOKENS * HIDDEN / 4;
        split_kernel<<<(n4 + 255) / 256, 256>>>(hidden, Ahi, Alo, n4);
    }
    // 0b) transpose+split weights
    tsplit_kernel<<<dim3(QKV_N / 32, HIDDEN / 32), 256>>>(Wqkv, Wqh, Wql, HIDDEN, QKV_N);
    tsplit_kernel<<<dim3(HIDDEN / 32, HIDDEN / 32), 256>>>(Wo, Woh, Wol, HIDDEN, HIDDEN);

    // 1) QKV projection
    gemm_mma_kernel<<<dim3(QKV_N / 128, TOKENS / 128), 256, GEMM_SMEM_BYTES>>>(
        TOKENS, QKV_N, HIDDEN, Ahi, Alo, Wqh, Wql, bqkv, qkv);

    // 2) RoPE + scale + split into Q/K/V bf16 hi/lo buffers
    rope_split_kernel<<<TOKENS, 1024>>>(qkv, pos32);

    // 3) Tensor-core flash attention -> writes g_Ahi/g_Alo directly
    flash_mma_kernel<<<dim3(SEQ / 128, BH), 256, FL_SMEM_BYTES>>>();

    // 4) Output projection
    gemm_mma_kernel<<<dim3(HIDDEN / 128, TOKENS / 128), 256, GEMM_SMEM_BYTES>>>(
        TOKENS, HIDDEN, HIDDEN, Ahi, Alo, Woh, Wol, bo, out);
}

// round 10
// speedup vs baseline: 3.2397x; 1.1104x over previous
#include <cuda_runtime.h>
#include <cuda_bf16.h>
#include <math.h>
#include <stdint.h>

// Problem constants
#define BATCH 2
#define SEQ 2048
#define HIDDEN 2048
#define HEADS 16
#define HEAD_DIM 128
#define TOKENS (BATCH * SEQ)          // 4096
#define QKV_N (3 * HIDDEN)            // 6144

// ---------------------------------------------------------------------------
// Scratch (allocation-free: __device__ globals)
// ---------------------------------------------------------------------------
__device__ float g_qkv[(size_t)TOKENS * QKV_N];     // [token][3*HIDDEN]
// hi/lo bf16 splits of GEMM "A" operand (hidden; later attention output)
__device__ __nv_bfloat16 g_Ahi[(size_t)TOKENS * HIDDEN];
__device__ __nv_bfloat16 g_Alo[(size_t)TOKENS * HIDDEN];
// hi/lo bf16 splits of transposed weights [N,K] K-major
__device__ __nv_bfloat16 g_Wqkv_hi[(size_t)QKV_N * HIDDEN];
__device__ __nv_bfloat16 g_Wqkv_lo[(size_t)QKV_N * HIDDEN];
__device__ __nv_bfloat16 g_Wo_hi[(size_t)HIDDEN * HIDDEN];
__device__ __nv_bfloat16 g_Wo_lo[(size_t)HIDDEN * HIDDEN];
// hi/lo bf16 splits of roped Q (scaled), roped K, V: [b*H+h][s][128]
#define BH (BATCH * HEADS)
__device__ __nv_bfloat16 g_Qh[(size_t)BH * SEQ * HEAD_DIM];
__device__ __nv_bfloat16 g_Ql[(size_t)BH * SEQ * HEAD_DIM];
__device__ __nv_bfloat16 g_Kh[(size_t)BH * SEQ * HEAD_DIM];
__device__ __nv_bfloat16 g_Kl[(size_t)BH * SEQ * HEAD_DIM];
__device__ __nv_bfloat16 g_Vh[(size_t)BH * SEQ * HEAD_DIM];
__device__ __nv_bfloat16 g_Vl[(size_t)BH * SEQ * HEAD_DIM];

// ---------------------------------------------------------------------------
// PTX helpers (sm_80-level, legal on plain compute_103 PTX)
// ---------------------------------------------------------------------------
__device__ __forceinline__ uint32_t smem_to_u32(const void* p) {
    uint32_t a;
    asm("{ .reg .u64 t; cvta.to.shared.u64 t, %1; cvt.u32.u64 %0, t; }"
        : "=r"(a) : "l"(p));
    return a;
}
__device__ __forceinline__ void cp_async16(uint32_t dst, const void* src) {
    asm volatile("cp.async.cg.shared.global [%0], [%1], 16;"
                 :: "r"(dst), "l"(src));
}
__device__ __forceinline__ void cp_commit() {
    asm volatile("cp.async.commit_group;" ::: "memory");
}
template <int N>
__device__ __forceinline__ void cp_wait() {
    asm volatile("cp.async.wait_group %0;" :: "n"(N) : "memory");
}
__device__ __forceinline__ void ldm_x4(uint32_t* r, uint32_t addr) {
    asm volatile("ldmatrix.sync.aligned.m8n8.x4.shared.b16 {%0,%1,%2,%3}, [%4];"
        : "=r"(r[0]), "=r"(r[1]), "=r"(r[2]), "=r"(r[3]) : "r"(addr));
}
__device__ __forceinline__ void ldm_x2(uint32_t* r, uint32_t addr) {
    asm volatile("ldmatrix.sync.aligned.m8n8.x2.shared.b16 {%0,%1}, [%2];"
        : "=r"(r[0]), "=r"(r[1]) : "r"(addr));
}
__device__ __forceinline__ void ldm_x2_trans(uint32_t* r, uint32_t addr) {
    asm volatile("ldmatrix.sync.aligned.m8n8.x2.trans.shared.b16 {%0,%1}, [%2];"
        : "=r"(r[0]), "=r"(r[1]) : "r"(addr));
}
__device__ __forceinline__ void mma_bf16(float* c, const uint32_t* a, const uint32_t* b) {
    asm volatile(
        "mma.sync.aligned.m16n8k16.row.col.f32.bf16.bf16.f32 "
        "{%0,%1,%2,%3}, {%4,%5,%6,%7}, {%8,%9}, {%0,%1,%2,%3};"
        : "+f"(c[0]), "+f"(c[1]), "+f"(c[2]), "+f"(c[3])
        : "r"(a[0]), "r"(a[1]), "r"(a[2]), "r"(a[3]), "r"(b[0]), "r"(b[1]));
}
__device__ __forceinline__ uint32_t pack_bf16(float a, float b) {
    __nv_bfloat162 t;
    t.x = __float2bfloat16(a);
    t.y = __float2bfloat16(b);
    return *(uint32_t*)&t;
}

// ---------------------------------------------------------------------------
// Elementwise hi/lo bf16 split: x -> hi=bf16(x), lo=bf16(x-hi). float4-wide.
// ---------------------------------------------------------------------------
__global__ __launch_bounds__(256) void split_kernel(
    const float* __restrict__ x, __nv_bfloat16* __restrict__ hi,
    __nv_bfloat16* __restrict__ lo, int n4)
{
    const int i = blockIdx.x * 256 + threadIdx.x;
    if (i >= n4) return;
    const float4 v = ((const float4*)x)[i];
    float f[4] = {v.x, v.y, v.z, v.w};
    uint32_t hp[2], lp[2];
    #pragma unroll
    for (int p = 0; p < 2; p++) {
        __nv_bfloat16 h0 = __float2bfloat16(f[2*p]);
        __nv_bfloat16 h1 = __float2bfloat16(f[2*p+1]);
        __nv_bfloat16 l0 = __float2bfloat16(f[2*p]   - __bfloat162float(h0));
        __nv_bfloat16 l1 = __float2bfloat16(f[2*p+1] - __bfloat162float(h1));
        __nv_bfloat162 hh; hh.x = h0; hh.y = h1;
        __nv_bfloat162 ll; ll.x = l0; ll.y = l1;
        hp[p] = *(uint32_t*)&hh;
        lp[p] = *(uint32_t*)&ll;
    }
    ((uint2*)hi)[i] = make_uint2(hp[0], hp[1]);
    ((uint2*)lo)[i] = make_uint2(lp[0], lp[1]);
}

// ---------------------------------------------------------------------------
// Transpose + hi/lo split: W [K,N] fp32 -> Thi/Tlo [N,K] bf16. 32x32 tiles.
// ---------------------------------------------------------------------------
__global__ __launch_bounds__(256) void tsplit_kernel(
    const float* __restrict__ W, __nv_bfloat16* __restrict__ Thi,
    __nv_bfloat16* __restrict__ Tlo, int K, int N)
{
    __shared__ float sm[32][33];
    const int n0 = blockIdx.x * 32;
    const int k0 = blockIdx.y * 32;
    const int tx = threadIdx.x & 31;
    const int ty = threadIdx.x >> 5;
    #pragma unroll
    for (int i = 0; i < 32; i += 8)
        sm[ty + i][tx] = W[(size_t)(k0 + ty + i) * N + n0 + tx];
    __syncthreads();
    #pragma unroll
    for (int i = 0; i < 32; i += 8) {
        const float v = sm[tx][ty + i];
        const __nv_bfloat16 h = __float2bfloat16(v);
        const __nv_bfloat16 l = __float2bfloat16(v - __bfloat162float(h));
        const size_t o = (size_t)(n0 + ty + i) * K + k0 + tx;
        Thi[o] = h;
        Tlo[o] = l;
    }
}

// ---------------------------------------------------------------------------
// Raw mma.sync bf16 GEMM with hi/lo split: C = A @ B^T + bias
// CTA tile 128x128, BK=32, 2-stage cp.async pipeline, ONE barrier per chunk.
// 8 warps, warp grid 4Mx2N; warp tile 32x64 = acc[2][8][4].
// Fragment index math identical to the (proven) flash QK^T loop; smem row
// pitch 80B = 5*16B (ldmatrix-aligned, bank-conflict-free).
// ---------------------------------------------------------------------------
#define ROWPAD 40
#define TILE_SM_BYTES (128 * ROWPAD * 2)        // 10240
#define STAGE_BYTES   (4 * TILE_SM_BYTES)       // 40960
#define GEMM_SMEM_BYTES (2 * STAGE_BYTES)       // 81920

__global__ __launch_bounds__(256, 2) void gemm_mma_kernel(
    int M, int Ntot, int K,
    const __nv_bfloat16* __restrict__ Ahi, const __nv_bfloat16* __restrict__ Alo,
    const __nv_bfloat16* __restrict__ Bhi, const __nv_bfloat16* __restrict__ Blo,
    const float* __restrict__ bias, float* __restrict__ C)
{
    extern __shared__ char smem[];
    const uint32_t smem_u32 = smem_to_u32(smem);

    const int t = threadIdx.x;
    const int wid = t >> 5;
    const int lane = t & 31;
    const int warpM = wid & 3;      // 0..3 -> 32-row band
    const int warpN = wid >> 2;     // 0..1 -> 64-col band
    const int m0 = blockIdx.y * 128;
    const int n0 = blockIdx.x * 128;

    float acc[2][8][4];
    #pragma unroll
    for (int mt = 0; mt < 2; mt++)
        #pragma unroll
        for (int nt = 0; nt < 8; nt++)
            #pragma unroll
            for (int e = 0; e < 4; e++) acc[mt][nt][e] = 0.0f;

    const int Ku4 = K >> 3;
    const uint4* srcs[4] = {
        (const uint4*)Ahi + (size_t)m0 * Ku4,
        (const uint4*)Alo + (size_t)m0 * Ku4,
        (const uint4*)Bhi + (size_t)n0 * Ku4,
        (const uint4*)Blo + (size_t)n0 * Ku4
    };

    const int NC = K >> 5;

    auto load_stage = [&](int chunk, int s) {
        const int kq = chunk << 2;
        const uint32_t sbase = smem_u32 + s * STAGE_BYTES;
        #pragma unroll
        for (int j = 0; j < 8; j++) {
            const int u = t + j * 256;
            const int tile = u >> 9;
            const int row = (u >> 2) & 127;
            const int seg = u & 3;
            const uint4* src = srcs[tile] + (size_t)row * Ku4 + kq + seg;
            const uint32_t dst = sbase + tile * TILE_SM_BYTES + row * 80 + seg * 16;
            cp_async16(dst, src);
        }
        cp_commit();
    };

    load_stage(0, 0);

    for (int i = 0; i < NC; i++) {
        const int s = i & 1;
        cp_wait<0>();
        __syncthreads();                 // single barrier per chunk
        if (i + 1 < NC) load_stage(i + 1, s ^ 1);  // overlaps compute below

        const uint32_t sb  = smem_u32 + s * STAGE_BYTES;
        const uint32_t sAh = sb;
        const uint32_t sAl = sb + TILE_SM_BYTES;
        const uint32_t sBh = sb + 2 * TILE_SM_BYTES;
        const uint32_t sBl = sb + 3 * TILE_SM_BYTES;

        #pragma unroll
        for (int ks = 0; ks < 2; ks++) {
            uint32_t aH[2][4], aL[2][4];
            #pragma unroll
            for (int mt = 0; mt < 2; mt++) {
                const uint32_t aoff = (warpM * 32 + mt * 16 + (lane & 15)) * 80
                                    + (ks * 16 + (lane >> 4) * 8) * 2;
                ldm_x4(aH[mt], sAh + aoff);
                ldm_x4(aL[mt], sAl + aoff);
            }
            #pragma unroll
            for (int nt = 0; nt < 8; nt++) {
                uint32_t bH[2], bL[2];
                const uint32_t boff = (warpN * 64 + nt * 8 + (lane & 7)) * 80
                                    + (ks * 16 + ((lane >> 3) & 1) * 8) * 2;
                ldm_x2(bH, sBh + boff);
                ldm_x2(bL, sBl + boff);
                #pragma unroll
                for (int mt = 0; mt < 2; mt++) {
                    mma_bf16(acc[mt][nt], aH[mt], bH);
                    mma_bf16(acc[mt][nt], aH[mt], bL);
                    mma_bf16(acc[mt][nt], aL[mt], bH);
                }
            }
        }
        // no trailing barrier: next iteration's wait+sync provides it
    }

    // Epilogue: registers only; bias added here.
    #pragma unroll
    for (int mt = 0; mt < 2; mt++) {
        const int r1 = m0 + warpM * 32 + mt * 16 + (lane >> 2);
        #pragma unroll
        for (int nt = 0; nt < 8; nt++) {
            const int c0 = n0 + warpN * 64 + nt * 8 + (lane & 3) * 2;
            const float b0 = __ldg(bias + c0);
            const float b1 = __ldg(bias + c0 + 1);
            float2 v0, v1;
            v0.x = acc[mt][nt][0] + b0;
            v0.y = acc[mt][nt][1] + b1;
            v1.x = acc[mt][nt][2] + b0;
            v1.y = acc[mt][nt][3] + b1;
            *(float2*)&C[(size_t)r1 * Ntot + c0] = v0;
            *(float2*)&C[(size_t)(r1 + 8) * Ntot + c0] = v1;
        }
    }
}

// ---------------------------------------------------------------------------
// RoPE + scale + hi/lo split into per-head-contiguous Q/K/V buffers.
// ---------------------------------------------------------------------------
__global__ __launch_bounds__(1024) void rope_split_kernel(
    const float* __restrict__ qkv, const int* __restrict__ pos32)
{
    const int token = blockIdx.x;
    const int b = token >> 11;
    const int s = token & 2047;
    const int t = threadIdx.x;
    const int h = t >> 6;
    const int j = t & 63;
    const float scale = 0.08838834764831845f;  // 1/sqrt(128)

    const bool is64 = (pos32[1] == 0);
    const int posi = is64 ? pos32[2 * token] : pos32[token];
    const float pos = (float)posi;

    const float inv = exp2f(-(float)j * 0.20762050595283508f);
    const float ang = pos * inv;
    float sn, cs;
    sincosf(ang, &sn, &cs);

    const size_t tb = (size_t)token * QKV_N;
    const size_t ob = ((size_t)(b * HEADS + h) * SEQ + s) * HEAD_DIM;

    // q (scaled)
    {
        const float x1 = qkv[tb + h * HEAD_DIM + j];
        const float x2 = qkv[tb + h * HEAD_DIM + j + 64];
        const float r1 = (x1 * cs - x2 * sn) * scale;
        const float r2 = (x2 * cs + x1 * sn) * scale;
        const __nv_bfloat16 h1 = __float2bfloat16(r1);
        const __nv_bfloat16 h2 = __float2bfloat16(r2);
        g_Qh[ob + j]      = h1;
        g_Qh[ob + j + 64] = h2;
        g_Ql[ob + j]      = __float2bfloat16(r1 - __bfloat162float(h1));
        g_Ql[ob + j + 64] = __float2bfloat16(r2 - __bfloat162float(h2));
    }
    // k
    {
        const float x1 = qkv[tb + HIDDEN + h * HEAD_DIM + j];
        const float x2 = qkv[tb + HIDDEN + h * HEAD_DIM + j + 64];
        const float r1 = x1 * cs - x2 * sn;
        const float r2 = x2 * cs + x1 * sn;
        const __nv_bfloat16 h1 = __float2bfloat16(r1);
        const __nv_bfloat16 h2 = __float2bfloat16(r2);
        g_Kh[ob + j]      = h1;
        g_Kh[ob + j + 64] = h2;
        g_Kl[ob + j]      = __float2bfloat16(r1 - __bfloat162float(h1));
        g_Kl[ob + j + 64] = __float2bfloat16(r2 - __bfloat162float(h2));
    }
    // v
    #pragma unroll
    for (int rep = 0; rep < 2; rep++) {
        const int e = t + rep * 1024;
        const int hv = e >> 7;
        const int dv = e & 127;
        const float x = qkv[tb + 2 * HIDDEN + e];
        const __nv_bfloat16 hb = __float2bfloat16(x);
        const size_t vo = ((size_t)(b * HEADS + hv) * SEQ + s) * HEAD_DIM + dv;
        g_Vh[vo] = hb;
        g_Vl[vo] = __float2bfloat16(x - __bfloat162float(hb));
    }
}

// ---------------------------------------------------------------------------
// Tensor-core flash attention (mma.sync m16n8k16 bf16, hi/lo split).
// ---------------------------------------------------------------------------
#define FLD 136
#define FQ_BYTES  (128 * FLD * 2)
#define FKV_ARR   (64 * FLD * 2)
#define FSTAGE_BYTES (4 * FKV_ARR)
#define FL_SMEM_BYTES (2 * FQ_BYTES + 2 * FSTAGE_BYTES)  // 208896

__global__ __launch_bounds__(256) void flash_mma_kernel()
{
    extern __shared__ char smem[];
    const uint32_t sb = smem_to_u32(smem);
    const uint32_t sQh = sb;
    const uint32_t sQl = sb + FQ_BYTES;
    const uint32_t sKV = sb + 2 * FQ_BYTES;

    const int t = threadIdx.x;
    const int w = t >> 5;
    const int lane = t & 31;
    const int qt = (int)gridDim.x - 1 - (int)blockIdx.x;
    const int bh = blockIdx.y;
    const int b = bh >> 4;
    const int h = bh & 15;
    const int q0 = qt * 128;
    const int nkt = 2 * qt + 2;

    const __nv_bfloat16* Qhg = g_Qh + (size_t)bh * SEQ * HEAD_DIM;
    const __nv_bfloat16* Qlg = g_Ql + (size_t)bh * SEQ * HEAD_DIM;
    const __nv_bfloat16* Khg = g_Kh + (size_t)bh * SEQ * HEAD_DIM;
    const __nv_bfloat16* Klg = g_Kl + (size_t)bh * SEQ * HEAD_DIM;
    const __nv_bfloat16* Vhg = g_Vh + (size_t)bh * SEQ * HEAD_DIM;
    const __nv_bfloat16* Vlg = g_Vl + (size_t)bh * SEQ * HEAD_DIM;

    {
        #pragma unroll
        for (int i = 0; i < 16; i++) {
            const int u = t + i * 256;
            const int arr = u >> 11;
            const int row = (u >> 4) & 127;
            const int ch = u & 15;
            const __nv_bfloat16* src = (arr ? Qlg : Qhg)
                + (size_t)(q0 + row) * HEAD_DIM + ch * 8;
            cp_async16(sb + arr * FQ_BYTES + row * 272 + ch * 16, src);
        }
    }
    auto load_kv = [&](int kt, int stage) {
        const int k0 = kt * 64;
        const uint32_t dstb = sKV + stage * FSTAGE_BYTES;
        const __nv_bfloat16* srcs[4] = {Khg, Klg, Vhg, Vlg};
        #pragma unroll
        for (int i = 0; i < 16; i++) {
            const int u = t + i * 256;
            const int arr = u >> 10;
            const int row = (u >> 4) & 63;
            const int ch = u & 15;
            const __nv_bfloat16* src = srcs[arr]
                + (size_t)(k0 + row) * HEAD_DIM + ch * 8;
            cp_async16(dstb + arr * FKV_ARR + row * 272 + ch * 16, src);
        }
        cp_commit();
    };
    load_kv(0, 0);

    const int rloc1 = w * 16 + (lane >> 2);
    const int row1 = q0 + rloc1;
    const int row2 = row1 + 8;
    float m1 = -INFINITY, m2 = -INFINITY, l1 = 0.0f, l2 = 0.0f;
    float sO[16][4];
    #pragma unroll
    for (int f = 0; f < 16; f++)
        #pragma unroll
        for (int e = 0; e < 4; e++) sO[f][e] = 0.0f;

    for (int kt = 0; kt < nkt; kt++) {
        const int st = kt & 1;
        if (kt + 1 < nkt) {
            load_kv(kt + 1, st ^ 1);
            cp_wait<1>();
        } else {
            cp_wait<0>();
        }
        __syncthreads();

        const uint32_t kb = sKV + st * FSTAGE_BYTES;
        const uint32_t kbl = kb + FKV_ARR;
        const uint32_t vb = kb + 2 * FKV_ARR;
        const uint32_t vbl = kb + 3 * FKV_ARR;
        const int k0 = kt * 64;

        float sS[8][4];
        #pragma unroll
        for (int f = 0; f < 8; f++)
            #pragma unroll
            for (int e = 0; e < 4; e++) sS[f][e] = 0.0f;

        #pragma unroll
        for (int kg = 0; kg < 8; kg++) {
            uint32_t aH[4], aL[4];
            const uint32_t qoff = (w * 16 + (lane & 15)) * 272
                                + (kg * 16 + (lane >> 4) * 8) * 2;
            ldm_x4(aH, sQh + qoff);
            ldm_x4(aL, sQl + qoff);
            #pragma unroll
            for (int f = 0; f < 8; f++) {
                uint32_t bH[2], bL[2];
                const uint32_t koff = (f * 8 + (lane & 7)) * 272
                                    + (kg * 16 + ((lane >> 3) & 1) * 8) * 2;
                ldm_x2(bH, kb + koff);
                ldm_x2(bL, kbl + koff);
                mma_bf16(sS[f], aH, bH);
                mma_bf16(sS[f], aH, bL);
                mma_bf16(sS[f], aL, bH);
            }
        }

        if (k0 + 63 > row1) {
            #pragma unroll
            for (int f = 0; f < 8; f++)
                #pragma unroll
                for (int e = 0; e < 4; e++) {
                    const int col = k0 + f * 8 + (lane & 3) * 2 + (e & 1);
                    const int rw = (e < 2) ? row1 : row2;
                    if (col > rw) sS[f][e] = -INFINITY;
                }
        }

        float mx1 = -INFINITY, mx2 = -INFINITY;
        #pragma unroll
        for (int f = 0; f < 8; f++) {
            mx1 = fmaxf(mx1, fmaxf(sS[f][0], sS[f][1]));
            mx2 = fmaxf(mx2, fmaxf(sS[f][2], sS[f][3]));
        }
        mx1 = fmaxf(mx1, __shfl_xor_sync(0xffffffffu, mx1, 1));
        mx1 = fmaxf(mx1, __shfl_xor_sync(0xffffffffu, mx1, 2));
        mx2 = fmaxf(mx2, __shfl_xor_sync(0xffffffffu, mx2, 1));
        mx2 = fmaxf(mx2, __shfl_xor_sync(0xffffffffu, mx2, 2));

        const float mn1 = fmaxf(m1, mx1);
        const float mn2 = fmaxf(m2, mx2);
        const float al1 = __expf(m1 - mn1);
        const float al2 = __expf(m2 - mn2);
        m1 = mn1; m2 = mn2;

        float sum1 = 0.0f, sum2 = 0.0f;
        #pragma unroll
        for (int f = 0; f < 8; f++) {
            sS[f][0] = __expf(sS[f][0] - m1);
            sS[f][1] = __expf(sS[f][1] - m1);
            sS[f][2] = __expf(sS[f][2] - m2);
            sS[f][3] = __expf(sS[f][3] - m2);
            sum1 += sS[f][0] + sS[f][1];
            sum2 += sS[f][2] + sS[f][3];
        }
        sum1 += __shfl_xor_sync(0xffffffffu, sum1, 1);
        sum1 += __shfl_xor_sync(0xffffffffu, sum1, 2);
        sum2 += __shfl_xor_sync(0xffffffffu, sum2, 1);
        sum2 += __shfl_xor_sync(0xffffffffu, sum2, 2);
        l1 = l1 * al1 + sum1;
        l2 = l2 * al2 + sum2;

        #pragma unroll
        for (int f = 0; f < 16; f++) {
            sO[f][0] *= al1; sO[f][1] *= al1;
            sO[f][2] *= al2; sO[f][3] *= al2;
        }

        #pragma unroll
        for (int g = 0; g < 4; g++) {
            uint32_t aPh[4], aPl[4];
            {
                const float* p0 = sS[2 * g];
                const float* p1 = sS[2 * g + 1];
                aPh[0] = pack_bf16(p0[0], p0[1]);
                aPh[1] = pack_bf16(p0[2], p0[3]);
                aPh[2] = pack_bf16(p1[0], p1[1]);
                aPh[3] = pack_bf16(p1[2], p1[3]);
                __nv_bfloat162 h0 = *(__nv_bfloat162*)&aPh[0];
                __nv_bfloat162 h1 = *(__nv_bfloat162*)&aPh[1];
                __nv_bfloat162 h2 = *(__nv_bfloat162*)&aPh[2];
                __nv_bfloat162 h3 = *(__nv_bfloat162*)&aPh[3];
                aPl[0] = pack_bf16(p0[0] - __bfloat162float(h0.x),
                                   p0[1] - __bfloat162float(h0.y));
                aPl[1] = pack_bf16(p0[2] - __bfloat162float(h1.x),
                                   p0[3] - __bfloat162float(h1.y));
                aPl[2] = pack_bf16(p1[0] - __bfloat162float(h2.x),
                                   p1[1] - __bfloat162float(h2.y));
                aPl[3] = pack_bf16(p1[2] - __bfloat162float(h3.x),
                                   p1[3] - __bfloat162float(h3.y));
            }
            #pragma unroll
            for (int f2 = 0; f2 < 16; f2++) {
                uint32_t bVh[2], bVl[2];
                const uint32_t voff = (g * 16 + (lane & 15)) * 272 + f2 * 16;
                ldm_x2_trans(bVh, vb + voff);
                ldm_x2_trans(bVl, vbl + voff);
                mma_bf16(sO[f2], aPh, bVh);
                mma_bf16(sO[f2], aPh, bVl);
                mma_bf16(sO[f2], aPl, bVh);
            }
        }
        __syncthreads();
    }

    const float linv1 = 1.0f / l1;
    const float linv2 = 1.0f / l2;
    const size_t tok1 = (size_t)(b * SEQ + row1) * HIDDEN + h * HEAD_DIM;
    const size_t tok2 = (size_t)(b * SEQ + row2) * HIDDEN + h * HEAD_DIM;
    #pragma unroll
    for (int f2 = 0; f2 < 16; f2++) {
        const int d = f2 * 8 + (lane & 3) * 2;
        {
            const float v0 = sO[f2][0] * linv1;
            const float v1 = sO[f2][1] * linv1;
            const uint32_t hh = pack_bf16(v0, v1);
            __nv_bfloat162 h2v = *(__nv_bfloat162*)&hh;
            const uint32_t ll = pack_bf16(v0 - __bfloat162float(h2v.x),
                                          v1 - __bfloat162float(h2v.y));
            *(uint32_t*)(g_Ahi + tok1 + d) = hh;
            *(uint32_t*)(g_Alo + tok1 + d) = ll;
        }
        {
            const float v0 = sO[f2][2] * linv2;
            const float v1 = sO[f2][3] * linv2;
            const uint32_t hh = pack_bf16(v0, v1);
            __nv_bfloat162 h2v = *(__nv_bfloat162*)&hh;
            const uint32_t ll = pack_bf16(v0 - __bfloat162float(h2v.x),
                                          v1 - __bfloat162float(h2v.y));
            *(uint32_t*)(g_Ahi + tok2 + d) = hh;
            *(uint32_t*)(g_Alo + tok2 + d) = ll;
        }
    }
}

// ---------------------------------------------------------------------------
// Launch
// ---------------------------------------------------------------------------
extern "C" void kernel_launch(void* const* d_in, const int* in_sizes, int n_in,
                              void* d_out, int out_size)
{
    const float* hidden = (const float*)d_in[0];
    const int*   pos32  = (const int*)d_in[1];
    const float* Wqkv   = (const float*)d_in[2];
    const float* bqkv   = (const float*)d_in[3];
    const float* Wo     = (const float*)d_in[4];
    const float* bo     = (const float*)d_in[5];
    float* out          = (float*)d_out;

    float* qkv;  cudaGetSymbolAddress((void**)&qkv,  g_qkv);
    __nv_bfloat16 *Ahi, *Alo, *Wqh, *Wql, *Woh, *Wol;
    cudaGetSymbolAddress((void**)&Ahi, g_Ahi);
    cudaGetSymbolAddress((void**)&Alo, g_Alo);
    cudaGetSymbolAddress((void**)&Wqh, g_Wqkv_hi);
    cudaGetSymbolAddress((void**)&Wql, g_Wqkv_lo);
    cudaGetSymbolAddress((void**)&Woh, g_Wo_hi);
    cudaGetSymbolAddress((void**)&Wol, g_Wo_lo);

    cudaFuncSetAttribute(gemm_mma_kernel,
                         cudaFuncAttributeMaxDynamicSharedMemorySize,
                         GEMM_SMEM_BYTES);
    cudaFuncSetAttribute(flash_mma_kernel,
                         cudaFuncAttributeMaxDynamicSharedMemorySize,
                         FL_SMEM_BYTES);

    // 0a) split hidden -> Ahi/Alo
    {
        const int n4 = TOKENS * HIDDEN / 4;
        split_kernel<<<(n4 + 255) / 256, 256>>>(hidden, Ahi, Alo, n4);
    }
    // 0b) transpose+split weights
    tsplit_kernel<<<dim3(QKV_N / 32, HIDDEN / 32), 256>>>(Wqkv, Wqh, Wql, HIDDEN, QKV_N);
    tsplit_kernel<<<dim3(HIDDEN / 32, HIDDEN / 32), 256>>>(Wo, Woh, Wol, HIDDEN, HIDDEN);

    // 1) QKV projection
    gemm_mma_kernel<<<dim3(QKV_N / 128, TOKENS / 128), 256, GEMM_SMEM_BYTES>>>(
        TOKENS, QKV_N, HIDDEN, Ahi, Alo, Wqh, Wql, bqkv, qkv);

    // 2) RoPE + scale + split into Q/K/V bf16 hi/lo buffers
    rope_split_kernel<<<TOKENS, 1024>>>(qkv, pos32);

    // 3) Tensor-core flash attention -> writes g_Ahi/g_Alo directly
    flash_mma_kernel<<<dim3(SEQ / 128, BH), 256, FL_SMEM_BYTES>>>();

    // 4) Output projection
    gemm_mma_kernel<<<dim3(HIDDEN / 128, TOKENS / 128), 256, GEMM_SMEM_BYTES>>>(
        TOKENS, HIDDEN, HIDDEN, Ahi, Alo, Woh, Wol, bo, out);
}

// round 13
// speedup vs baseline: 4.1995x; 1.2963x over previous
#include <cuda_runtime.h>
#include <cuda_bf16.h>
#include <cuda_fp16.h>
#include <math.h>
#include <stdint.h>

// Problem constants
#define BATCH 2
#define SEQ 2048
#define HIDDEN 2048
#define HEADS 16
#define HEAD_DIM 128
#define TOKENS (BATCH * SEQ)          // 4096
#define QKV_N (3 * HIDDEN)            // 6144

// ---------------------------------------------------------------------------
// Scratch (allocation-free: __device__ globals)
// ---------------------------------------------------------------------------
__device__ float g_qkv[(size_t)TOKENS * QKV_N];     // [token][3*HIDDEN]
// fp16 hi/lo splits of GEMM "A" operand (hidden; later attention output)
__device__ __half g_Ahi[(size_t)TOKENS * HIDDEN];
__device__ __half g_Alo[(size_t)TOKENS * HIDDEN];
// single-fp16 transposed weights [N,K] K-major
__device__ __half g_Wqkv_h[(size_t)QKV_N * HIDDEN];
__device__ __half g_Wo_h[(size_t)HIDDEN * HIDDEN];
// bf16 hi/lo splits of roped Q (scaled), roped K, V: [b*H+h][s][128]
#define BH (BATCH * HEADS)
__device__ __nv_bfloat16 g_Qh[(size_t)BH * SEQ * HEAD_DIM];
__device__ __nv_bfloat16 g_Ql[(size_t)BH * SEQ * HEAD_DIM];
__device__ __nv_bfloat16 g_Kh[(size_t)BH * SEQ * HEAD_DIM];
__device__ __nv_bfloat16 g_Kl[(size_t)BH * SEQ * HEAD_DIM];
__device__ __nv_bfloat16 g_Vh[(size_t)BH * SEQ * HEAD_DIM];
__device__ __nv_bfloat16 g_Vl[(size_t)BH * SEQ * HEAD_DIM];

// ---------------------------------------------------------------------------
// PTX helpers (sm_80-level, legal on plain compute_103 PTX)
// ---------------------------------------------------------------------------
__device__ __forceinline__ uint32_t smem_to_u32(const void* p) {
    uint32_t a;
    asm("{ .reg .u64 t; cvta.to.shared.u64 t, %1; cvt.u32.u64 %0, t; }"
        : "=r"(a) : "l"(p));
    return a;
}
__device__ __forceinline__ void cp_async16(uint32_t dst, const void* src) {
    asm volatile("cp.async.cg.shared.global [%0], [%1], 16;"
                 :: "r"(dst), "l"(src));
}
__device__ __forceinline__ void cp_commit() {
    asm volatile("cp.async.commit_group;" ::: "memory");
}
template <int N>
__device__ __forceinline__ void cp_wait() {
    asm volatile("cp.async.wait_group %0;" :: "n"(N) : "memory");
}
__device__ __forceinline__ void ldm_x4(uint32_t* r, uint32_t addr) {
    asm volatile("ldmatrix.sync.aligned.m8n8.x4.shared.b16 {%0,%1,%2,%3}, [%4];"
        : "=r"(r[0]), "=r"(r[1]), "=r"(r[2]), "=r"(r[3]) : "r"(addr));
}
__device__ __forceinline__ void ldm_x2(uint32_t* r, uint32_t addr) {
    asm volatile("ldmatrix.sync.aligned.m8n8.x2.shared.b16 {%0,%1}, [%2];"
        : "=r"(r[0]), "=r"(r[1]) : "r"(addr));
}
__device__ __forceinline__ void ldm_x2_trans(uint32_t* r, uint32_t addr) {
    asm volatile("ldmatrix.sync.aligned.m8n8.x2.trans.shared.b16 {%0,%1}, [%2];"
        : "=r"(r[0]), "=r"(r[1]) : "r"(addr));
}
__device__ __forceinline__ void mma_bf16(float* c, const uint32_t* a, const uint32_t* b) {
    asm volatile(
        "mma.sync.aligned.m16n8k16.row.col.f32.bf16.bf16.f32 "
        "{%0,%1,%2,%3}, {%4,%5,%6,%7}, {%8,%9}, {%0,%1,%2,%3};"
        : "+f"(c[0]), "+f"(c[1]), "+f"(c[2]), "+f"(c[3])
        : "r"(a[0]), "r"(a[1]), "r"(a[2]), "r"(a[3]), "r"(b[0]), "r"(b[1]));
}
__device__ __forceinline__ void mma_fp16(float* c, const uint32_t* a, const uint32_t* b) {
    asm volatile(
        "mma.sync.aligned.m16n8k16.row.col.f32.f16.f16.f32 "
        "{%0,%1,%2,%3}, {%4,%5,%6,%7}, {%8,%9}, {%0,%1,%2,%3};"
        : "+f"(c[0]), "+f"(c[1]), "+f"(c[2]), "+f"(c[3])
        : "r"(a[0]), "r"(a[1]), "r"(a[2]), "r"(a[3]), "r"(b[0]), "r"(b[1]));
}
__device__ __forceinline__ uint32_t pack_bf16(float a, float b) {
    __nv_bfloat162 t;
    t.x = __float2bfloat16(a);
    t.y = __float2bfloat16(b);
    return *(uint32_t*)&t;
}
__device__ __forceinline__ uint32_t pack_fp16(float a, float b) {
    __half2 t;
    t.x = __float2half_rn(a);
    t.y = __float2half_rn(b);
    return *(uint32_t*)&t;
}

// ---------------------------------------------------------------------------
// Elementwise fp16 hi/lo split: x -> hi=fp16(x), lo=fp16(x-hi). float4-wide.
// ---------------------------------------------------------------------------
__global__ __launch_bounds__(256) void split_kernel(
    const float* __restrict__ x, __half* __restrict__ hi,
    __half* __restrict__ lo, int n4)
{
    const int i = blockIdx.x * 256 + threadIdx.x;
    if (i >= n4) return;
    const float4 v = ((const float4*)x)[i];
    float f[4] = {v.x, v.y, v.z, v.w};
    uint32_t hp[2], lp[2];
    #pragma unroll
    for (int p = 0; p < 2; p++) {
        const __half h0 = __float2half_rn(f[2*p]);
        const __half h1 = __float2half_rn(f[2*p+1]);
        const __half l0 = __float2half_rn(f[2*p]   - __half2float(h0));
        const __half l1 = __float2half_rn(f[2*p+1] - __half2float(h1));
        __half2 hh; hh.x = h0; hh.y = h1;
        __half2 ll; ll.x = l0; ll.y = l1;
        hp[p] = *(uint32_t*)&hh;
        lp[p] = *(uint32_t*)&ll;
    }
    ((uint2*)hi)[i] = make_uint2(hp[0], hp[1]);
    ((uint2*)lo)[i] = make_uint2(lp[0], lp[1]);
}

// ---------------------------------------------------------------------------
// Transpose to single fp16: W [K,N] fp32 -> T [N,K] fp16. 32x32 tiles.
// ---------------------------------------------------------------------------
__global__ __launch_bounds__(256) void tsplit_kernel(
    const float* __restrict__ W, __half* __restrict__ T, int K, int N)
{
    __shared__ float sm[32][33];
    const int n0 = blockIdx.x * 32;
    const int k0 = blockIdx.y * 32;
    const int tx = threadIdx.x & 31;
    const int ty = threadIdx.x >> 5;
    #pragma unroll
    for (int i = 0; i < 32; i += 8)
        sm[ty + i][tx] = W[(size_t)(k0 + ty + i) * N + n0 + tx];
    __syncthreads();
    #pragma unroll
    for (int i = 0; i < 32; i += 8)
        T[(size_t)(n0 + ty + i) * K + k0 + tx] = __float2half_rn(sm[tx][ty + i]);
}

// ---------------------------------------------------------------------------
// Raw mma.sync fp16 GEMM, asymmetric split: C = (Ahi+Alo) @ B^T + bias
// A: fp16 hi/lo [M,K]; B: single fp16 [N,K]. 2 MMA passes.
// CTA tile 128x128, BK=32, 3-stage cp.async pipeline, one barrier/chunk.
// 8 warps, warp grid 4Mx2N; warp tile 32x64 = acc[2][8][4]. 2 CTAs/SM.
// smem row pitch 80B (ldmatrix-aligned, conflict-free).
// ---------------------------------------------------------------------------
#define G_TILE_BYTES  (128 * 40 * 2)             // 10240
#define G_STAGE_BYTES (3 * G_TILE_BYTES)         // 30720 (Ahi, Alo, B)
#define GEMM_SMEM_BYTES (3 * G_STAGE_BYTES)      // 92160

__global__ __launch_bounds__(256, 2) void gemm_mma_kernel(
    int M, int Ntot, int K,
    const __half* __restrict__ Ahi, const __half* __restrict__ Alo,
    const __half* __restrict__ B,
    const float* __restrict__ bias, float* __restrict__ C)
{
    extern __shared__ char smem[];
    const uint32_t smem_u32 = smem_to_u32(smem);

    const int t = threadIdx.x;
    const int wid = t >> 5;
    const int lane = t & 31;
    const int warpM = wid & 3;      // 0..3 -> 32-row band
    const int warpN = wid >> 2;     // 0..1 -> 64-col band
    const int m0 = blockIdx.y * 128;
    const int n0 = blockIdx.x * 128;

    float acc[2][8][4];
    #pragma unroll
    for (int mt = 0; mt < 2; mt++)
        #pragma unroll
        for (int nt = 0; nt < 8; nt++)
            #pragma unroll
            for (int e = 0; e < 4; e++) acc[mt][nt][e] = 0.0f;

    const int Ku4 = K >> 3;
    const uint4* srcs[3] = {
        (const uint4*)Ahi + (size_t)m0 * Ku4,
        (const uint4*)Alo + (size_t)m0 * Ku4,
        (const uint4*)B   + (size_t)n0 * Ku4
    };

    const int NC = K >> 5;

    auto load_stage = [&](int chunk, int s) {
        const int kq = chunk << 2;
        const uint32_t sbase = smem_u32 + s * G_STAGE_BYTES;
        #pragma unroll
        for (int j = 0; j < 6; j++) {
            const int u = t + j * 256;
            const int tile = u >> 9;
            const int row = (u >> 2) & 127;
            const int seg = u & 3;
            const uint4* src = srcs[tile] + (size_t)row * Ku4 + kq + seg;
            const uint32_t dst = sbase + tile * G_TILE_BYTES + row * 80 + seg * 16;
            cp_async16(dst, src);
        }
        cp_commit();
    };

    load_stage(0, 0);
    load_stage(1, 1);

    for (int i = 0; i < NC; i++) {
        const int s = i - (i / 3) * 3;   // i % 3
        cp_wait<1>();
        __syncthreads();
        if (i + 2 < NC) {
            const int s2 = (i + 2) - ((i + 2) / 3) * 3;
            load_stage(i + 2, s2);
        }

        const uint32_t sb  = smem_u32 + s * G_STAGE_BYTES;
        const uint32_t sAh = sb;
        const uint32_t sAl = sb + G_TILE_BYTES;
        const uint32_t sB  = sb + 2 * G_TILE_BYTES;

        #pragma unroll
        for (int ks = 0; ks < 2; ks++) {
            uint32_t aH[2][4], aL[2][4];
            #pragma unroll
            for (int mt = 0; mt < 2; mt++) {
                const uint32_t aoff = (warpM * 32 + mt * 16 + (lane & 15)) * 80
                                    + (ks * 16 + (lane >> 4) * 8) * 2;
                ldm_x4(aH[mt], sAh + aoff);
                ldm_x4(aL[mt], sAl + aoff);
            }
            // B: load nt-pairs with x4 (lanes 0-15 -> nt, lanes 16-31 -> nt+1)
            uint32_t bfr[8][2];
            #pragma unroll
            for (int nt2 = 0; nt2 < 4; nt2++) {
                uint32_t tmp[4];
                const uint32_t boff =
                    (warpN * 64 + nt2 * 16 + ((lane >> 4) & 1) * 8 + (lane & 7)) * 80
                    + (ks * 16 + ((lane >> 3) & 1) * 8) * 2;
                ldm_x4(tmp, sB + boff);
                bfr[2 * nt2][0] = tmp[0];
                bfr[2 * nt2][1] = tmp[1];
                bfr[2 * nt2 + 1][0] = tmp[2];
                bfr[2 * nt2 + 1][1] = tmp[3];
            }
            #pragma unroll
            for (int nt = 0; nt < 8; nt++)
                #pragma unroll
                for (int mt = 0; mt < 2; mt++) {
                    mma_fp16(acc[mt][nt], aH[mt], bfr[nt]);
                    mma_fp16(acc[mt][nt], aL[mt], bfr[nt]);
                }
        }
    }

    // Epilogue: registers only; bias added here in fp32.
    #pragma unroll
    for (int mt = 0; mt < 2; mt++) {
        const int r1 = m0 + warpM * 32 + mt * 16 + (lane >> 2);
        #pragma unroll
        for (int nt = 0; nt < 8; nt++) {
            const int c0 = n0 + warpN * 64 + nt * 8 + (lane & 3) * 2;
            const float b0 = __ldg(bias + c0);
            const float b1 = __ldg(bias + c0 + 1);
            float2 v0, v1;
            v0.x = acc[mt][nt][0] + b0;
            v0.y = acc[mt][nt][1] + b1;
            v1.x = acc[mt][nt][2] + b0;
            v1.y = acc[mt][nt][3] + b1;
            *(float2*)&C[(size_t)r1 * Ntot + c0] = v0;
            *(float2*)&C[(size_t)(r1 + 8) * Ntot + c0] = v1;
        }
    }
}

// ---------------------------------------------------------------------------
// RoPE + scale + bf16 hi/lo split into per-head-contiguous Q/K/V buffers.
// ---------------------------------------------------------------------------
__global__ __launch_bounds__(1024) void rope_split_kernel(
    const float* __restrict__ qkv, const int* __restrict__ pos32)
{
    const int token = blockIdx.x;
    const int b = token >> 11;
    const int s = token & 2047;
    const int t = threadIdx.x;
    const int h = t >> 6;
    const int j = t & 63;
    const float scale = 0.08838834764831845f;  // 1/sqrt(128)

    const bool is64 = (pos32[1] == 0);
    const int posi = is64 ? pos32[2 * token] : pos32[token];
    const float pos = (float)posi;

    const float inv = exp2f(-(float)j * 0.20762050595283508f);
    const float ang = pos * inv;
    float sn, cs;
    sincosf(ang, &sn, &cs);

    const size_t tb = (size_t)token * QKV_N;
    const size_t ob = ((size_t)(b * HEADS + h) * SEQ + s) * HEAD_DIM;

    // q (scaled)
    {
        const float x1 = qkv[tb + h * HEAD_DIM + j];
        const float x2 = qkv[tb + h * HEAD_DIM + j + 64];
        const float r1 = (x1 * cs - x2 * sn) * scale;
        const float r2 = (x2 * cs + x1 * sn) * scale;
        const __nv_bfloat16 h1 = __float2bfloat16(r1);
        const __nv_bfloat16 h2 = __float2bfloat16(r2);
        g_Qh[ob + j]      = h1;
        g_Qh[ob + j + 64] = h2;
        g_Ql[ob + j]      = __float2bfloat16(r1 - __bfloat162float(h1));
        g_Ql[ob + j + 64] = __float2bfloat16(r2 - __bfloat162float(h2));
    }
    // k
    {
        const float x1 = qkv[tb + HIDDEN + h * HEAD_DIM + j];
        const float x2 = qkv[tb + HIDDEN + h * HEAD_DIM + j + 64];
        const float r1 = x1 * cs - x2 * sn;
        const float r2 = x2 * cs + x1 * sn;
        const __nv_bfloat16 h1 = __float2bfloat16(r1);
        const __nv_bfloat16 h2 = __float2bfloat16(r2);
        g_Kh[ob + j]      = h1;
        g_Kh[ob + j + 64] = h2;
        g_Kl[ob + j]      = __float2bfloat16(r1 - __bfloat162float(h1));
        g_Kl[ob + j + 64] = __float2bfloat16(r2 - __bfloat162float(h2));
    }
    // v
    #pragma unroll
    for (int rep = 0; rep < 2; rep++) {
        const int e = t + rep * 1024;
        const int hv = e >> 7;
        const int dv = e & 127;
        const float x = qkv[tb + 2 * HIDDEN + e];
        const __nv_bfloat16 hb = __float2bfloat16(x);
        const size_t vo = ((size_t)(b * HEADS + hv) * SEQ + s) * HEAD_DIM + dv;
        g_Vh[vo] = hb;
        g_Vl[vo] = __float2bfloat16(x - __bfloat162float(hb));
    }
}

// ---------------------------------------------------------------------------
// Tensor-core flash attention (mma.sync m16n8k16 bf16, hi/lo split).
// Epilogue writes fp16 hi/lo into g_Ahi/g_Alo for the output projection.
// ---------------------------------------------------------------------------
#define FLD 136
#define FQ_BYTES  (128 * FLD * 2)
#define FKV_ARR   (64 * FLD * 2)
#define FSTAGE_BYTES (4 * FKV_ARR)
#define FL_SMEM_BYTES (2 * FQ_BYTES + 2 * FSTAGE_BYTES)  // 208896

__global__ __launch_bounds__(256) void flash_mma_kernel()
{
    extern __shared__ char smem[];
    const uint32_t sb = smem_to_u32(smem);
    const uint32_t sQh = sb;
    const uint32_t sQl = sb + FQ_BYTES;
    const uint32_t sKV = sb + 2 * FQ_BYTES;

    const int t = threadIdx.x;
    const int w = t >> 5;
    const int lane = t & 31;
    const int qt = (int)gridDim.x - 1 - (int)blockIdx.x;
    const int bh = blockIdx.y;
    const int b = bh >> 4;
    const int h = bh & 15;
    const int q0 = qt * 128;
    const int nkt = 2 * qt + 2;

    const __nv_bfloat16* Qhg = g_Qh + (size_t)bh * SEQ * HEAD_DIM;
    const __nv_bfloat16* Qlg = g_Ql + (size_t)bh * SEQ * HEAD_DIM;
    const __nv_bfloat16* Khg = g_Kh + (size_t)bh * SEQ * HEAD_DIM;
    const __nv_bfloat16* Klg = g_Kl + (size_t)bh * SEQ * HEAD_DIM;
    const __nv_bfloat16* Vhg = g_Vh + (size_t)bh * SEQ * HEAD_DIM;
    const __nv_bfloat16* Vlg = g_Vl + (size_t)bh * SEQ * HEAD_DIM;

    {
        #pragma unroll
        for (int i = 0; i < 16; i++) {
            const int u = t + i * 256;
            const int arr = u >> 11;
            const int row = (u >> 4) & 127;
            const int ch = u & 15;
            const __nv_bfloat16* src = (arr ? Qlg : Qhg)
                + (size_t)(q0 + row) * HEAD_DIM + ch * 8;
            cp_async16(sb + arr * FQ_BYTES + row * 272 + ch * 16, src);
        }
    }
    auto load_kv = [&](int kt, int stage) {
        const int k0 = kt * 64;
        const uint32_t dstb = sKV + stage * FSTAGE_BYTES;
        const __nv_bfloat16* srcs[4] = {Khg, Klg, Vhg, Vlg};
        #pragma unroll
        for (int i = 0; i < 16; i++) {
            const int u = t + i * 256;
            const int arr = u >> 10;
            const int row = (u >> 4) & 63;
            const int ch = u & 15;
            const __nv_bfloat16* src = srcs[arr]
                + (size_t)(k0 + row) * HEAD_DIM + ch * 8;
            cp_async16(dstb + arr * FKV_ARR + row * 272 + ch * 16, src);
        }
        cp_commit();
    };
    load_kv(0, 0);

    const int rloc1 = w * 16 + (lane >> 2);
    const int row1 = q0 + rloc1;
    const int row2 = row1 + 8;
    float m1 = -INFINITY, m2 = -INFINITY, l1 = 0.0f, l2 = 0.0f;
    float sO[16][4];
    #pragma unroll
    for (int f = 0; f < 16; f++)
        #pragma unroll
        for (int e = 0; e < 4; e++) sO[f][e] = 0.0f;

    for (int kt = 0; kt < nkt; kt++) {
        const int st = kt & 1;
        if (kt + 1 < nkt) {
            load_kv(kt + 1, st ^ 1);
            cp_wait<1>();
        } else {
            cp_wait<0>();
        }
        __syncthreads();

        const uint32_t kb = sKV + st * FSTAGE_BYTES;
        const uint32_t kbl = kb + FKV_ARR;
        const uint32_t vb = kb + 2 * FKV_ARR;
        const uint32_t vbl = kb + 3 * FKV_ARR;
        const int k0 = kt * 64;

        float sS[8][4];
        #pragma unroll
        for (int f = 0; f < 8; f++)
            #pragma unroll
            for (int e = 0; e < 4; e++) sS[f][e] = 0.0f;

        #pragma unroll
        for (int kg = 0; kg < 8; kg++) {
            uint32_t aH[4], aL[4];
            const uint32_t qoff = (w * 16 + (lane & 15)) * 272
                                + (kg * 16 + (lane >> 4) * 8) * 2;
            ldm_x4(aH, sQh + qoff);
            ldm_x4(aL, sQl + qoff);
            #pragma unroll
            for (int f = 0; f < 8; f++) {
                uint32_t bH[2], bL[2];
                const uint32_t koff = (f * 8 + (lane & 7)) * 272
                                    + (kg * 16 + ((lane >> 3) & 1) * 8) * 2;
                ldm_x2(bH, kb + koff);
                ldm_x2(bL, kbl + koff);
                mma_bf16(sS[f], aH, bH);
                mma_bf16(sS[f], aH, bL);
                mma_bf16(sS[f], aL, bH);
            }
        }

        if (k0 + 63 > row1) {
            #pragma unroll
            for (int f = 0; f < 8; f++)
                #pragma unroll
                for (int e = 0; e < 4; e++) {
                    const int col = k0 + f * 8 + (lane & 3) * 2 + (e & 1);
                    const int rw = (e < 2) ? row1 : row2;
                    if (col > rw) sS[f][e] = -INFINITY;
                }
        }

        float mx1 = -INFINITY, mx2 = -INFINITY;
        #pragma unroll
        for (int f = 0; f < 8; f++) {
            mx1 = fmaxf(mx1, fmaxf(sS[f][0], sS[f][1]));
            mx2 = fmaxf(mx2, fmaxf(sS[f][2], sS[f][3]));
        }
        mx1 = fmaxf(mx1, __shfl_xor_sync(0xffffffffu, mx1, 1));
        mx1 = fmaxf(mx1, __shfl_xor_sync(0xffffffffu, mx1, 2));
        mx2 = fmaxf(mx2, __shfl_xor_sync(0xffffffffu, mx2, 1));
        mx2 = fmaxf(mx2, __shfl_xor_sync(0xffffffffu, mx2, 2));

        const float mn1 = fmaxf(m1, mx1);
        const float mn2 = fmaxf(m2, mx2);
        const float al1 = __expf(m1 - mn1);
        const float al2 = __expf(m2 - mn2);
        m1 = mn1; m2 = mn2;

        float sum1 = 0.0f, sum2 = 0.0f;
        #pragma unroll
        for (int f = 0; f < 8; f++) {
            sS[f][0] = __expf(sS[f][0] - m1);
            sS[f][1] = __expf(sS[f][1] - m1);
            sS[f][2] = __expf(sS[f][2] - m2);
            sS[f][3] = __expf(sS[f][3] - m2);
            sum1 += sS[f][0] + sS[f][1];
            sum2 += sS[f][2] + sS[f][3];
        }
        sum1 += __shfl_xor_sync(0xffffffffu, sum1, 1);
        sum1 += __shfl_xor_sync(0xffffffffu, sum1, 2);
        sum2 += __shfl_xor_sync(0xffffffffu, sum2, 1);
        sum2 += __shfl_xor_sync(0xffffffffu, sum2, 2);
        l1 = l1 * al1 + sum1;
        l2 = l2 * al2 + sum2;

        #pragma unroll
        for (int f = 0; f < 16; f++) {
            sO[f][0] *= al1; sO[f][1] *= al1;
            sO[f][2] *= al2; sO[f][3] *= al2;
        }

        #pragma unroll
        for (int g = 0; g < 4; g++) {
            uint32_t aPh[4], aPl[4];
            {
                const float* p0 = sS[2 * g];
                const float* p1 = sS[2 * g + 1];
                aPh[0] = pack_bf16(p0[0], p0[1]);
                aPh[1] = pack_bf16(p0[2], p0[3]);
                aPh[2] = pack_bf16(p1[0], p1[1]);
                aPh[3] = pack_bf16(p1[2], p1[3]);
                __nv_bfloat162 h0 = *(__nv_bfloat162*)&aPh[0];
                __nv_bfloat162 h1 = *(__nv_bfloat162*)&aPh[1];
                __nv_bfloat162 h2 = *(__nv_bfloat162*)&aPh[2];
                __nv_bfloat162 h3 = *(__nv_bfloat162*)&aPh[3];
                aPl[0] = pack_bf16(p0[0] - __bfloat162float(h0.x),
                                   p0[1] - __bfloat162float(h0.y));
                aPl[1] = pack_bf16(p0[2] - __bfloat162float(h1.x),
                                   p0[3] - __bfloat162float(h1.y));
                aPl[2] = pack_bf16(p1[0] - __bfloat162float(h2.x),
                                   p1[1] - __bfloat162float(h2.y));
                aPl[3] = pack_bf16(p1[2] - __bfloat162float(h3.x),
                                   p1[3] - __bfloat162float(h3.y));
            }
            #pragma unroll
            for (int f2 = 0; f2 < 16; f2++) {
                uint32_t bVh[2], bVl[2];
                const uint32_t voff = (g * 16 + (lane & 15)) * 272 + f2 * 16;
                ldm_x2_trans(bVh, vb + voff);
                ldm_x2_trans(bVl, vbl + voff);
                mma_bf16(sO[f2], aPh, bVh);
                mma_bf16(sO[f2], aPh, bVl);
                mma_bf16(sO[f2], aPl, bVh);
            }
        }
        __syncthreads();
    }

    // epilogue: normalize, fp16 hi/lo split, write to g_Ahi/g_Alo
    const float linv1 = 1.0f / l1;
    const float linv2 = 1.0f / l2;
    const size_t tok1 = (size_t)(b * SEQ + row1) * HIDDEN + h * HEAD_DIM;
    const size_t tok2 = (size_t)(b * SEQ + row2) * HIDDEN + h * HEAD_DIM;
    #pragma unroll
    for (int f2 = 0; f2 < 16; f2++) {
        const int d = f2 * 8 + (lane & 3) * 2;
        {
            const float v0 = sO[f2][0] * linv1;
            const float v1 = sO[f2][1] * linv1;
            const uint32_t hh = pack_fp16(v0, v1);
            __half2 h2v = *(__half2*)&hh;
            const uint32_t ll = pack_fp16(v0 - __half2float(h2v.x),
                                          v1 - __half2float(h2v.y));
            *(uint32_t*)(g_Ahi + tok1 + d) = hh;
            *(uint32_t*)(g_Alo + tok1 + d) = ll;
        }
        {
            const float v0 = sO[f2][2] * linv2;
            const float v1 = sO[f2][3] * linv2;
            const uint32_t hh = pack_fp16(v0, v1);
            __half2 h2v = *(__half2*)&hh;
            const uint32_t ll = pack_fp16(v0 - __half2float(h2v.x),
                                          v1 - __half2float(h2v.y));
            *(uint32_t*)(g_Ahi + tok2 + d) = hh;
            *(uint32_t*)(g_Alo + tok2 + d) = ll;
        }
    }
}

// ---------------------------------------------------------------------------
// Launch
// ---------------------------------------------------------------------------
extern "C" void kernel_launch(void* const* d_in, const int* in_sizes, int n_in,
                              void* d_out, int out_size)
{
    const float* hidden = (const float*)d_in[0];
    const int*   pos32  = (const int*)d_in[1];
    const float* Wqkv   = (const float*)d_in[2];
    const float* bqkv   = (const float*)d_in[3];
    const float* Wo     = (const float*)d_in[4];
    const float* bo     = (const float*)d_in[5];
    float* out          = (float*)d_out;

    float* qkv;  cudaGetSymbolAddress((void**)&qkv,  g_qkv);
    __half *Ahi, *Alo, *Wqh, *Woh;
    cudaGetSymbolAddress((void**)&Ahi, g_Ahi);
    cudaGetSymbolAddress((void**)&Alo, g_Alo);
    cudaGetSymbolAddress((void**)&Wqh, g_Wqkv_h);
    cudaGetSymbolAddress((void**)&Woh, g_Wo_h);

    cudaFuncSetAttribute(gemm_mma_kernel,
                         cudaFuncAttributeMaxDynamicSharedMemorySize,
                         GEMM_SMEM_BYTES);
    cudaFuncSetAttribute(flash_mma_kernel,
                         cudaFuncAttributeMaxDynamicSharedMemorySize,
                         FL_SMEM_BYTES);

    // 0a) split hidden -> Ahi/Alo (fp16)
    {
        const int n4 = TOKENS * HIDDEN / 4;
        split_kernel<<<(n4 + 255) / 256, 256>>>(hidden, Ahi, Alo, n4);
    }
    // 0b) transpose weights to single fp16
    tsplit_kernel<<<dim3(QKV_N / 32, HIDDEN / 32), 256>>>(Wqkv, Wqh, HIDDEN, QKV_N);
    tsplit_kernel<<<dim3(HIDDEN / 32, HIDDEN / 32), 256>>>(Wo, Woh, HIDDEN, HIDDEN);

    // 1) QKV projection (fp16, 2-pass)
    gemm_mma_kernel<<<dim3(QKV_N / 128, TOKENS / 128), 256, GEMM_SMEM_BYTES>>>(
        TOKENS, QKV_N, HIDDEN, Ahi, Alo, Wqh, bqkv, qkv);

    // 2) RoPE + scale + bf16 hi/lo split into Q/K/V buffers
    rope_split_kernel<<<TOKENS, 1024>>>(qkv, pos32);

    // 3) Tensor-core flash attention (bf16 3-pass) -> writes fp16 g_Ahi/g_Alo
    flash_mma_kernel<<<dim3(SEQ / 128, BH), 256, FL_SMEM_BYTES>>>();

    // 4) Output projection (fp16, 2-pass)
    gemm_mma_kernel<<<dim3(HIDDEN / 128, TOKENS / 128), 256, GEMM_SMEM_BYTES>>>(
        TOKENS, HIDDEN, HIDDEN, Ahi, Alo, Woh, bo, out);
}

// round 14
// speedup vs baseline: 5.6707x; 1.3503x over previous
#include <cuda_runtime.h>
#include <cuda_bf16.h>
#include <cuda_fp16.h>
#include <math.h>
#include <stdint.h>

// Problem constants
#define BATCH 2
#define SEQ 2048
#define HIDDEN 2048
#define HEADS 16
#define HEAD_DIM 128
#define TOKENS (BATCH * SEQ)          // 4096
#define QKV_N (3 * HIDDEN)            // 6144

// ---------------------------------------------------------------------------
// Scratch (allocation-free: __device__ globals)
// ---------------------------------------------------------------------------
__device__ float g_qkv[(size_t)TOKENS * QKV_N];     // [token][3*HIDDEN]
// single-fp16 GEMM "A" operand (hidden; later attention output)
__device__ __half g_A[(size_t)TOKENS * HIDDEN];
// single-fp16 transposed weights [N,K] K-major
__device__ __half g_Wqkv_h[(size_t)QKV_N * HIDDEN];
__device__ __half g_Wo_h[(size_t)HIDDEN * HIDDEN];
// bf16 hi/lo splits of roped Q (scaled), roped K, V: [b*H+h][s][128]
#define BH (BATCH * HEADS)
__device__ __nv_bfloat16 g_Qh[(size_t)BH * SEQ * HEAD_DIM];
__device__ __nv_bfloat16 g_Ql[(size_t)BH * SEQ * HEAD_DIM];
__device__ __nv_bfloat16 g_Kh[(size_t)BH * SEQ * HEAD_DIM];
__device__ __nv_bfloat16 g_Kl[(size_t)BH * SEQ * HEAD_DIM];
__device__ __nv_bfloat16 g_Vh[(size_t)BH * SEQ * HEAD_DIM];
__device__ __nv_bfloat16 g_Vl[(size_t)BH * SEQ * HEAD_DIM];

// ---------------------------------------------------------------------------
// PTX helpers (sm_80-level, legal on plain compute_103 PTX)
// ---------------------------------------------------------------------------
__device__ __forceinline__ uint32_t smem_to_u32(const void* p) {
    uint32_t a;
    asm("{ .reg .u64 t; cvta.to.shared.u64 t, %1; cvt.u32.u64 %0, t; }"
        : "=r"(a) : "l"(p));
    return a;
}
__device__ __forceinline__ void cp_async16(uint32_t dst, const void* src) {
    asm volatile("cp.async.cg.shared.global [%0], [%1], 16;"
                 :: "r"(dst), "l"(src));
}
__device__ __forceinline__ void cp_commit() {
    asm volatile("cp.async.commit_group;" ::: "memory");
}
template <int N>
__device__ __forceinline__ void cp_wait() {
    asm volatile("cp.async.wait_group %0;" :: "n"(N) : "memory");
}
__device__ __forceinline__ void ldm_x4(uint32_t* r, uint32_t addr) {
    asm volatile("ldmatrix.sync.aligned.m8n8.x4.shared.b16 {%0,%1,%2,%3}, [%4];"
        : "=r"(r[0]), "=r"(r[1]), "=r"(r[2]), "=r"(r[3]) : "r"(addr));
}
__device__ __forceinline__ void ldm_x2(uint32_t* r, uint32_t addr) {
    asm volatile("ldmatrix.sync.aligned.m8n8.x2.shared.b16 {%0,%1}, [%2];"
        : "=r"(r[0]), "=r"(r[1]) : "r"(addr));
}
__device__ __forceinline__ void ldm_x2_trans(uint32_t* r, uint32_t addr) {
    asm volatile("ldmatrix.sync.aligned.m8n8.x2.trans.shared.b16 {%0,%1}, [%2];"
        : "=r"(r[0]), "=r"(r[1]) : "r"(addr));
}
__device__ __forceinline__ void mma_bf16(float* c, const uint32_t* a, const uint32_t* b) {
    asm volatile(
        "mma.sync.aligned.m16n8k16.row.col.f32.bf16.bf16.f32 "
        "{%0,%1,%2,%3}, {%4,%5,%6,%7}, {%8,%9}, {%0,%1,%2,%3};"
        : "+f"(c[0]), "+f"(c[1]), "+f"(c[2]), "+f"(c[3])
        : "r"(a[0]), "r"(a[1]), "r"(a[2]), "r"(a[3]), "r"(b[0]), "r"(b[1]));
}
__device__ __forceinline__ void mma_fp16(float* c, const uint32_t* a, const uint32_t* b) {
    asm volatile(
        "mma.sync.aligned.m16n8k16.row.col.f32.f16.f16.f32 "
        "{%0,%1,%2,%3}, {%4,%5,%6,%7}, {%8,%9}, {%0,%1,%2,%3};"
        : "+f"(c[0]), "+f"(c[1]), "+f"(c[2]), "+f"(c[3])
        : "r"(a[0]), "r"(a[1]), "r"(a[2]), "r"(a[3]), "r"(b[0]), "r"(b[1]));
}
__device__ __forceinline__ uint32_t pack_bf16(float a, float b) {
    __nv_bfloat162 t;
    t.x = __float2bfloat16(a);
    t.y = __float2bfloat16(b);
    return *(uint32_t*)&t;
}
__device__ __forceinline__ uint32_t pack_fp16(float a, float b) {
    __half2 t;
    t.x = __float2half_rn(a);
    t.y = __float2half_rn(b);
    return *(uint32_t*)&t;
}

// ---------------------------------------------------------------------------
// fp32 -> fp16 convert (A operand). float4-wide.
// ---------------------------------------------------------------------------
__global__ __launch_bounds__(256) void convert_kernel(
    const float* __restrict__ x, __half* __restrict__ y, int n4)
{
    const int i = blockIdx.x * 256 + threadIdx.x;
    if (i >= n4) return;
    const float4 v = ((const float4*)x)[i];
    const uint32_t p0 = pack_fp16(v.x, v.y);
    const uint32_t p1 = pack_fp16(v.z, v.w);
    ((uint2*)y)[i] = make_uint2(p0, p1);
}

// ---------------------------------------------------------------------------
// Transpose to single fp16: W [K,N] fp32 -> T [N,K] fp16. 32x32 tiles.
// ---------------------------------------------------------------------------
__global__ __launch_bounds__(256) void tsplit_kernel(
    const float* __restrict__ W, __half* __restrict__ T, int K, int N)
{
    __shared__ float sm[32][33];
    const int n0 = blockIdx.x * 32;
    const int k0 = blockIdx.y * 32;
    const int tx = threadIdx.x & 31;
    const int ty = threadIdx.x >> 5;
    #pragma unroll
    for (int i = 0; i < 32; i += 8)
        sm[ty + i][tx] = W[(size_t)(k0 + ty + i) * N + n0 + tx];
    __syncthreads();
    #pragma unroll
    for (int i = 0; i < 32; i += 8)
        T[(size_t)(n0 + ty + i) * K + k0 + tx] = __float2half_rn(sm[tx][ty + i]);
}

// ---------------------------------------------------------------------------
// Raw mma.sync fp16 GEMM, single pass: C = A @ B^T + bias
// A: fp16 [M,K]; B: fp16 [N,K]. CTA tile 128x128, BK=32, 3-stage cp.async.
// 8 warps, warp grid 4Mx2N; warp tile 32x64 = acc[2][8][4]. 2 CTAs/SM.
// smem row pitch 80B (ldmatrix-aligned, conflict-free).
// ---------------------------------------------------------------------------
#define G_TILE_BYTES  (128 * 40 * 2)             // 10240
#define G_STAGE_BYTES (2 * G_TILE_BYTES)         // 20480 (A, B)
#define GEMM_SMEM_BYTES (3 * G_STAGE_BYTES)      // 61440

__global__ __launch_bounds__(256, 2) void gemm_mma_kernel(
    int M, int Ntot, int K,
    const __half* __restrict__ A, const __half* __restrict__ B,
    const float* __restrict__ bias, float* __restrict__ C)
{
    extern __shared__ char smem[];
    const uint32_t smem_u32 = smem_to_u32(smem);

    const int t = threadIdx.x;
    const int wid = t >> 5;
    const int lane = t & 31;
    const int warpM = wid & 3;      // 0..3 -> 32-row band
    const int warpN = wid >> 2;     // 0..1 -> 64-col band
    const int m0 = blockIdx.y * 128;
    const int n0 = blockIdx.x * 128;

    float acc[2][8][4];
    #pragma unroll
    for (int mt = 0; mt < 2; mt++)
        #pragma unroll
        for (int nt = 0; nt < 8; nt++)
            #pragma unroll
            for (int e = 0; e < 4; e++) acc[mt][nt][e] = 0.0f;

    const int Ku4 = K >> 3;
    const uint4* srcs[2] = {
        (const uint4*)A + (size_t)m0 * Ku4,
        (const uint4*)B + (size_t)n0 * Ku4
    };

    const int NC = K >> 5;

    auto load_stage = [&](int chunk, int s) {
        const int kq = chunk << 2;
        const uint32_t sbase = smem_u32 + s * G_STAGE_BYTES;
        #pragma unroll
        for (int j = 0; j < 4; j++) {
            const int u = t + j * 256;
            const int tile = u >> 9;
            const int row = (u >> 2) & 127;
            const int seg = u & 3;
            const uint4* src = srcs[tile] + (size_t)row * Ku4 + kq + seg;
            const uint32_t dst = sbase + tile * G_TILE_BYTES + row * 80 + seg * 16;
            cp_async16(dst, src);
        }
        cp_commit();
    };

    load_stage(0, 0);
    load_stage(1, 1);

    for (int i = 0; i < NC; i++) {
        const int s = i - (i / 3) * 3;   // i % 3
        cp_wait<1>();
        __syncthreads();
        if (i + 2 < NC) {
            const int s2 = (i + 2) - ((i + 2) / 3) * 3;
            load_stage(i + 2, s2);
        }

        const uint32_t sb = smem_u32 + s * G_STAGE_BYTES;
        const uint32_t sA = sb;
        const uint32_t sB = sb + G_TILE_BYTES;

        #pragma unroll
        for (int ks = 0; ks < 2; ks++) {
            uint32_t aF[2][4];
            #pragma unroll
            for (int mt = 0; mt < 2; mt++) {
                const uint32_t aoff = (warpM * 32 + mt * 16 + (lane & 15)) * 80
                                    + (ks * 16 + (lane >> 4) * 8) * 2;
                ldm_x4(aF[mt], sA + aoff);
            }
            // B: load nt-pairs with x4 (lanes 0-15 -> nt, lanes 16-31 -> nt+1)
            uint32_t bfr[8][2];
            #pragma unroll
            for (int nt2 = 0; nt2 < 4; nt2++) {
                uint32_t tmp[4];
                const uint32_t boff =
                    (warpN * 64 + nt2 * 16 + ((lane >> 4) & 1) * 8 + (lane & 7)) * 80
                    + (ks * 16 + ((lane >> 3) & 1) * 8) * 2;
                ldm_x4(tmp, sB + boff);
                bfr[2 * nt2][0] = tmp[0];
                bfr[2 * nt2][1] = tmp[1];
                bfr[2 * nt2 + 1][0] = tmp[2];
                bfr[2 * nt2 + 1][1] = tmp[3];
            }
            #pragma unroll
            for (int nt = 0; nt < 8; nt++)
                #pragma unroll
                for (int mt = 0; mt < 2; mt++)
                    mma_fp16(acc[mt][nt], aF[mt], bfr[nt]);
        }
    }

    // Epilogue: registers only; bias added here in fp32.
    #pragma unroll
    for (int mt = 0; mt < 2; mt++) {
        const int r1 = m0 + warpM * 32 + mt * 16 + (lane >> 2);
        #pragma unroll
        for (int nt = 0; nt < 8; nt++) {
            const int c0 = n0 + warpN * 64 + nt * 8 + (lane & 3) * 2;
            const float b0 = __ldg(bias + c0);
            const float b1 = __ldg(bias + c0 + 1);
            float2 v0, v1;
            v0.x = acc[mt][nt][0] + b0;
            v0.y = acc[mt][nt][1] + b1;
            v1.x = acc[mt][nt][2] + b0;
            v1.y = acc[mt][nt][3] + b1;
            *(float2*)&C[(size_t)r1 * Ntot + c0] = v0;
            *(float2*)&C[(size_t)(r1 + 8) * Ntot + c0] = v1;
        }
    }
}

// ---------------------------------------------------------------------------
// RoPE + scale + bf16 hi/lo split into per-head-contiguous Q/K/V buffers.
// ---------------------------------------------------------------------------
__global__ __launch_bounds__(1024) void rope_split_kernel(
    const float* __restrict__ qkv, const int* __restrict__ pos32)
{
    const int token = blockIdx.x;
    const int b = token >> 11;
    const int s = token & 2047;
    const int t = threadIdx.x;
    const int h = t >> 6;
    const int j = t & 63;
    const float scale = 0.08838834764831845f;  // 1/sqrt(128)

    const bool is64 = (pos32[1] == 0);
    const int posi = is64 ? pos32[2 * token] : pos32[token];
    const float pos = (float)posi;

    const float inv = exp2f(-(float)j * 0.20762050595283508f);
    const float ang = pos * inv;
    float sn, cs;
    sincosf(ang, &sn, &cs);

    const size_t tb = (size_t)token * QKV_N;
    const size_t ob = ((size_t)(b * HEADS + h) * SEQ + s) * HEAD_DIM;

    // q (scaled)
    {
        const float x1 = qkv[tb + h * HEAD_DIM + j];
        const float x2 = qkv[tb + h * HEAD_DIM + j + 64];
        const float r1 = (x1 * cs - x2 * sn) * scale;
        const float r2 = (x2 * cs + x1 * sn) * scale;
        const __nv_bfloat16 h1 = __float2bfloat16(r1);
        const __nv_bfloat16 h2 = __float2bfloat16(r2);
        g_Qh[ob + j]      = h1;
        g_Qh[ob + j + 64] = h2;
        g_Ql[ob + j]      = __float2bfloat16(r1 - __bfloat162float(h1));
        g_Ql[ob + j + 64] = __float2bfloat16(r2 - __bfloat162float(h2));
    }
    // k
    {
        const float x1 = qkv[tb + HIDDEN + h * HEAD_DIM + j];
        const float x2 = qkv[tb + HIDDEN + h * HEAD_DIM + j + 64];
        const float r1 = x1 * cs - x2 * sn;
        const float r2 = x2 * cs + x1 * sn;
        const __nv_bfloat16 h1 = __float2bfloat16(r1);
        const __nv_bfloat16 h2 = __float2bfloat16(r2);
        g_Kh[ob + j]      = h1;
        g_Kh[ob + j + 64] = h2;
        g_Kl[ob + j]      = __float2bfloat16(r1 - __bfloat162float(h1));
        g_Kl[ob + j + 64] = __float2bfloat16(r2 - __bfloat162float(h2));
    }
    // v
    #pragma unroll
    for (int rep = 0; rep < 2; rep++) {
        const int e = t + rep * 1024;
        const int hv = e >> 7;
        const int dv = e & 127;
        const float x = qkv[tb + 2 * HIDDEN + e];
        const __nv_bfloat16 hb = __float2bfloat16(x);
        const size_t vo = ((size_t)(b * HEADS + hv) * SEQ + s) * HEAD_DIM + dv;
        g_Vh[vo] = hb;
        g_Vl[vo] = __float2bfloat16(x - __bfloat162float(hb));
    }
}

// ---------------------------------------------------------------------------
// Tensor-core flash attention (mma.sync m16n8k16 bf16, hi/lo split).
// Epilogue writes single fp16 into g_A for the output projection.
// ---------------------------------------------------------------------------
#define FLD 136
#define FQ_BYTES  (128 * FLD * 2)
#define FKV_ARR   (64 * FLD * 2)
#define FSTAGE_BYTES (4 * FKV_ARR)
#define FL_SMEM_BYTES (2 * FQ_BYTES + 2 * FSTAGE_BYTES)  // 208896

__global__ __launch_bounds__(256) void flash_mma_kernel()
{
    extern __shared__ char smem[];
    const uint32_t sb = smem_to_u32(smem);
    const uint32_t sQh = sb;
    const uint32_t sQl = sb + FQ_BYTES;
    const uint32_t sKV = sb + 2 * FQ_BYTES;

    const int t = threadIdx.x;
    const int w = t >> 5;
    const int lane = t & 31;
    const int qt = (int)gridDim.x - 1 - (int)blockIdx.x;
    const int bh = blockIdx.y;
    const int b = bh >> 4;
    const int h = bh & 15;
    const int q0 = qt * 128;
    const int nkt = 2 * qt + 2;

    const __nv_bfloat16* Qhg = g_Qh + (size_t)bh * SEQ * HEAD_DIM;
    const __nv_bfloat16* Qlg = g_Ql + (size_t)bh * SEQ * HEAD_DIM;
    const __nv_bfloat16* Khg = g_Kh + (size_t)bh * SEQ * HEAD_DIM;
    const __nv_bfloat16* Klg = g_Kl + (size_t)bh * SEQ * HEAD_DIM;
    const __nv_bfloat16* Vhg = g_Vh + (size_t)bh * SEQ * HEAD_DIM;
    const __nv_bfloat16* Vlg = g_Vl + (size_t)bh * SEQ * HEAD_DIM;

    {
        #pragma unroll
        for (int i = 0; i < 16; i++) {
            const int u = t + i * 256;
            const int arr = u >> 11;
            const int row = (u >> 4) & 127;
            const int ch = u & 15;
            const __nv_bfloat16* src = (arr ? Qlg : Qhg)
                + (size_t)(q0 + row) * HEAD_DIM + ch * 8;
            cp_async16(sb + arr * FQ_BYTES + row * 272 + ch * 16, src);
        }
    }
    auto load_kv = [&](int kt, int stage) {
        const int k0 = kt * 64;
        const uint32_t dstb = sKV + stage * FSTAGE_BYTES;
        const __nv_bfloat16* srcs[4] = {Khg, Klg, Vhg, Vlg};
        #pragma unroll
        for (int i = 0; i < 16; i++) {
            const int u = t + i * 256;
            const int arr = u >> 10;
            const int row = (u >> 4) & 63;
            const int ch = u & 15;
            const __nv_bfloat16* src = srcs[arr]
                + (size_t)(k0 + row) * HEAD_DIM + ch * 8;
            cp_async16(dstb + arr * FKV_ARR + row * 272 + ch * 16, src);
        }
        cp_commit();
    };
    load_kv(0, 0);

    const int rloc1 = w * 16 + (lane >> 2);
    const int row1 = q0 + rloc1;
    const int row2 = row1 + 8;
    float m1 = -INFINITY, m2 = -INFINITY, l1 = 0.0f, l2 = 0.0f;
    float sO[16][4];
    #pragma unroll
    for (int f = 0; f < 16; f++)
        #pragma unroll
        for (int e = 0; e < 4; e++) sO[f][e] = 0.0f;

    for (int kt = 0; kt < nkt; kt++) {
        const int st = kt & 1;
        if (kt + 1 < nkt) {
            load_kv(kt + 1, st ^ 1);
            cp_wait<1>();
        } else {
            cp_wait<0>();
        }
        __syncthreads();

        const uint32_t kb = sKV + st * FSTAGE_BYTES;
        const uint32_t kbl = kb + FKV_ARR;
        const uint32_t vb = kb + 2 * FKV_ARR;
        const uint32_t vbl = kb + 3 * FKV_ARR;
        const int k0 = kt * 64;

        float sS[8][4];
        #pragma unroll
        for (int f = 0; f < 8; f++)
            #pragma unroll
            for (int e = 0; e < 4; e++) sS[f][e] = 0.0f;

        #pragma unroll
        for (int kg = 0; kg < 8; kg++) {
            uint32_t aH[4], aL[4];
            const uint32_t qoff = (w * 16 + (lane & 15)) * 272
                                + (kg * 16 + (lane >> 4) * 8) * 2;
            ldm_x4(aH, sQh + qoff);
            ldm_x4(aL, sQl + qoff);
            #pragma unroll
            for (int f = 0; f < 8; f++) {
                uint32_t bH[2], bL[2];
                const uint32_t koff = (f * 8 + (lane & 7)) * 272
                                    + (kg * 16 + ((lane >> 3) & 1) * 8) * 2;
                ldm_x2(bH, kb + koff);
                ldm_x2(bL, kbl + koff);
                mma_bf16(sS[f], aH, bH);
                mma_bf16(sS[f], aH, bL);
                mma_bf16(sS[f], aL, bH);
            }
        }

        if (k0 + 63 > row1) {
            #pragma unroll
            for (int f = 0; f < 8; f++)
                #pragma unroll
                for (int e = 0; e < 4; e++) {
                    const int col = k0 + f * 8 + (lane & 3) * 2 + (e & 1);
                    const int rw = (e < 2) ? row1 : row2;
                    if (col > rw) sS[f][e] = -INFINITY;
                }
        }

        float mx1 = -INFINITY, mx2 = -INFINITY;
        #pragma unroll
        for (int f = 0; f < 8; f++) {
            mx1 = fmaxf(mx1, fmaxf(sS[f][0], sS[f][1]));
            mx2 = fmaxf(mx2, fmaxf(sS[f][2], sS[f][3]));
        }
        mx1 = fmaxf(mx1, __shfl_xor_sync(0xffffffffu, mx1, 1));
        mx1 = fmaxf(mx1, __shfl_xor_sync(0xffffffffu, mx1, 2));
        mx2 = fmaxf(mx2, __shfl_xor_sync(0xffffffffu, mx2, 1));
        mx2 = fmaxf(mx2, __shfl_xor_sync(0xffffffffu, mx2, 2));

        const float mn1 = fmaxf(m1, mx1);
        const float mn2 = fmaxf(m2, mx2);
        const float al1 = __expf(m1 - mn1);
        const float al2 = __expf(m2 - mn2);
        m1 = mn1; m2 = mn2;

        float sum1 = 0.0f, sum2 = 0.0f;
        #pragma unroll
        for (int f = 0; f < 8; f++) {
            sS[f][0] = __expf(sS[f][0] - m1);
            sS[f][1] = __expf(sS[f][1] - m1);
            sS[f][2] = __expf(sS[f][2] - m2);
            sS[f][3] = __expf(sS[f][3] - m2);
            sum1 += sS[f][0] + sS[f][1];
            sum2 += sS[f][2] + sS[f][3];
        }
        sum1 += __shfl_xor_sync(0xffffffffu, sum1, 1);
        sum1 += __shfl_xor_sync(0xffffffffu, sum1, 2);
        sum2 += __shfl_xor_sync(0xffffffffu, sum2, 1);
        sum2 += __shfl_xor_sync(0xffffffffu, sum2, 2);
        l1 = l1 * al1 + sum1;
        l2 = l2 * al2 + sum2;

        #pragma unroll
        for (int f = 0; f < 16; f++) {
            sO[f][0] *= al1; sO[f][1] *= al1;
            sO[f][2] *= al2; sO[f][3] *= al2;
        }

        #pragma unroll
        for (int g = 0; g < 4; g++) {
            uint32_t aPh[4], aPl[4];
            {
                const float* p0 = sS[2 * g];
                const float* p1 = sS[2 * g + 1];
                aPh[0] = pack_bf16(p0[0], p0[1]);
                aPh[1] = pack_bf16(p0[2], p0[3]);
                aPh[2] = pack_bf16(p1[0], p1[1]);
                aPh[3] = pack_bf16(p1[2], p1[3]);
                __nv_bfloat162 h0 = *(__nv_bfloat162*)&aPh[0];
                __nv_bfloat162 h1 = *(__nv_bfloat162*)&aPh[1];
                __nv_bfloat162 h2 = *(__nv_bfloat162*)&aPh[2];
                __nv_bfloat162 h3 = *(__nv_bfloat162*)&aPh[3];
                aPl[0] = pack_bf16(p0[0] - __bfloat162float(h0.x),
                                   p0[1] - __bfloat162float(h0.y));
                aPl[1] = pack_bf16(p0[2] - __bfloat162float(h1.x),
                                   p0[3] - __bfloat162float(h1.y));
                aPl[2] = pack_bf16(p1[0] - __bfloat162float(h2.x),
                                   p1[1] - __bfloat162float(h2.y));
                aPl[3] = pack_bf16(p1[2] - __bfloat162float(h3.x),
                                   p1[3] - __bfloat162float(h3.y));
            }
            #pragma unroll
            for (int f2 = 0; f2 < 16; f2++) {
                uint32_t bVh[2], bVl[2];
                const uint32_t voff = (g * 16 + (lane & 15)) * 272 + f2 * 16;
                ldm_x2_trans(bVh, vb + voff);
                ldm_x2_trans(bVl, vbl + voff);
                mma_bf16(sO[f2], aPh, bVh);
                mma_bf16(sO[f2], aPh, bVl);
                mma_bf16(sO[f2], aPl, bVh);
            }
        }
        __syncthreads();
    }

    // epilogue: normalize, write single fp16 to g_A
    const float linv1 = 1.0f / l1;
    const float linv2 = 1.0f / l2;
    const size_t tok1 = (size_t)(b * SEQ + row1) * HIDDEN + h * HEAD_DIM;
    const size_t tok2 = (size_t)(b * SEQ + row2) * HIDDEN + h * HEAD_DIM;
    #pragma unroll
    for (int f2 = 0; f2 < 16; f2++) {
        const int d = f2 * 8 + (lane & 3) * 2;
        *(uint32_t*)(g_A + tok1 + d) =
            pack_fp16(sO[f2][0] * linv1, sO[f2][1] * linv1);
        *(uint32_t*)(g_A + tok2 + d) =
            pack_fp16(sO[f2][2] * linv2, sO[f2][3] * linv2);
    }
}

// ---------------------------------------------------------------------------
// Launch
// ---------------------------------------------------------------------------
extern "C" void kernel_launch(void* const* d_in, const int* in_sizes, int n_in,
                              void* d_out, int out_size)
{
    const float* hidden = (const float*)d_in[0];
    const int*   pos32  = (const int*)d_in[1];
    const float* Wqkv   = (const float*)d_in[2];
    const float* bqkv   = (const float*)d_in[3];
    const float* Wo     = (const float*)d_in[4];
    const float* bo     = (const float*)d_in[5];
    float* out          = (float*)d_out;

    float* qkv;  cudaGetSymbolAddress((void**)&qkv,  g_qkv);
    __half *A, *Wqh, *Woh;
    cudaGetSymbolAddress((void**)&A, g_A);
    cudaGetSymbolAddress((void**)&Wqh, g_Wqkv_h);
    cudaGetSymbolAddress((void**)&Woh, g_Wo_h);

    cudaFuncSetAttribute(gemm_mma_kernel,
                         cudaFuncAttributeMaxDynamicSharedMemorySize,
                         GEMM_SMEM_BYTES);
    cudaFuncSetAttribute(flash_mma_kernel,
                         cudaFuncAttributeMaxDynamicSharedMemorySize,
                         FL_SMEM_BYTES);

    // 0a) convert hidden -> A (fp16)
    {
        const int n4 = TOKENS * HIDDEN / 4;
        convert_kernel<<<(n4 + 255) / 256, 256>>>(hidden, A, n4);
    }
    // 0b) transpose weights to single fp16
    tsplit_kernel<<<dim3(QKV_N / 32, HIDDEN / 32), 256>>>(Wqkv, Wqh, HIDDEN, QKV_N);
    tsplit_kernel<<<dim3(HIDDEN / 32, HIDDEN / 32), 256>>>(Wo, Woh, HIDDEN, HIDDEN);

    // 1) QKV projection (fp16, single pass)
    gemm_mma_kernel<<<dim3(QKV_N / 128, TOKENS / 128), 256, GEMM_SMEM_BYTES>>>(
        TOKENS, QKV_N, HIDDEN, A, Wqh, bqkv, qkv);

    // 2) RoPE + scale + bf16 hi/lo split into Q/K/V buffers
    rope_split_kernel<<<TOKENS, 1024>>>(qkv, pos32);

    // 3) Tensor-core flash attention (bf16 3-pass) -> writes fp16 g_A
    flash_mma_kernel<<<dim3(SEQ / 128, BH), 256, FL_SMEM_BYTES>>>();

    // 4) Output projection (fp16, single pass)
    gemm_mma_kernel<<<dim3(HIDDEN / 128, TOKENS / 128), 256, GEMM_SMEM_BYTES>>>(
        TOKENS, HIDDEN, HIDDEN, A, Woh, bo, out);
}

// round 16
// speedup vs baseline: 7.5717x; 1.3352x over previous
#include <cuda_runtime.h>
#include <cuda_bf16.h>
#include <cuda_fp16.h>
#include <math.h>
#include <stdint.h>

// Problem constants
#define BATCH 2
#define SEQ 2048
#define HIDDEN 2048
#define HEADS 16
#define HEAD_DIM 128
#define TOKENS (BATCH * SEQ)          // 4096
#define QKV_N (3 * HIDDEN)            // 6144

// ---------------------------------------------------------------------------
// Scratch (allocation-free: __device__ globals)
// ---------------------------------------------------------------------------
__device__ float g_qkv[(size_t)TOKENS * QKV_N];     // [token][3*HIDDEN]
// single-fp16 GEMM "A" operand (hidden; later attention output)
__device__ __half g_A[(size_t)TOKENS * HIDDEN];
// single-fp16 transposed weights [N,K] K-major
__device__ __half g_Wqkv_h[(size_t)QKV_N * HIDDEN];
__device__ __half g_Wo_h[(size_t)HIDDEN * HIDDEN];
// single-fp16 roped Q (scaled), roped K, V: [b*H+h][s][128]
#define BH (BATCH * HEADS)
__device__ __half g_Q[(size_t)BH * SEQ * HEAD_DIM];
__device__ __half g_K[(size_t)BH * SEQ * HEAD_DIM];
__device__ __half g_V[(size_t)BH * SEQ * HEAD_DIM];

// ---------------------------------------------------------------------------
// PTX helpers (sm_80-level, legal on plain compute_103 PTX)
// ---------------------------------------------------------------------------
__device__ __forceinline__ uint32_t smem_to_u32(const void* p) {
    uint32_t a;
    asm("{ .reg .u64 t; cvta.to.shared.u64 t, %1; cvt.u32.u64 %0, t; }"
        : "=r"(a) : "l"(p));
    return a;
}
__device__ __forceinline__ void cp_async16(uint32_t dst, const void* src) {
    asm volatile("cp.async.cg.shared.global [%0], [%1], 16;"
                 :: "r"(dst), "l"(src));
}
__device__ __forceinline__ void cp_commit() {
    asm volatile("cp.async.commit_group;" ::: "memory");
}
template <int N>
__device__ __forceinline__ void cp_wait() {
    asm volatile("cp.async.wait_group %0;" :: "n"(N) : "memory");
}
__device__ __forceinline__ void ldm_x4(uint32_t* r, uint32_t addr) {
    asm volatile("ldmatrix.sync.aligned.m8n8.x4.shared.b16 {%0,%1,%2,%3}, [%4];"
        : "=r"(r[0]), "=r"(r[1]), "=r"(r[2]), "=r"(r[3]) : "r"(addr));
}
__device__ __forceinline__ void ldm_x2(uint32_t* r, uint32_t addr) {
    asm volatile("ldmatrix.sync.aligned.m8n8.x2.shared.b16 {%0,%1}, [%2];"
        : "=r"(r[0]), "=r"(r[1]) : "r"(addr));
}
__device__ __forceinline__ void ldm_x2_trans(uint32_t* r, uint32_t addr) {
    asm volatile("ldmatrix.sync.aligned.m8n8.x2.trans.shared.b16 {%0,%1}, [%2];"
        : "=r"(r[0]), "=r"(r[1]) : "r"(addr));
}
__device__ __forceinline__ void mma_fp16(float* c, const uint32_t* a, const uint32_t* b) {
    asm volatile(
        "mma.sync.aligned.m16n8k16.row.col.f32.f16.f16.f32 "
        "{%0,%1,%2,%3}, {%4,%5,%6,%7}, {%8,%9}, {%0,%1,%2,%3};"
        : "+f"(c[0]), "+f"(c[1]), "+f"(c[2]), "+f"(c[3])
        : "r"(a[0]), "r"(a[1]), "r"(a[2]), "r"(a[3]), "r"(b[0]), "r"(b[1]));
}
__device__ __forceinline__ uint32_t pack_fp16(float a, float b) {
    __half2 t;
    t.x = __float2half_rn(a);
    t.y = __float2half_rn(b);
    return *(uint32_t*)&t;
}

// ---------------------------------------------------------------------------
// fp32 -> fp16 convert (A operand). float4-wide.
// ---------------------------------------------------------------------------
__global__ __launch_bounds__(256) void convert_kernel(
    const float* __restrict__ x, __half* __restrict__ y, int n4)
{
    const int i = blockIdx.x * 256 + threadIdx.x;
    if (i >= n4) return;
    const float4 v = ((const float4*)x)[i];
    const uint32_t p0 = pack_fp16(v.x, v.y);
    const uint32_t p1 = pack_fp16(v.z, v.w);
    ((uint2*)y)[i] = make_uint2(p0, p1);
}

// ---------------------------------------------------------------------------
// Transpose to single fp16: W [K,N] fp32 -> T [N,K] fp16. 32x32 tiles.
// ---------------------------------------------------------------------------
__global__ __launch_bounds__(256) void tsplit_kernel(
    const float* __restrict__ W, __half* __restrict__ T, int K, int N)
{
    __shared__ float sm[32][33];
    const int n0 = blockIdx.x * 32;
    const int k0 = blockIdx.y * 32;
    const int tx = threadIdx.x & 31;
    const int ty = threadIdx.x >> 5;
    #pragma unroll
    for (int i = 0; i < 32; i += 8)
        sm[ty + i][tx] = W[(size_t)(k0 + ty + i) * N + n0 + tx];
    __syncthreads();
    #pragma unroll
    for (int i = 0; i < 32; i += 8)
        T[(size_t)(n0 + ty + i) * K + k0 + tx] = __float2half_rn(sm[tx][ty + i]);
}

// ---------------------------------------------------------------------------
// Raw mma.sync fp16 GEMM, single pass: C = A @ B^T + bias (unchanged, proven)
// ---------------------------------------------------------------------------
#define G_TILE_BYTES  (128 * 40 * 2)             // 10240
#define G_STAGE_BYTES (2 * G_TILE_BYTES)         // 20480 (A, B)
#define GEMM_SMEM_BYTES (3 * G_STAGE_BYTES)      // 61440

__global__ __launch_bounds__(256, 2) void gemm_mma_kernel(
    int M, int Ntot, int K,
    const __half* __restrict__ A, const __half* __restrict__ B,
    const float* __restrict__ bias, float* __restrict__ C)
{
    extern __shared__ char smem[];
    const uint32_t smem_u32 = smem_to_u32(smem);

    const int t = threadIdx.x;
    const int wid = t >> 5;
    const int lane = t & 31;
    const int warpM = wid & 3;
    const int warpN = wid >> 2;
    const int m0 = blockIdx.y * 128;
    const int n0 = blockIdx.x * 128;

    float acc[2][8][4];
    #pragma unroll
    for (int mt = 0; mt < 2; mt++)
        #pragma unroll
        for (int nt = 0; nt < 8; nt++)
            #pragma unroll
            for (int e = 0; e < 4; e++) acc[mt][nt][e] = 0.0f;

    const int Ku4 = K >> 3;
    const uint4* srcs[2] = {
        (const uint4*)A + (size_t)m0 * Ku4,
        (const uint4*)B + (size_t)n0 * Ku4
    };

    const int NC = K >> 5;

    auto load_stage = [&](int chunk, int s) {
        const int kq = chunk << 2;
        const uint32_t sbase = smem_u32 + s * G_STAGE_BYTES;
        #pragma unroll
        for (int j = 0; j < 4; j++) {
            const int u = t + j * 256;
            const int tile = u >> 9;
            const int row = (u >> 2) & 127;
            const int seg = u & 3;
            const uint4* src = srcs[tile] + (size_t)row * Ku4 + kq + seg;
            const uint32_t dst = sbase + tile * G_TILE_BYTES + row * 80 + seg * 16;
            cp_async16(dst, src);
        }
        cp_commit();
    };

    load_stage(0, 0);
    load_stage(1, 1);

    for (int i = 0; i < NC; i++) {
        const int s = i - (i / 3) * 3;   // i % 3
        cp_wait<1>();
        __syncthreads();
        if (i + 2 < NC) {
            const int s2 = (i + 2) - ((i + 2) / 3) * 3;
            load_stage(i + 2, s2);
        }

        const uint32_t sb = smem_u32 + s * G_STAGE_BYTES;
        const uint32_t sA = sb;
        const uint32_t sB = sb + G_TILE_BYTES;

        #pragma unroll
        for (int ks = 0; ks < 2; ks++) {
            uint32_t aF[2][4];
            #pragma unroll
            for (int mt = 0; mt < 2; mt++) {
                const uint32_t aoff = (warpM * 32 + mt * 16 + (lane & 15)) * 80
                                    + (ks * 16 + (lane >> 4) * 8) * 2;
                ldm_x4(aF[mt], sA + aoff);
            }
            uint32_t bfr[8][2];
            #pragma unroll
            for (int nt2 = 0; nt2 < 4; nt2++) {
                uint32_t tmp[4];
                const uint32_t boff =
                    (warpN * 64 + nt2 * 16 + ((lane >> 4) & 1) * 8 + (lane & 7)) * 80
                    + (ks * 16 + ((lane >> 3) & 1) * 8) * 2;
                ldm_x4(tmp, sB + boff);
                bfr[2 * nt2][0] = tmp[0];
                bfr[2 * nt2][1] = tmp[1];
                bfr[2 * nt2 + 1][0] = tmp[2];
                bfr[2 * nt2 + 1][1] = tmp[3];
            }
            #pragma unroll
            for (int nt = 0; nt < 8; nt++)
                #pragma unroll
                for (int mt = 0; mt < 2; mt++)
                    mma_fp16(acc[mt][nt], aF[mt], bfr[nt]);
        }
    }

    #pragma unroll
    for (int mt = 0; mt < 2; mt++) {
        const int r1 = m0 + warpM * 32 + mt * 16 + (lane >> 2);
        #pragma unroll
        for (int nt = 0; nt < 8; nt++) {
            const int c0 = n0 + warpN * 64 + nt * 8 + (lane & 3) * 2;
            const float b0 = __ldg(bias + c0);
            const float b1 = __ldg(bias + c0 + 1);
            float2 v0, v1;
            v0.x = acc[mt][nt][0] + b0;
            v0.y = acc[mt][nt][1] + b1;
            v1.x = acc[mt][nt][2] + b0;
            v1.y = acc[mt][nt][3] + b1;
            *(float2*)&C[(size_t)r1 * Ntot + c0] = v0;
            *(float2*)&C[(size_t)(r1 + 8) * Ntot + c0] = v1;
        }
    }
}

// ---------------------------------------------------------------------------
// RoPE + scale + fp16 convert into per-head-contiguous Q/K/V buffers.
// ---------------------------------------------------------------------------
__global__ __launch_bounds__(1024) void rope_split_kernel(
    const float* __restrict__ qkv, const int* __restrict__ pos32)
{
    const int token = blockIdx.x;
    const int b = token >> 11;
    const int s = token & 2047;
    const int t = threadIdx.x;
    const int h = t >> 6;
    const int j = t & 63;
    const float scale = 0.08838834764831845f;  // 1/sqrt(128)

    const bool is64 = (pos32[1] == 0);
    const int posi = is64 ? pos32[2 * token] : pos32[token];
    const float pos = (float)posi;

    const float inv = exp2f(-(float)j * 0.20762050595283508f);
    const float ang = pos * inv;
    float sn, cs;
    sincosf(ang, &sn, &cs);

    const size_t tb = (size_t)token * QKV_N;
    const size_t ob = ((size_t)(b * HEADS + h) * SEQ + s) * HEAD_DIM;

    // q (scaled)
    {
        const float x1 = qkv[tb + h * HEAD_DIM + j];
        const float x2 = qkv[tb + h * HEAD_DIM + j + 64];
        g_Q[ob + j]      = __float2half_rn((x1 * cs - x2 * sn) * scale);
        g_Q[ob + j + 64] = __float2half_rn((x2 * cs + x1 * sn) * scale);
    }
    // k
    {
        const float x1 = qkv[tb + HIDDEN + h * HEAD_DIM + j];
        const float x2 = qkv[tb + HIDDEN + h * HEAD_DIM + j + 64];
        g_K[ob + j]      = __float2half_rn(x1 * cs - x2 * sn);
        g_K[ob + j + 64] = __float2half_rn(x2 * cs + x1 * sn);
    }
    // v
    #pragma unroll
    for (int rep = 0; rep < 2; rep++) {
        const int e = t + rep * 1024;
        const int hv = e >> 7;
        const int dv = e & 127;
        const float x = qkv[tb + 2 * HIDDEN + e];
        const size_t vo = ((size_t)(b * HEADS + hv) * SEQ + s) * HEAD_DIM + dv;
        g_V[vo] = __float2half_rn(x);
    }
}

// ---------------------------------------------------------------------------
// Tensor-core flash attention — single-pass fp16 (Q,K,V,P fp16; fp32 accum).
// Block: 128 q-rows x 64-key tiles, 8 warps, K/V double-buffered, 2 CTAs/SM.
// ---------------------------------------------------------------------------
#define FQ_BYTES  (128 * 272)          // 34816
#define FKV_ARR   (64 * 272)           // 17408
#define FSTAGE_BYTES (2 * FKV_ARR)     // K, V: 34816
#define FL_SMEM_BYTES (FQ_BYTES + 2 * FSTAGE_BYTES)  // 104448

__global__ __launch_bounds__(256, 2) void flash_mma_kernel()
{
    extern __shared__ char smem[];
    const uint32_t sb = smem_to_u32(smem);
    const uint32_t sQ  = sb;
    const uint32_t sKV = sb + FQ_BYTES;

    const int t = threadIdx.x;
    const int w = t >> 5;
    const int lane = t & 31;
    const int qt = (int)gridDim.x - 1 - (int)blockIdx.x;   // big tiles first
    const int bh = blockIdx.y;
    const int b = bh >> 4;
    const int h = bh & 15;
    const int q0 = qt * 128;
    const int nkt = 2 * qt + 2;

    const __half* Qg = g_Q + (size_t)bh * SEQ * HEAD_DIM;
    const __half* Kg = g_K + (size_t)bh * SEQ * HEAD_DIM;
    const __half* Vg = g_V + (size_t)bh * SEQ * HEAD_DIM;

    // Load Q: 128 rows x 16 chunks of 16B = 2048 over 256 threads
    {
        #pragma unroll
        for (int i = 0; i < 8; i++) {
            const int u = t + i * 256;
            const int row = u >> 4;
            const int ch = u & 15;
            cp_async16(sQ + row * 272 + ch * 16,
                       Qg + (size_t)(q0 + row) * HEAD_DIM + ch * 8);
        }
    }
    auto load_kv = [&](int kt, int stage) {
        const int k0 = kt * 64;
        const uint32_t dstb = sKV + stage * FSTAGE_BYTES;
        #pragma unroll
        for (int i = 0; i < 8; i++) {
            const int u = t + i * 256;
            const int arr = u >> 10;              // 0=K, 1=V
            const int row = (u >> 4) & 63;
            const int ch = u & 15;
            const __half* src = (arr ? Vg : Kg)
                + (size_t)(k0 + row) * HEAD_DIM + ch * 8;
            cp_async16(dstb + arr * FKV_ARR + row * 272 + ch * 16, src);
        }
        cp_commit();
    };
    load_kv(0, 0);

    const int rloc1 = w * 16 + (lane >> 2);
    const int row1 = q0 + rloc1;
    const int row2 = row1 + 8;
    float m1 = -INFINITY, m2 = -INFINITY, l1 = 0.0f, l2 = 0.0f;
    float sO[16][4];
    #pragma unroll
    for (int f = 0; f < 16; f++)
        #pragma unroll
        for (int e = 0; e < 4; e++) sO[f][e] = 0.0f;

    for (int kt = 0; kt < nkt; kt++) {
        const int st = kt & 1;
        if (kt + 1 < nkt) {
            load_kv(kt + 1, st ^ 1);
            cp_wait<1>();
        } else {
            cp_wait<0>();
        }
        __syncthreads();

        const uint32_t kb = sKV + st * FSTAGE_BYTES;          // K
        const uint32_t vb = kb + FKV_ARR;                     // V
        const int k0 = kt * 64;

        // ---- S = Q K^T (single fp16 pass)
        float sS[8][4];
        #pragma unroll
        for (int f = 0; f < 8; f++)
            #pragma unroll
            for (int e = 0; e < 4; e++) sS[f][e] = 0.0f;

        #pragma unroll
        for (int kg = 0; kg < 8; kg++) {
            uint32_t aF[4];
            const uint32_t qoff = (w * 16 + (lane & 15)) * 272
                                + (kg * 16 + (lane >> 4) * 8) * 2;
            ldm_x4(aF, sQ + qoff);
            #pragma unroll
            for (int f = 0; f < 8; f++) {
                uint32_t bF[2];
                const uint32_t koff = (f * 8 + (lane & 7)) * 272
                                    + (kg * 16 + ((lane >> 3) & 1) * 8) * 2;
                ldm_x2(bF, kb + koff);
                mma_fp16(sS[f], aF, bF);
            }
        }

        // ---- causal mask
        if (k0 + 63 > row1) {
            #pragma unroll
            for (int f = 0; f < 8; f++)
                #pragma unroll
                for (int e = 0; e < 4; e++) {
                    const int col = k0 + f * 8 + (lane & 3) * 2 + (e & 1);
                    const int rw = (e < 2) ? row1 : row2;
                    if (col > rw) sS[f][e] = -INFINITY;
                }
        }

        // ---- online softmax
        float mx1 = -INFINITY, mx2 = -INFINITY;
        #pragma unroll
        for (int f = 0; f < 8; f++) {
            mx1 = fmaxf(mx1, fmaxf(sS[f][0], sS[f][1]));
            mx2 = fmaxf(mx2, fmaxf(sS[f][2], sS[f][3]));
        }
        mx1 = fmaxf(mx1, __shfl_xor_sync(0xffffffffu, mx1, 1));
        mx1 = fmaxf(mx1, __shfl_xor_sync(0xffffffffu, mx1, 2));
        mx2 = fmaxf(mx2, __shfl_xor_sync(0xffffffffu, mx2, 1));
        mx2 = fmaxf(mx2, __shfl_xor_sync(0xffffffffu, mx2, 2));

        const float mn1 = fmaxf(m1, mx1);
        const float mn2 = fmaxf(m2, mx2);
        const float al1 = __expf(m1 - mn1);
        const float al2 = __expf(m2 - mn2);
        m1 = mn1; m2 = mn2;

        float sum1 = 0.0f, sum2 = 0.0f;
        #pragma unroll
        for (int f = 0; f < 8; f++) {
            sS[f][0] = __expf(sS[f][0] - m1);
            sS[f][1] = __expf(sS[f][1] - m1);
            sS[f][2] = __expf(sS[f][2] - m2);
            sS[f][3] = __expf(sS[f][3] - m2);
            sum1 += sS[f][0] + sS[f][1];
            sum2 += sS[f][2] + sS[f][3];
        }
        sum1 += __shfl_xor_sync(0xffffffffu, sum1, 1);
        sum1 += __shfl_xor_sync(0xffffffffu, sum1, 2);
        sum2 += __shfl_xor_sync(0xffffffffu, sum2, 1);
        sum2 += __shfl_xor_sync(0xffffffffu, sum2, 2);
        l1 = l1 * al1 + sum1;
        l2 = l2 * al2 + sum2;

        #pragma unroll
        for (int f = 0; f < 16; f++) {
            sO[f][0] *= al1; sO[f][1] *= al1;
            sO[f][2] *= al2; sO[f][3] *= al2;
        }

        // ---- O += P V (single fp16 pass); P packed from S regs
        #pragma unroll
        for (int g = 0; g < 4; g++) {
            uint32_t aP[4];
            {
                const float* p0 = sS[2 * g];
                const float* p1 = sS[2 * g + 1];
                aP[0] = pack_fp16(p0[0], p0[1]);
                aP[1] = pack_fp16(p0[2], p0[3]);
                aP[2] = pack_fp16(p1[0], p1[1]);
                aP[3] = pack_fp16(p1[2], p1[3]);
            }
            #pragma unroll
            for (int f2 = 0; f2 < 16; f2++) {
                uint32_t bV[2];
                const uint32_t voff = (g * 16 + (lane & 15)) * 272 + f2 * 16;
                ldm_x2_trans(bV, vb + voff);
                mma_fp16(sO[f2], aP, bV);
            }
        }
        __syncthreads();
    }

    // epilogue: normalize, write single fp16 to g_A
    const float linv1 = 1.0f / l1;
    const float linv2 = 1.0f / l2;
    const size_t tok1 = (size_t)(b * SEQ + row1) * HIDDEN + h * HEAD_DIM;
    const size_t tok2 = (size_t)(b * SEQ + row2) * HIDDEN + h * HEAD_DIM;
    #pragma unroll
    for (int f2 = 0; f2 < 16; f2++) {
        const int d = f2 * 8 + (lane & 3) * 2;
        *(uint32_t*)(g_A + tok1 + d) =
            pack_fp16(sO[f2][0] * linv1, sO[f2][1] * linv1);
        *(uint32_t*)(g_A + tok2 + d) =
            pack_fp16(sO[f2][2] * linv2, sO[f2][3] * linv2);
    }
}

// ---------------------------------------------------------------------------
// Launch
// ---------------------------------------------------------------------------
extern "C" void kernel_launch(void* const* d_in, const int* in_sizes, int n_in,
                              void* d_out, int out_size)
{
    const float* hidden = (const float*)d_in[0];
    const int*   pos32  = (const int*)d_in[1];
    const float* Wqkv   = (const float*)d_in[2];
    const float* bqkv   = (const float*)d_in[3];
    const float* Wo     = (const float*)d_in[4];
    const float* bo     = (const float*)d_in[5];
    float* out          = (float*)d_out;

    float* qkv;  cudaGetSymbolAddress((void**)&qkv,  g_qkv);
    __half *A, *Wqh, *Woh;
    cudaGetSymbolAddress((void**)&A, g_A);
    cudaGetSymbolAddress((void**)&Wqh, g_Wqkv_h);
    cudaGetSymbolAddress((void**)&Woh, g_Wo_h);

    cudaFuncSetAttribute(gemm_mma_kernel,
                         cudaFuncAttributeMaxDynamicSharedMemorySize,
                         GEMM_SMEM_BYTES);
    cudaFuncSetAttribute(flash_mma_kernel,
                         cudaFuncAttributeMaxDynamicSharedMemorySize,
                         FL_SMEM_BYTES);

    // 0a) convert hidden -> A (fp16)
    {
        const int n4 = TOKENS * HIDDEN / 4;
        convert_kernel<<<(n4 + 255) / 256, 256>>>(hidden, A, n4);
    }
    // 0b) transpose weights to single fp16
    tsplit_kernel<<<dim3(QKV_N / 32, HIDDEN / 32), 256>>>(Wqkv, Wqh, HIDDEN, QKV_N);
    tsplit_kernel<<<dim3(HIDDEN / 32, HIDDEN / 32), 256>>>(Wo, Woh, HIDDEN, HIDDEN);

    // 1) QKV projection (fp16, single pass)
    gemm_mma_kernel<<<dim3(QKV_N / 128, TOKENS / 128), 256, GEMM_SMEM_BYTES>>>(
        TOKENS, QKV_N, HIDDEN, A, Wqh, bqkv, qkv);

    // 2) RoPE + scale + fp16 Q/K/V buffers
    rope_split_kernel<<<TOKENS, 1024>>>(qkv, pos32);

    // 3) Tensor-core flash attention (fp16 single pass) -> writes fp16 g_A
    flash_mma_kernel<<<dim3(SEQ / 128, BH), 256, FL_SMEM_BYTES>>>();

    // 4) Output projection (fp16, single pass)
    gemm_mma_kernel<<<dim3(HIDDEN / 128, TOKENS / 128), 256, GEMM_SMEM_BYTES>>>(
        TOKENS, HIDDEN, HIDDEN, A, Woh, bo, out);
}

// round 17
// speedup vs baseline: 8.1409x; 1.0752x over previous
#include <cuda_runtime.h>
#include <cuda_bf16.h>
#include <cuda_fp16.h>
#include <math.h>
#include <stdint.h>

// Problem constants
#define BATCH 2
#define SEQ 2048
#define HIDDEN 2048
#define HEADS 16
#define HEAD_DIM 128
#define TOKENS (BATCH * SEQ)          // 4096
#define QKV_N (3 * HIDDEN)            // 6144

// ---------------------------------------------------------------------------
// Scratch (allocation-free: __device__ globals)
// ---------------------------------------------------------------------------
__device__ float g_qkv[(size_t)TOKENS * QKV_N];     // [token][3*HIDDEN]
// single-fp16 GEMM "A" operand (hidden; later attention output)
__device__ __half g_A[(size_t)TOKENS * HIDDEN];
// single-fp16 transposed weights [N,K] K-major
__device__ __half g_Wqkv_h[(size_t)QKV_N * HIDDEN];
__device__ __half g_Wo_h[(size_t)HIDDEN * HIDDEN];
// single-fp16 roped Q (scaled), roped K, V: [b*H+h][s][128]
#define BH (BATCH * HEADS)
__device__ __half g_Q[(size_t)BH * SEQ * HEAD_DIM];
__device__ __half g_K[(size_t)BH * SEQ * HEAD_DIM];
__device__ __half g_V[(size_t)BH * SEQ * HEAD_DIM];

// ---------------------------------------------------------------------------
// PTX helpers (sm_80-level, legal on plain compute_103 PTX)
// ---------------------------------------------------------------------------
__device__ __forceinline__ uint32_t smem_to_u32(const void* p) {
    uint32_t a;
    asm("{ .reg .u64 t; cvta.to.shared.u64 t, %1; cvt.u32.u64 %0, t; }"
        : "=r"(a) : "l"(p));
    return a;
}
__device__ __forceinline__ void cp_async16(uint32_t dst, const void* src) {
    asm volatile("cp.async.cg.shared.global [%0], [%1], 16;"
                 :: "r"(dst), "l"(src));
}
__device__ __forceinline__ void cp_commit() {
    asm volatile("cp.async.commit_group;" ::: "memory");
}
template <int N>
__device__ __forceinline__ void cp_wait() {
    asm volatile("cp.async.wait_group %0;" :: "n"(N) : "memory");
}
__device__ __forceinline__ void ldm_x4(uint32_t* r, uint32_t addr) {
    asm volatile("ldmatrix.sync.aligned.m8n8.x4.shared.b16 {%0,%1,%2,%3}, [%4];"
        : "=r"(r[0]), "=r"(r[1]), "=r"(r[2]), "=r"(r[3]) : "r"(addr));
}
__device__ __forceinline__ void ldm_x2(uint32_t* r, uint32_t addr) {
    asm volatile("ldmatrix.sync.aligned.m8n8.x2.shared.b16 {%0,%1}, [%2];"
        : "=r"(r[0]), "=r"(r[1]) : "r"(addr));
}
__device__ __forceinline__ void ldm_x2_trans(uint32_t* r, uint32_t addr) {
    asm volatile("ldmatrix.sync.aligned.m8n8.x2.trans.shared.b16 {%0,%1}, [%2];"
        : "=r"(r[0]), "=r"(r[1]) : "r"(addr));
}
__device__ __forceinline__ void mma_fp16(float* c, const uint32_t* a, const uint32_t* b) {
    asm volatile(
        "mma.sync.aligned.m16n8k16.row.col.f32.f16.f16.f32 "
        "{%0,%1,%2,%3}, {%4,%5,%6,%7}, {%8,%9}, {%0,%1,%2,%3};"
        : "+f"(c[0]), "+f"(c[1]), "+f"(c[2]), "+f"(c[3])
        : "r"(a[0]), "r"(a[1]), "r"(a[2]), "r"(a[3]), "r"(b[0]), "r"(b[1]));
}
__device__ __forceinline__ uint32_t pack_fp16(float a, float b) {
    __half2 t;
    t.x = __float2half_rn(a);
    t.y = __float2half_rn(b);
    return *(uint32_t*)&t;
}

// ---------------------------------------------------------------------------
// fp32 -> fp16 convert (A operand). float4-wide.
// ---------------------------------------------------------------------------
__global__ __launch_bounds__(256) void convert_kernel(
    const float* __restrict__ x, __half* __restrict__ y, int n4)
{
    const int i = blockIdx.x * 256 + threadIdx.x;
    if (i >= n4) return;
    const float4 v = ((const float4*)x)[i];
    const uint32_t p0 = pack_fp16(v.x, v.y);
    const uint32_t p1 = pack_fp16(v.z, v.w);
    ((uint2*)y)[i] = make_uint2(p0, p1);
}

// ---------------------------------------------------------------------------
// Transpose to single fp16: W [K,N] fp32 -> T [N,K] fp16. 32x32 tiles.
// ---------------------------------------------------------------------------
__global__ __launch_bounds__(256) void tsplit_kernel(
    const float* __restrict__ W, __half* __restrict__ T, int K, int N)
{
    __shared__ float sm[32][33];
    const int n0 = blockIdx.x * 32;
    const int k0 = blockIdx.y * 32;
    const int tx = threadIdx.x & 31;
    const int ty = threadIdx.x >> 5;
    #pragma unroll
    for (int i = 0; i < 32; i += 8)
        sm[ty + i][tx] = W[(size_t)(k0 + ty + i) * N + n0 + tx];
    __syncthreads();
    #pragma unroll
    for (int i = 0; i < 32; i += 8)
        T[(size_t)(n0 + ty + i) * K + k0 + tx] = __float2half_rn(sm[tx][ty + i]);
}

// ---------------------------------------------------------------------------
// Raw mma.sync fp16 GEMM, single pass: C = A @ B^T + bias
// CTA tile 128x128, BK=64 (halves barrier count), 2-stage cp.async double
// buffer. 8 warps, warp grid 4Mx2N; warp tile 32x64 = acc[2][8][4]. 2 CTAs/SM.
// smem row pitch 144B = 9*16B (ldmatrix-aligned; 8-row groups hit banks
// 4r mod 32 -> conflict-free).
// ---------------------------------------------------------------------------
#define G_TILE_BYTES  (128 * 144)                // 18432
#define G_STAGE_BYTES (2 * G_TILE_BYTES)         // 36864 (A, B)
#define GEMM_SMEM_BYTES (2 * G_STAGE_BYTES)      // 73728

__global__ __launch_bounds__(256, 2) void gemm_mma_kernel(
    int M, int Ntot, int K,
    const __half* __restrict__ A, const __half* __restrict__ B,
    const float* __restrict__ bias, float* __restrict__ C)
{
    extern __shared__ char smem[];
    const uint32_t smem_u32 = smem_to_u32(smem);

    const int t = threadIdx.x;
    const int wid = t >> 5;
    const int lane = t & 31;
    const int warpM = wid & 3;      // 0..3 -> 32-row band
    const int warpN = wid >> 2;     // 0..1 -> 64-col band
    const int m0 = blockIdx.y * 128;
    const int n0 = blockIdx.x * 128;

    float acc[2][8][4];
    #pragma unroll
    for (int mt = 0; mt < 2; mt++)
        #pragma unroll
        for (int nt = 0; nt < 8; nt++)
            #pragma unroll
            for (int e = 0; e < 4; e++) acc[mt][nt][e] = 0.0f;

    const int Ku4 = K >> 3;
    const uint4* srcs[2] = {
        (const uint4*)A + (size_t)m0 * Ku4,
        (const uint4*)B + (size_t)n0 * Ku4
    };

    const int NC = K >> 6;   // 64-wide K chunks

    auto load_stage = [&](int chunk, int s) {
        const int kq = chunk << 3;   // uint4 offset (64 halves = 8 uint4)
        const uint32_t sbase = smem_u32 + s * G_STAGE_BYTES;
        #pragma unroll
        for (int j = 0; j < 8; j++) {
            const int u = t + j * 256;
            const int tile = u >> 10;            // 0=A, 1=B
            const int row = (u >> 3) & 127;
            const int seg = u & 7;
            const uint4* src = srcs[tile] + (size_t)row * Ku4 + kq + seg;
            const uint32_t dst = sbase + tile * G_TILE_BYTES + row * 144 + seg * 16;
            cp_async16(dst, src);
        }
        cp_commit();
    };

    load_stage(0, 0);

    for (int i = 0; i < NC; i++) {
        const int s = i & 1;
        cp_wait<0>();
        __syncthreads();                       // one barrier per 64-wide chunk
        if (i + 1 < NC) load_stage(i + 1, s ^ 1);   // overlaps compute below

        const uint32_t sb = smem_u32 + s * G_STAGE_BYTES;
        const uint32_t sA = sb;
        const uint32_t sB = sb + G_TILE_BYTES;

        #pragma unroll
        for (int ks = 0; ks < 4; ks++) {
            uint32_t aF[2][4];
            #pragma unroll
            for (int mt = 0; mt < 2; mt++) {
                const uint32_t aoff = (warpM * 32 + mt * 16 + (lane & 15)) * 144
                                    + (ks * 16 + (lane >> 4) * 8) * 2;
                ldm_x4(aF[mt], sA + aoff);
            }
            // B: load nt-pairs with x4 (lanes 0-15 -> nt, lanes 16-31 -> nt+1)
            uint32_t bfr[8][2];
            #pragma unroll
            for (int nt2 = 0; nt2 < 4; nt2++) {
                uint32_t tmp[4];
                const uint32_t boff =
                    (warpN * 64 + nt2 * 16 + ((lane >> 4) & 1) * 8 + (lane & 7)) * 144
                    + (ks * 16 + ((lane >> 3) & 1) * 8) * 2;
                ldm_x4(tmp, sB + boff);
                bfr[2 * nt2][0] = tmp[0];
                bfr[2 * nt2][1] = tmp[1];
                bfr[2 * nt2 + 1][0] = tmp[2];
                bfr[2 * nt2 + 1][1] = tmp[3];
            }
            #pragma unroll
            for (int nt = 0; nt < 8; nt++)
                #pragma unroll
                for (int mt = 0; mt < 2; mt++)
                    mma_fp16(acc[mt][nt], aF[mt], bfr[nt]);
        }
    }

    // Epilogue: registers only; bias added here in fp32.
    #pragma unroll
    for (int mt = 0; mt < 2; mt++) {
        const int r1 = m0 + warpM * 32 + mt * 16 + (lane >> 2);
        #pragma unroll
        for (int nt = 0; nt < 8; nt++) {
            const int c0 = n0 + warpN * 64 + nt * 8 + (lane & 3) * 2;
            const float b0 = __ldg(bias + c0);
            const float b1 = __ldg(bias + c0 + 1);
            float2 v0, v1;
            v0.x = acc[mt][nt][0] + b0;
            v0.y = acc[mt][nt][1] + b1;
            v1.x = acc[mt][nt][2] + b0;
            v1.y = acc[mt][nt][3] + b1;
            *(float2*)&C[(size_t)r1 * Ntot + c0] = v0;
            *(float2*)&C[(size_t)(r1 + 8) * Ntot + c0] = v1;
        }
    }
}

// ---------------------------------------------------------------------------
// RoPE + scale + fp16 convert into per-head-contiguous Q/K/V buffers.
// ---------------------------------------------------------------------------
__global__ __launch_bounds__(1024) void rope_split_kernel(
    const float* __restrict__ qkv, const int* __restrict__ pos32)
{
    const int token = blockIdx.x;
    const int b = token >> 11;
    const int s = token & 2047;
    const int t = threadIdx.x;
    const int h = t >> 6;
    const int j = t & 63;
    const float scale = 0.08838834764831845f;  // 1/sqrt(128)

    const bool is64 = (pos32[1] == 0);
    const int posi = is64 ? pos32[2 * token] : pos32[token];
    const float pos = (float)posi;

    const float inv = exp2f(-(float)j * 0.20762050595283508f);
    const float ang = pos * inv;
    float sn, cs;
    sincosf(ang, &sn, &cs);

    const size_t tb = (size_t)token * QKV_N;
    const size_t ob = ((size_t)(b * HEADS + h) * SEQ + s) * HEAD_DIM;

    // q (scaled)
    {
        const float x1 = qkv[tb + h * HEAD_DIM + j];
        const float x2 = qkv[tb + h * HEAD_DIM + j + 64];
        g_Q[ob + j]      = __float2half_rn((x1 * cs - x2 * sn) * scale);
        g_Q[ob + j + 64] = __float2half_rn((x2 * cs + x1 * sn) * scale);
    }
    // k
    {
        const float x1 = qkv[tb + HIDDEN + h * HEAD_DIM + j];
        const float x2 = qkv[tb + HIDDEN + h * HEAD_DIM + j + 64];
        g_K[ob + j]      = __float2half_rn(x1 * cs - x2 * sn);
        g_K[ob + j + 64] = __float2half_rn(x2 * cs + x1 * sn);
    }
    // v
    #pragma unroll
    for (int rep = 0; rep < 2; rep++) {
        const int e = t + rep * 1024;
        const int hv = e >> 7;
        const int dv = e & 127;
        const float x = qkv[tb + 2 * HIDDEN + e];
        const size_t vo = ((size_t)(b * HEADS + hv) * SEQ + s) * HEAD_DIM + dv;
        g_V[vo] = __float2half_rn(x);
    }
}

// ---------------------------------------------------------------------------
// Tensor-core flash attention — single-pass fp16 (Q,K,V,P fp16; fp32 accum).
// Block: 128 q-rows x 64-key tiles, 8 warps, K/V double-buffered, 2 CTAs/SM.
// ---------------------------------------------------------------------------
#define FQ_BYTES  (128 * 272)          // 34816
#define FKV_ARR   (64 * 272)           // 17408
#define FSTAGE_BYTES (2 * FKV_ARR)     // K, V: 34816
#define FL_SMEM_BYTES (FQ_BYTES + 2 * FSTAGE_BYTES)  // 104448

__global__ __launch_bounds__(256, 2) void flash_mma_kernel()
{
    extern __shared__ char smem[];
    const uint32_t sb = smem_to_u32(smem);
    const uint32_t sQ  = sb;
    const uint32_t sKV = sb + FQ_BYTES;

    const int t = threadIdx.x;
    const int w = t >> 5;
    const int lane = t & 31;
    const int qt = (int)gridDim.x - 1 - (int)blockIdx.x;   // big tiles first
    const int bh = blockIdx.y;
    const int b = bh >> 4;
    const int h = bh & 15;
    const int q0 = qt * 128;
    const int nkt = 2 * qt + 2;

    const __half* Qg = g_Q + (size_t)bh * SEQ * HEAD_DIM;
    const __half* Kg = g_K + (size_t)bh * SEQ * HEAD_DIM;
    const __half* Vg = g_V + (size_t)bh * SEQ * HEAD_DIM;

    // Load Q: 128 rows x 16 chunks of 16B = 2048 over 256 threads
    {
        #pragma unroll
        for (int i = 0; i < 8; i++) {
            const int u = t + i * 256;
            const int row = u >> 4;
            const int ch = u & 15;
            cp_async16(sQ + row * 272 + ch * 16,
                       Qg + (size_t)(q0 + row) * HEAD_DIM + ch * 8);
        }
    }
    auto load_kv = [&](int kt, int stage) {
        const int k0 = kt * 64;
        const uint32_t dstb = sKV + stage * FSTAGE_BYTES;
        #pragma unroll
        for (int i = 0; i < 8; i++) {
            const int u = t + i * 256;
            const int arr = u >> 10;              // 0=K, 1=V
            const int row = (u >> 4) & 63;
            const int ch = u & 15;
            const __half* src = (arr ? Vg : Kg)
                + (size_t)(k0 + row) * HEAD_DIM + ch * 8;
            cp_async16(dstb + arr * FKV_ARR + row * 272 + ch * 16, src);
        }
        cp_commit();
    };
    load_kv(0, 0);

    const int rloc1 = w * 16 + (lane >> 2);
    const int row1 = q0 + rloc1;
    const int row2 = row1 + 8;
    float m1 = -INFINITY, m2 = -INFINITY, l1 = 0.0f, l2 = 0.0f;
    float sO[16][4];
    #pragma unroll
    for (int f = 0; f < 16; f++)
        #pragma unroll
        for (int e = 0; e < 4; e++) sO[f][e] = 0.0f;

    for (int kt = 0; kt < nkt; kt++) {
        const int st = kt & 1;
        if (kt + 1 < nkt) {
            load_kv(kt + 1, st ^ 1);
            cp_wait<1>();
        } else {
            cp_wait<0>();
        }
        __syncthreads();

        const uint32_t kb = sKV + st * FSTAGE_BYTES;          // K
        const uint32_t vb = kb + FKV_ARR;                     // V
        const int k0 = kt * 64;

        // ---- S = Q K^T (single fp16 pass)
        float sS[8][4];
        #pragma unroll
        for (int f = 0; f < 8; f++)
            #pragma unroll
            for (int e = 0; e < 4; e++) sS[f][e] = 0.0f;

        #pragma unroll
        for (int kg = 0; kg < 8; kg++) {
            uint32_t aF[4];
            const uint32_t qoff = (w * 16 + (lane & 15)) * 272
                                + (kg * 16 + (lane >> 4) * 8) * 2;
            ldm_x4(aF, sQ + qoff);
            #pragma unroll
            for (int f = 0; f < 8; f++) {
                uint32_t bF[2];
                const uint32_t koff = (f * 8 + (lane & 7)) * 272
                                    + (kg * 16 + ((lane >> 3) & 1) * 8) * 2;
                ldm_x2(bF, kb + koff);
                mma_fp16(sS[f], aF, bF);
            }
        }

        // ---- causal mask
        if (k0 + 63 > row1) {
            #pragma unroll
            for (int f = 0; f < 8; f++)
                #pragma unroll
                for (int e = 0; e < 4; e++) {
                    const int col = k0 + f * 8 + (lane & 3) * 2 + (e & 1);
                    const int rw = (e < 2) ? row1 : row2;
                    if (col > rw) sS[f][e] = -INFINITY;
                }
        }

        // ---- online softmax
        float mx1 = -INFINITY, mx2 = -INFINITY;
        #pragma unroll
        for (int f = 0; f < 8; f++) {
            mx1 = fmaxf(mx1, fmaxf(sS[f][0], sS[f][1]));
            mx2 = fmaxf(mx2, fmaxf(sS[f][2], sS[f][3]));
        }
        mx1 = fmaxf(mx1, __shfl_xor_sync(0xffffffffu, mx1, 1));
        mx1 = fmaxf(mx1, __shfl_xor_sync(0xffffffffu, mx1, 2));
        mx2 = fmaxf(mx2, __shfl_xor_sync(0xffffffffu, mx2, 1));
        mx2 = fmaxf(mx2, __shfl_xor_sync(0xffffffffu, mx2, 2));

        const float mn1 = fmaxf(m1, mx1);
        const float mn2 = fmaxf(m2, mx2);
        const float al1 = __expf(m1 - mn1);
        const float al2 = __expf(m2 - mn2);
        m1 = mn1; m2 = mn2;

        float sum1 = 0.0f, sum2 = 0.0f;
        #pragma unroll
        for (int f = 0; f < 8; f++) {
            sS[f][0] = __expf(sS[f][0] - m1);
            sS[f][1] = __expf(sS[f][1] - m1);
            sS[f][2] = __expf(sS[f][2] - m2);
            sS[f][3] = __expf(sS[f][3] - m2);
            sum1 += sS[f][0] + sS[f][1];
            sum2 += sS[f][2] + sS[f][3];
        }
        sum1 += __shfl_xor_sync(0xffffffffu, sum1, 1);
        sum1 += __shfl_xor_sync(0xffffffffu, sum1, 2);
        sum2 += __shfl_xor_sync(0xffffffffu, sum2, 1);
        sum2 += __shfl_xor_sync(0xffffffffu, sum2, 2);
        l1 = l1 * al1 + sum1;
        l2 = l2 * al2 + sum2;

        #pragma unroll
        for (int f = 0; f < 16; f++) {
            sO[f][0] *= al1; sO[f][1] *= al1;
            sO[f][2] *= al2; sO[f][3] *= al2;
        }

        // ---- O += P V (single fp16 pass); P packed from S regs
        #pragma unroll
        for (int g = 0; g < 4; g++) {
            uint32_t aP[4];
            {
                const float* p0 = sS[2 * g];
                const float* p1 = sS[2 * g + 1];
                aP[0] = pack_fp16(p0[0], p0[1]);
                aP[1] = pack_fp16(p0[2], p0[3]);
                aP[2] = pack_fp16(p1[0], p1[1]);
                aP[3] = pack_fp16(p1[2], p1[3]);
            }
            #pragma unroll
            for (int f2 = 0; f2 < 16; f2++) {
                uint32_t bV[2];
                const uint32_t voff = (g * 16 + (lane & 15)) * 272 + f2 * 16;
                ldm_x2_trans(bV, vb + voff);
                mma_fp16(sO[f2], aP, bV);
            }
        }
        __syncthreads();
    }

    // epilogue: normalize, write single fp16 to g_A
    const float linv1 = 1.0f / l1;
    const float linv2 = 1.0f / l2;
    const size_t tok1 = (size_t)(b * SEQ + row1) * HIDDEN + h * HEAD_DIM;
    const size_t tok2 = (size_t)(b * SEQ + row2) * HIDDEN + h * HEAD_DIM;
    #pragma unroll
    for (int f2 = 0; f2 < 16; f2++) {
        const int d = f2 * 8 + (lane & 3) * 2;
        *(uint32_t*)(g_A + tok1 + d) =
            pack_fp16(sO[f2][0] * linv1, sO[f2][1] * linv1);
        *(uint32_t*)(g_A + tok2 + d) =
            pack_fp16(sO[f2][2] * linv2, sO[f2][3] * linv2);
    }
}

// ---------------------------------------------------------------------------
// Launch
// ---------------------------------------------------------------------------
extern "C" void kernel_launch(void* const* d_in, const int* in_sizes, int n_in,
                              void* d_out, int out_size)
{
    const float* hidden = (const float*)d_in[0];
    const int*   pos32  = (const int*)d_in[1];
    const float* Wqkv   = (const float*)d_in[2];
    const float* bqkv   = (const float*)d_in[3];
    const float* Wo     = (const float*)d_in[4];
    const float* bo     = (const float*)d_in[5];
    float* out          = (float*)d_out;

    float* qkv;  cudaGetSymbolAddress((void**)&qkv,  g_qkv);
    __half *A, *Wqh, *Woh;
    cudaGetSymbolAddress((void**)&A, g_A);
    cudaGetSymbolAddress((void**)&Wqh, g_Wqkv_h);
    cudaGetSymbolAddress((void**)&Woh, g_Wo_h);

    cudaFuncSetAttribute(gemm_mma_kernel,
                         cudaFuncAttributeMaxDynamicSharedMemorySize,
                         GEMM_SMEM_BYTES);
    cudaFuncSetAttribute(flash_mma_kernel,
                         cudaFuncAttributeMaxDynamicSharedMemorySize,
                         FL_SMEM_BYTES);

    // 0a) convert hidden -> A (fp16)
    {
        const int n4 = TOKENS * HIDDEN / 4;
        convert_kernel<<<(n4 + 255) / 256, 256>>>(hidden, A, n4);
    }
    // 0b) transpose weights to single fp16
    tsplit_kernel<<<dim3(QKV_N / 32, HIDDEN / 32), 256>>>(Wqkv, Wqh, HIDDEN, QKV_N);
    tsplit_kernel<<<dim3(HIDDEN / 32, HIDDEN / 32), 256>>>(Wo, Woh, HIDDEN, HIDDEN);

    // 1) QKV projection (fp16, single pass, BK=64)
    gemm_mma_kernel<<<dim3(QKV_N / 128, TOKENS / 128), 256, GEMM_SMEM_BYTES>>>(
        TOKENS, QKV_N, HIDDEN, A, Wqh, bqkv, qkv);

    // 2) RoPE + scale + fp16 Q/K/V buffers
    rope_split_kernel<<<TOKENS, 1024>>>(qkv, pos32);

    // 3) Tensor-core flash attention (fp16 single pass) -> writes fp16 g_A
    flash_mma_kernel<<<dim3(SEQ / 128, BH), 256, FL_SMEM_BYTES>>>();

    // 4) Output projection (fp16, single pass, BK=64)
    gemm_mma_kernel<<<dim3(HIDDEN / 128, TOKENS / 128), 256, GEMM_SMEM_BYTES>>>(
        TOKENS, HIDDEN, HIDDEN, A, Woh, bo, out);
}